// round 9
// baseline (speedup 1.0000x reference)
#include <cuda_runtime.h>
#include <cuda_bf16.h>
#include <math.h>
#include <stdint.h>

#define B_   2
#define L_   4096
#define H_   1024
#define NH_  4
#define DK_  256
#define DV_  256
#define C_   32
#define NC_  128
#define BL_  8192
#define BH_  8
#define F1_  2048
#define NQKV 3072

// ------------------------- scratch (static device memory; no allocs) -------
__device__ float g_qkvp[BL_*NQKV];
__device__ float g_qs[BL_*H_], g_ks[BL_*H_], g_vs[BL_*H_];
__device__ float g_qn[BL_*H_], g_kn[BL_*H_], g_kb[BL_*H_], g_vb[BL_*H_];
__device__ float g_u [BL_*H_], g_w [BL_*H_];
__device__ float g_delta[BL_*H_], g_shrt[BL_*H_], g_long[BL_*H_];
__device__ float g_h1[BL_*F1_];
__device__ float g_att[BH_*NC_*C_*C_];
__device__ float g_beta[BL_*NH_];
__device__ float g_fw[BL_*16];
// bf16 hi/lo staging
__device__ __nv_bfloat16 g_ahi[BL_*H_],  g_alo[BL_*H_];
__device__ __nv_bfloat16 g_mhi[BL_*H_],  g_mlo[BL_*H_];
__device__ __nv_bfloat16 g_wqkv_hi[NQKV*H_], g_wqkv_lo[NQKV*H_];
__device__ __nv_bfloat16 g_wf1_hi[F1_*H_],   g_wf1_lo[F1_*H_];
__device__ __nv_bfloat16 g_wo_hi[H_*H_],     g_wo_lo[H_*H_];

__device__ __forceinline__ float sigmoidf_(float x) { return 1.f / (1.f + expf(-x)); }
__device__ __forceinline__ float geluf_(float x) {
    return 0.5f * x * (1.f + erff(x * 0.70710678118654752440f));
}
__device__ __forceinline__ uint32_t smem_u32_(const void* p) {
    uint32_t a;
    asm("{ .reg .u64 t; cvta.to.shared.u64 t, %1; cvt.u32.u64 %0, t; }" : "=r"(a) : "l"(p));
    return a;
}
__device__ __forceinline__ uint32_t pack_bf16_hi_(float x, float y) {
    __nv_bfloat162 h = __halves2bfloat162(__float2bfloat16(x), __float2bfloat16(y));
    return *reinterpret_cast<uint32_t*>(&h);
}
__device__ __forceinline__ uint32_t pack_bf16_lo_(float x, float y) {
    float hx = __bfloat162float(__float2bfloat16(x));
    float hy = __bfloat162float(__float2bfloat16(y));
    __nv_bfloat162 l = __halves2bfloat162(__float2bfloat16(x - hx), __float2bfloat16(y - hy));
    return *reinterpret_cast<uint32_t*>(&l);
}
__device__ __forceinline__ void cp16_(uint32_t dst, const void* src) {
    asm volatile("cp.async.ca.shared.global [%0], [%1], 16;" :: "r"(dst), "l"(src));
}

// ------------------------- prep: fp32 -> bf16 hi/lo ------------------------
__global__ __launch_bounds__(256) void cvt_a_kernel(
    const float* __restrict__ x, __nv_bfloat16* __restrict__ hi, __nv_bfloat16* __restrict__ lo)
{
    int i = (blockIdx.x * 256 + threadIdx.x) * 4;
    float4 v = *(const float4*)(x + i);
    uint2 oh, ol;
    oh.x = pack_bf16_hi_(v.x, v.y); oh.y = pack_bf16_hi_(v.z, v.w);
    ol.x = pack_bf16_lo_(v.x, v.y); ol.y = pack_bf16_lo_(v.z, v.w);
    *(uint2*)(hi + i) = oh;
    *(uint2*)(lo + i) = ol;
}

// W [K][N] -> Wt hi/lo [N][K]  (32x32 smem transpose)
__global__ __launch_bounds__(256) void cvt_wt_kernel(
    const float* __restrict__ W, __nv_bfloat16* __restrict__ hi, __nv_bfloat16* __restrict__ lo,
    int K, int N)
{
    __shared__ float tile[32][33];
    int n0 = blockIdx.x * 32, k0 = blockIdx.y * 32;
    int tx = threadIdx.x & 31, ty = threadIdx.x >> 5;   // 32 x 8
#pragma unroll
    for (int i = 0; i < 4; i++)
        tile[ty + 8 * i][tx] = W[(size_t)(k0 + ty + 8 * i) * N + n0 + tx];
    __syncthreads();
#pragma unroll
    for (int i = 0; i < 4; i++) {
        float v = tile[tx][ty + 8 * i];
        __nv_bfloat16 h = __float2bfloat16(v);
        size_t o = (size_t)(n0 + ty + 8 * i) * K + k0 + tx;
        hi[o] = h;
        lo[o] = __float2bfloat16(v - __bfloat162float(h));
    }
}

// ===================== pipelined warp-mma bf16 split-x3 GEMM ================
// C[M,N] = A[M,K] @ B^T[N,K], bf16 hi/lo inputs. act==1: gelu(+bias).
// CTA 128x128, 8 warps, BK=32, 2-stage cp.async double buffer.
#define MMA_BF16_(c, a0, a1, a2, a3, b0, b1) \
    asm volatile("mma.sync.aligned.m16n8k16.row.col.f32.bf16.bf16.f32 " \
        "{%0,%1,%2,%3}, {%4,%5,%6,%7}, {%8,%9}, {%0,%1,%2,%3};" \
        : "+f"((c)[0]), "+f"((c)[1]), "+f"((c)[2]), "+f"((c)[3]) \
        : "r"(a0), "r"(a1), "r"(a2), "r"(a3), "r"(b0), "r"(b1))

#define MG_SMEM 65536

__device__ __forceinline__ uint32_t frag2_(const uint32_t* sm, int base, int row, int j) {
    return sm[base + row * 16 + ((((j >> 2) ^ ((row >> 1) & 3)) << 2) | (j & 3))];
}

__device__ __forceinline__ void fill_stage_(
    uint32_t smem_b, int stage,
    const __nv_bfloat16* __restrict__ Ahi_g, const __nv_bfloat16* __restrict__ Alo_g,
    const __nv_bfloat16* __restrict__ Bhi_g, const __nv_bfloat16* __restrict__ Blo_g,
    int row0, int col0, int K, int k0, int tid)
{
#pragma unroll
    for (int i = 0; i < 8; i++) {
        int task = i * 256 + tid;            // 0..2047
        int op = task >> 9;                  // 0..3
        int rem = task & 511;
        int row = rem >> 2, chunk = rem & 3;
        const __nv_bfloat16* gp =
            (op == 0) ? Ahi_g + (size_t)(row0 + row) * K :
            (op == 1) ? Alo_g + (size_t)(row0 + row) * K :
            (op == 2) ? Bhi_g + (size_t)(col0 + row) * K :
                        Blo_g + (size_t)(col0 + row) * K;
        gp += k0 + chunk * 8;
        uint32_t word = (uint32_t)(stage * 8192 + op * 2048 + row * 16
                        + ((chunk ^ ((row >> 1) & 3)) << 2));
        cp16_(smem_b + word * 4, gp);
    }
}

__global__ __launch_bounds__(256, 2) void mma_gemm2_kernel(
    const __nv_bfloat16* __restrict__ Ahi_g, const __nv_bfloat16* __restrict__ Alo_g,
    const __nv_bfloat16* __restrict__ Bhi_g, const __nv_bfloat16* __restrict__ Blo_g,
    const float* __restrict__ bias, float* __restrict__ C,
    int N, int K, int act)
{
    extern __shared__ __align__(16) uint32_t smem_u[];
    const uint32_t smem_b = smem_u32_(smem_u);
    const int tid = threadIdx.x;
    const int wid = tid >> 5, lane = tid & 31;
    const int g = lane >> 2, t = lane & 3;
    const int warp_m = (wid & 3) * 32;
    const int warp_n = (wid >> 2) * 64;
    const int row0 = blockIdx.y * 128, col0 = blockIdx.x * 128;

    float acc[2][8][4];
#pragma unroll
    for (int mt = 0; mt < 2; mt++)
#pragma unroll
        for (int nt = 0; nt < 8; nt++)
#pragma unroll
            for (int e = 0; e < 4; e++) acc[mt][nt][e] = 0.f;

    const int ntl = K >> 5;
    fill_stage_(smem_b, 0, Ahi_g, Alo_g, Bhi_g, Blo_g, row0, col0, K, 0, tid);
    asm volatile("cp.async.commit_group;");

    for (int tt = 0; tt < ntl; tt++) {
        if (tt + 1 < ntl) {
            fill_stage_(smem_b, (tt + 1) & 1, Ahi_g, Alo_g, Bhi_g, Blo_g,
                        row0, col0, K, (tt + 1) * 32, tid);
            asm volatile("cp.async.commit_group;");
            asm volatile("cp.async.wait_group 1;");
        } else {
            asm volatile("cp.async.wait_group 0;");
        }
        __syncthreads();

        const int sb = (tt & 1) * 8192;
#pragma unroll
        for (int ks = 0; ks < 2; ks++) {
            const int cA = ks * 8 + t, cB = cA + 4;
            uint32_t ah[2][4], al[2][4];
#pragma unroll
            for (int mt = 0; mt < 2; mt++) {
                int r = warp_m + mt * 16 + g;
                ah[mt][0] = frag2_(smem_u, sb, r, cA);
                ah[mt][1] = frag2_(smem_u, sb, r + 8, cA);
                ah[mt][2] = frag2_(smem_u, sb, r, cB);
                ah[mt][3] = frag2_(smem_u, sb, r + 8, cB);
                al[mt][0] = frag2_(smem_u, sb + 2048, r, cA);
                al[mt][1] = frag2_(smem_u, sb + 2048, r + 8, cA);
                al[mt][2] = frag2_(smem_u, sb + 2048, r, cB);
                al[mt][3] = frag2_(smem_u, sb + 2048, r + 8, cB);
            }
#pragma unroll
            for (int nt = 0; nt < 8; nt++) {
                int n = warp_n + nt * 8 + g;
                uint32_t bh0 = frag2_(smem_u, sb + 4096, n, cA);
                uint32_t bh1 = frag2_(smem_u, sb + 4096, n, cB);
                uint32_t bl0 = frag2_(smem_u, sb + 6144, n, cA);
                uint32_t bl1 = frag2_(smem_u, sb + 6144, n, cB);
#pragma unroll
                for (int mt = 0; mt < 2; mt++) {
                    MMA_BF16_(acc[mt][nt], ah[mt][0], ah[mt][1], ah[mt][2], ah[mt][3], bh0, bh1);
                    MMA_BF16_(acc[mt][nt], ah[mt][0], ah[mt][1], ah[mt][2], ah[mt][3], bl0, bl1);
                    MMA_BF16_(acc[mt][nt], al[mt][0], al[mt][1], al[mt][2], al[mt][3], bh0, bh1);
                }
            }
        }
        __syncthreads();
    }

    // ---- epilogue -----------------------------------------------------------
#pragma unroll
    for (int mt = 0; mt < 2; mt++) {
        int r0g = row0 + warp_m + mt * 16 + g;
#pragma unroll
        for (int nt = 0; nt < 8; nt++) {
            int c = col0 + warp_n + nt * 8 + 2 * t;
            float2 v0, v1;
            v0.x = acc[mt][nt][0]; v0.y = acc[mt][nt][1];
            v1.x = acc[mt][nt][2]; v1.y = acc[mt][nt][3];
            if (act == 1) {
                float b0 = bias[c], b1 = bias[c + 1];
                v0.x = geluf_(v0.x + b0); v0.y = geluf_(v0.y + b1);
                v1.x = geluf_(v1.x + b0); v1.y = geluf_(v1.y + b1);
            }
            *(float2*)(C + (size_t)r0g * N + c) = v0;
            *(float2*)(C + (size_t)(r0g + 8) * N + c) = v1;
        }
    }
}

// ------------------------- short causal depthwise conv (K=4) + silu ---------
__global__ __launch_bounds__(256) void conv4_silu_kernel(
    const float* __restrict__ x, const float* __restrict__ f, float* __restrict__ y,
    int xstride, int xoff)
{
    int idx = blockIdx.x * 256 + threadIdx.x;      // (bl, c)
    int c  = idx & (H_ - 1);
    int bl = idx >> 10;
    int l  = bl & (L_ - 1);
    const float* xp = x + (size_t)bl * xstride + xoff + c;
    float4 fv = *(const float4*)(f + c * 4);
    float acc = fv.w * xp[0];
    if (l >= 1) acc += fv.z * xp[-xstride];
    if (l >= 2) acc += fv.y * xp[-2 * xstride];
    if (l >= 3) acc += fv.x * xp[-3 * xstride];
    y[idx] = acc * sigmoidf_(acc);
}

// ------------------------- beta = sigmoid(hs @ Wb) --------------------------
__global__ __launch_bounds__(128) void beta_kernel(
    const float* __restrict__ hs, const float* __restrict__ Wb, float* __restrict__ beta)
{
    int bl = blockIdx.x;
    int wrp = threadIdx.x >> 5, lane = threadIdx.x & 31;
    const float* hp = hs + (size_t)bl * H_;
    float acc = 0.f;
    for (int d = lane; d < H_; d += 32) acc += hp[d] * Wb[d * NH_ + wrp];
#pragma unroll
    for (int o = 16; o; o >>= 1) acc += __shfl_xor_sync(0xffffffffu, acc, o);
    if (lane == 0) beta[bl * NH_ + wrp] = sigmoidf_(acc);
}

// ------------------------- l2norm + beta-scale + [B,H,L,D] transpose --------
__global__ __launch_bounds__(256) void normtr_kernel(
    const float* __restrict__ qs, const float* __restrict__ ks, const float* __restrict__ vs,
    const float* __restrict__ beta,
    float* __restrict__ qn, float* __restrict__ kn, float* __restrict__ kb, float* __restrict__ vb)
{
    int bl = blockIdx.x, h = blockIdx.y, d = threadIdx.x;
    int b = bl >> 12;
    int l = bl & (L_ - 1);
    size_t src = (size_t)bl * H_ + h * DK_ + d;
    float qv = qs[src], kv = ks[src], vv = vs[src];
    float s1 = qv * qv, s2 = kv * kv;
#pragma unroll
    for (int o = 16; o; o >>= 1) {
        s1 += __shfl_xor_sync(0xffffffffu, s1, o);
        s2 += __shfl_xor_sync(0xffffffffu, s2, o);
    }
    __shared__ float r1[8], r2[8];
    __shared__ float inv1, inv2;
    int lane = d & 31, wid = d >> 5;
    if (lane == 0) { r1[wid] = s1; r2[wid] = s2; }
    __syncthreads();
    if (d == 0) {
        float t1 = 0.f, t2 = 0.f;
        for (int i = 0; i < 8; i++) { t1 += r1[i]; t2 += r2[i]; }
        inv1 = rsqrtf(t1);
        inv2 = rsqrtf(t2);
    }
    __syncthreads();
    float bt = beta[bl * NH_ + h];
    size_t dst = (((size_t)b * NH_ + h) * L_ + l) * DK_ + d;
    float knv = kv * inv2;
    qn[dst] = qv * inv1;
    kn[dst] = knv;
    kb[dst] = knv * bt;
    vb[dst] = vv * bt;
}

// ------------------------- per-chunk: UT transform, u, w, attn --------------
__global__ __launch_bounds__(256) void chunk_kernel(
    const float* __restrict__ qn, const float* __restrict__ kn,
    const float* __restrict__ kb, const float* __restrict__ vb,
    float* __restrict__ U, float* __restrict__ Wm, float* __restrict__ ATT)
{
    extern __shared__ float sm[];
    float* sk  = sm;            // 32x256
    float* skb = sm + 8192;     // 32x256
    float* sx  = sm + 16384;    // 32x256 (vb then qn)
    float* T   = sm + 24576;    // 32x33
    int bh = blockIdx.x, n = blockIdx.y;
    int tid = threadIdx.x;
    size_t base = ((size_t)bh * L_ + n * C_) * DK_;

    for (int i = tid; i < 2048; i += 256) {
        ((float4*)sk)[i]  = ((const float4*)(kn + base))[i];
        ((float4*)skb)[i] = ((const float4*)(kb + base))[i];
        ((float4*)sx)[i]  = ((const float4*)(vb + base))[i];
    }
    __syncthreads();

    // A = -(kb @ kn^T) * strict_lower
    for (int e = tid; e < 1024; e += 256) {
        int i = e >> 5, j = e & 31;
        float a = 0.f;
        if (j < i) {
            const float* pi = skb + i * 256;
            const float* pj = sk + j * 256;
            for (int d = 0; d < 256; d++) a -= pi[d] * pj[d];
        }
        T[i * 33 + j] = a;
    }
    __syncthreads();

    // forward substitution (warp 0)
    if (tid < 32) {
        int j = tid;
        for (int i = 1; i < 32; i++) {
            float rv = T[i * 33 + j];
            float acc = rv;
            for (int m = 1; m < i; m++)
                acc += __shfl_sync(0xffffffffu, rv, m) * T[m * 33 + j];
            __syncwarp();
            T[i * 33 + j] = acc;
            __syncwarp();
        }
        T[j * 33 + j] = 1.f;
    }
    __syncthreads();

    // u = T @ vb, w = T @ kb
    for (int idx = tid; idx < 8192; idx += 256) {
        int c = idx >> 8, d = idx & 255;
        float au = 0.f, aw = 0.f;
#pragma unroll
        for (int j = 0; j < 32; j++) {
            float t = T[c * 33 + j];
            au += t * sx[j * 256 + d];
            aw += t * skb[j * 256 + d];
        }
        U[base + idx]  = au;
        Wm[base + idx] = aw;
    }
    __syncthreads();

    // attn = (qn @ kn^T) * causal
    for (int i = tid; i < 2048; i += 256)
        ((float4*)sx)[i] = ((const float4*)(qn + base))[i];
    __syncthreads();
    float* att = ATT + ((size_t)bh * NC_ + n) * 1024;
    for (int e = tid; e < 1024; e += 256) {
        int c = e >> 5, j = e & 31;
        float a = 0.f;
        if (j <= c) {
            const float* pq = sx + c * 256;
            const float* pk = sk + j * 256;
            for (int d = 0; d < 256; d++) a += pq[d] * pk[d];
        }
        att[e] = a;
    }
}

// ------------------------- sequential chunk scan (dv tiled by 16) -----------
// S transposed [16 e][260 d] (stride 260: 16B-aligned rows, stride/4 odd ->
// rows spread over bank quads), sq/sk/sw padded to 260, sat to 36.
#define SCAN_SMEM (31296 * 4)
__global__ __launch_bounds__(256) void scan_kernel(
    const float* __restrict__ qn, const float* __restrict__ kn,
    const float* __restrict__ U, const float* __restrict__ Wm,
    const float* __restrict__ ATT, float* __restrict__ OUT)
{
    extern __shared__ float sm[];
    float* St  = sm;             // [16][260]
    float* sq  = sm + 4160;      // [32][260]
    float* sk  = sm + 12480;     // [32][260]
    float* sw  = sm + 20800;     // [32][260]
    float* su  = sm + 29120;     // [32][16]
    float* sut = sm + 29632;     // [32][16]
    float* sat = sm + 30144;     // [32][36]
    const int bh = blockIdx.x, tile = blockIdx.y;
    const int tid = threadIdx.x;
    const int b = bh >> 2, h = bh & 3;
    const int g = tid >> 3, eg = tid & 7;

    for (int i = tid; i < 4160; i += 256) St[i] = 0.f;

    for (int n = 0; n < NC_; n++) {
        __syncthreads();
        size_t base = ((size_t)bh * L_ + n * C_) * 256;
        for (int i = tid; i < 2048; i += 256) {
            int c = i >> 6, o = (i & 63) * 4;
            *(float4*)(sq + c * 260 + o) = ((const float4*)(qn + base))[i];
            *(float4*)(sk + c * 260 + o) = ((const float4*)(kn + base))[i];
            *(float4*)(sw + c * 260 + o) = ((const float4*)(Wm + base))[i];
        }
        if (tid < 128) {
            int c = tid >> 2, e4 = (tid & 3) * 4;
            *(float4*)(su + c * 16 + e4) = *(const float4*)(U + base + c * 256 + tile * 16 + e4);
        }
        {
            int c = tid >> 3, j4 = (tid & 7) * 4;
            *(float4*)(sat + c * 36 + j4) =
                ((const float4*)(ATT + ((size_t)bh * NC_ + n) * 1024))[tid];
        }
        __syncthreads();

        // u_t = u - w@S ; o_partial = q@S (dk = 256)
        float2 aw = make_float2(0.f, 0.f);
        float2 aq = make_float2(0.f, 0.f);
        const float* wr  = sw + g * 260;
        const float* qr  = sq + g * 260;
        const float* s0p = St + (eg * 2) * 260;
        const float* s1p = St + (eg * 2 + 1) * 260;
#pragma unroll 8
        for (int d = 0; d < 256; d += 4) {
            float4 w4 = *(const float4*)(wr + d);
            float4 q4 = *(const float4*)(qr + d);
            float4 s0 = *(const float4*)(s0p + d);
            float4 s1 = *(const float4*)(s1p + d);
            aw.x += w4.x * s0.x + w4.y * s0.y + w4.z * s0.z + w4.w * s0.w;
            aw.y += w4.x * s1.x + w4.y * s1.y + w4.z * s1.z + w4.w * s1.w;
            aq.x += q4.x * s0.x + q4.y * s0.y + q4.z * s0.z + q4.w * s0.w;
            aq.y += q4.x * s1.x + q4.y * s1.y + q4.z * s1.z + q4.w * s1.w;
        }
        float2 uv = *(float2*)(su + g * 16 + eg * 2);
        float2 ut = make_float2(uv.x - aw.x, uv.y - aw.y);
        *(float2*)(sut + g * 16 + eg * 2) = ut;
        __syncthreads();

        // o = q@S + attn @ u_t
        const float* ar = sat + g * 36;
#pragma unroll
        for (int j = 0; j < 32; j += 4) {
            float4 a4 = *(const float4*)(ar + j);
            float2 u0 = *(float2*)(sut + (j + 0) * 16 + eg * 2);
            float2 u1 = *(float2*)(sut + (j + 1) * 16 + eg * 2);
            float2 u2 = *(float2*)(sut + (j + 2) * 16 + eg * 2);
            float2 u3 = *(float2*)(sut + (j + 3) * 16 + eg * 2);
            aq.x += a4.x * u0.x + a4.y * u1.x + a4.z * u2.x + a4.w * u3.x;
            aq.y += a4.x * u0.y + a4.y * u1.y + a4.z * u2.y + a4.w * u3.y;
        }
        *(float2*)(OUT + (size_t)(b * L_ + n * C_ + g) * H_ + h * 256 + tile * 16 + eg * 2) = aq;

        // S += k^T @ u_t : thread owns d-octet g, e-pair eg
        float a0[8], a1[8];
#pragma unroll
        for (int i = 0; i < 8; i++) { a0[i] = 0.f; a1[i] = 0.f; }
        for (int c2 = 0; c2 < 32; c2++) {
            float2 u2 = *(float2*)(sut + c2 * 16 + eg * 2);
            const float* kr = sk + c2 * 260 + g * 8;
            float4 k0 = *(const float4*)(kr);
            float4 k1 = *(const float4*)(kr + 4);
            a0[0] += k0.x * u2.x; a1[0] += k0.x * u2.y;
            a0[1] += k0.y * u2.x; a1[1] += k0.y * u2.y;
            a0[2] += k0.z * u2.x; a1[2] += k0.z * u2.y;
            a0[3] += k0.w * u2.x; a1[3] += k0.w * u2.y;
            a0[4] += k1.x * u2.x; a1[4] += k1.x * u2.y;
            a0[5] += k1.y * u2.x; a1[5] += k1.y * u2.y;
            a0[6] += k1.z * u2.x; a1[6] += k1.z * u2.y;
            a0[7] += k1.w * u2.x; a1[7] += k1.w * u2.y;
        }
        float* st0 = St + (eg * 2) * 260 + g * 8;
        float* st1 = St + (eg * 2 + 1) * 260 + g * 8;
        {
            float4 v0 = *(float4*)(st0), v1 = *(float4*)(st0 + 4);
            v0.x += a0[0]; v0.y += a0[1]; v0.z += a0[2]; v0.w += a0[3];
            v1.x += a0[4]; v1.y += a0[5]; v1.z += a0[6]; v1.w += a0[7];
            *(float4*)(st0) = v0; *(float4*)(st0 + 4) = v1;
            float4 w0 = *(float4*)(st1), w1 = *(float4*)(st1 + 4);
            w0.x += a1[0]; w0.y += a1[1]; w0.z += a1[2]; w0.w += a1[3];
            w1.x += a1[4]; w1.y += a1[5]; w1.z += a1[6]; w1.w += a1[7];
            *(float4*)(st1) = w0; *(float4*)(st1 + 4) = w1;
        }
    }
}

// ------------------------- FIR K=7 (unrolled) -------------------------------
__global__ __launch_bounds__(256) void fir7_kernel(
    const float* __restrict__ x, const float* __restrict__ f, float* __restrict__ y)
{
    int idx = blockIdx.x * 256 + threadIdx.x;
    int c  = idx & (H_ - 1);
    int bl = idx >> 10;
    int l  = bl & (L_ - 1);
    const float* fp = f + (size_t)c * 7;
    float acc = 0.f;
#pragma unroll
    for (int t = 0; t < 7; t++) {
        int dl = t - 6;
        if (l + dl >= 0) acc += x[idx + dl * H_] * fp[t];
    }
    y[idx] = acc;
}

// ------------------------- FIR K=64: smem tile + register sliding window ----
#define FIR64_SMEM ((127 * 128 + 64 * 129) * 4)
__global__ __launch_bounds__(256) void fir64_smem_kernel(
    const float* __restrict__ x, const float* __restrict__ f, float* __restrict__ y)
{
    extern __shared__ float fsm[];
    float* sx = fsm;                 // 127 x 128
    float* sf = fsm + 127 * 128;     // 64 x 129
    const int ctile = blockIdx.x & 7;
    const int ltile = blockIdx.x >> 3;
    const int l0 = ltile * 64;
    const int lb = l0 & (L_ - 1);
    const int c0 = ctile * 128;
    const int tid = threadIdx.x;

    for (int i = tid; i < 64 * 128; i += 256) {
        int c = i >> 6, t = i & 63;
        sf[t * 129 + c] = f[(size_t)(c0 + c) * 64 + t];
    }
    for (int i = tid; i < 127 * 128; i += 256) {
        int j = i >> 7, c = i & 127;
        int lrel = lb + j - 63;
        float v = 0.f;
        if (lrel >= 0)
            v = x[(size_t)(l0 + j - 63) * H_ + c0 + c];
        sx[j * 128 + c] = v;
    }
    __syncthreads();

    const int c = tid & 127;
    const int lg = (tid >> 7) * 32;
    float acc[32], win[32];
#pragma unroll
    for (int i = 0; i < 32; i++) acc[i] = 0.f;
#pragma unroll
    for (int i = 0; i < 32; i++) win[i] = sx[(lg + i) * 128 + c];
#pragma unroll
    for (int t = 0; t < 64; t++) {
        float ft = sf[t * 129 + c];
#pragma unroll
        for (int i = 0; i < 32; i++) acc[i] += ft * win[i];
        if (t < 63) {
#pragma unroll
            for (int i = 0; i < 31; i++) win[i] = win[i + 1];
            win[31] = sx[(lg + t + 32) * 128 + c];
        }
    }
#pragma unroll
    for (int i = 0; i < 32; i++)
        y[(size_t)(l0 + lg + i) * H_ + c0 + c] = acc[i];
}

// ------------------------- fusion gate: h1 @ Wf2 + bf2 -> softmax4 ----------
__global__ __launch_bounds__(128) void gate_kernel(
    const float* __restrict__ h1, const float* __restrict__ Wf2,
    const float* __restrict__ bf2, float* __restrict__ fw)
{
    int bl = blockIdx.x, tid = threadIdx.x;
    float acc[16];
#pragma unroll
    for (int j = 0; j < 16; j++) acc[j] = 0.f;
    const float* hp = h1 + (size_t)bl * F1_;
    for (int d = tid; d < F1_; d += 128) {
        float hv = hp[d];
        const float4* w4 = (const float4*)(Wf2 + d * 16);
        float4 w0 = w4[0], w1 = w4[1], w2 = w4[2], w3 = w4[3];
        acc[0] += hv * w0.x; acc[1] += hv * w0.y; acc[2] += hv * w0.z; acc[3] += hv * w0.w;
        acc[4] += hv * w1.x; acc[5] += hv * w1.y; acc[6] += hv * w1.z; acc[7] += hv * w1.w;
        acc[8] += hv * w2.x; acc[9] += hv * w2.y; acc[10] += hv * w2.z; acc[11] += hv * w2.w;
        acc[12] += hv * w3.x; acc[13] += hv * w3.y; acc[14] += hv * w3.z; acc[15] += hv * w3.w;
    }
    __shared__ float red[16][129];
    __shared__ float logit[16];
#pragma unroll
    for (int j = 0; j < 16; j++) red[j][tid] = acc[j];
    __syncthreads();
    if (tid < 16) {
        float s = bf2[tid];
        for (int i = 0; i < 128; i++) s += red[tid][i];
        logit[tid] = s;
    }
    __syncthreads();
    if (tid < 4) {
        float l0 = logit[tid * 4], l1 = logit[tid * 4 + 1];
        float l2 = logit[tid * 4 + 2], l3 = logit[tid * 4 + 3];
        float m = fmaxf(fmaxf(l0, l1), fmaxf(l2, l3));
        float e0 = expf(l0 - m), e1 = expf(l1 - m), e2 = expf(l2 - m), e3 = expf(l3 - m);
        float inv = 1.f / (e0 + e1 + e2 + e3);
        float* o = fw + (size_t)bl * 16 + tid * 4;
        o[0] = e0 * inv; o[1] = e1 * inv; o[2] = e2 * inv; o[3] = e3 * inv;
    }
}

// ------------------------- branch mix + per-head rmsnorm -> bf16 hi/lo ------
__global__ __launch_bounds__(256) void mix_rms_kernel(
    const float* __restrict__ br_s, const float* __restrict__ br_l,
    const float* __restrict__ br_d, const float* __restrict__ br_v,
    const float* __restrict__ fw, const float* __restrict__ rmsw,
    __nv_bfloat16* __restrict__ Mhi, __nv_bfloat16* __restrict__ Mlo)
{
    int bl = blockIdx.x, h = blockIdx.y, d = threadIdx.x;
    size_t i = (size_t)bl * H_ + h * 256 + d;
    const float* f = fw + (size_t)bl * 16 + h * 4;
    float val = f[0] * br_s[i] + f[1] * br_l[i] + f[2] * br_d[i] + f[3] * br_v[i];
    float ss = val * val;
#pragma unroll
    for (int o = 16; o; o >>= 1) ss += __shfl_xor_sync(0xffffffffu, ss, o);
    __shared__ float red[8];
    __shared__ float scale;
    if ((d & 31) == 0) red[d >> 5] = ss;
    __syncthreads();
    if (d == 0) {
        float t = 0.f;
        for (int k = 0; k < 8; k++) t += red[k];
        scale = rsqrtf(t * (1.f / 256.f) + 1e-5f);
    }
    __syncthreads();
    float o = val * scale * rmsw[d];
    __nv_bfloat16 hb = __float2bfloat16(o);
    Mhi[i] = hb;
    Mlo[i] = __float2bfloat16(o - __bfloat162float(hb));
}

// ------------------------- launcher ----------------------------------------
extern "C" void kernel_launch(void* const* d_in, const int* in_sizes, int n_in,
                              void* d_out, int out_size)
{
    const float* hs   = (const float*)d_in[0];
    const float* Wq   = (const float*)d_in[1];
    const float* Wk   = (const float*)d_in[2];
    const float* Wv   = (const float*)d_in[3];
    const float* Wb   = (const float*)d_in[4];
    const float* cq   = (const float*)d_in[5];
    const float* ck   = (const float*)d_in[6];
    const float* cv   = (const float*)d_in[7];
    const float* fsw  = (const float*)d_in[8];
    const float* flw  = (const float*)d_in[9];
    const float* Wf1  = (const float*)d_in[10];
    const float* bf1  = (const float*)d_in[11];
    const float* Wf2  = (const float*)d_in[12];
    const float* bf2  = (const float*)d_in[13];
    const float* rmsw = (const float*)d_in[14];
    const float* Wo   = (const float*)d_in[15];
    float* out = (float*)d_out;

    float *qkvp, *qs, *ks, *vs, *qn, *kn, *kb, *vb;
    float *u, *w, *delta, *shrt, *lng, *h1, *att, *beta, *fw;
    __nv_bfloat16 *ahi, *alo, *mhi, *mlo, *wqh, *wql, *wf1h, *wf1l, *woh, *wol;
    cudaGetSymbolAddress((void**)&qkvp, g_qkvp);
    cudaGetSymbolAddress((void**)&qs, g_qs);
    cudaGetSymbolAddress((void**)&ks, g_ks);
    cudaGetSymbolAddress((void**)&vs, g_vs);
    cudaGetSymbolAddress((void**)&qn, g_qn);
    cudaGetSymbolAddress((void**)&kn, g_kn);
    cudaGetSymbolAddress((void**)&kb, g_kb);
    cudaGetSymbolAddress((void**)&vb, g_vb);
    cudaGetSymbolAddress((void**)&u, g_u);
    cudaGetSymbolAddress((void**)&w, g_w);
    cudaGetSymbolAddress((void**)&delta, g_delta);
    cudaGetSymbolAddress((void**)&shrt, g_shrt);
    cudaGetSymbolAddress((void**)&lng, g_long);
    cudaGetSymbolAddress((void**)&h1, g_h1);
    cudaGetSymbolAddress((void**)&att, g_att);
    cudaGetSymbolAddress((void**)&beta, g_beta);
    cudaGetSymbolAddress((void**)&fw, g_fw);
    cudaGetSymbolAddress((void**)&ahi, g_ahi);
    cudaGetSymbolAddress((void**)&alo, g_alo);
    cudaGetSymbolAddress((void**)&mhi, g_mhi);
    cudaGetSymbolAddress((void**)&mlo, g_mlo);
    cudaGetSymbolAddress((void**)&wqh, g_wqkv_hi);
    cudaGetSymbolAddress((void**)&wql, g_wqkv_lo);
    cudaGetSymbolAddress((void**)&wf1h, g_wf1_hi);
    cudaGetSymbolAddress((void**)&wf1l, g_wf1_lo);
    cudaGetSymbolAddress((void**)&woh, g_wo_hi);
    cudaGetSymbolAddress((void**)&wol, g_wo_lo);

    cudaFuncSetAttribute(mma_gemm2_kernel, cudaFuncAttributeMaxDynamicSharedMemorySize, MG_SMEM);
    cudaFuncSetAttribute(chunk_kernel, cudaFuncAttributeMaxDynamicSharedMemorySize, 102528);
    cudaFuncSetAttribute(scan_kernel,  cudaFuncAttributeMaxDynamicSharedMemorySize, SCAN_SMEM);
    cudaFuncSetAttribute(fir64_smem_kernel, cudaFuncAttributeMaxDynamicSharedMemorySize, FIR64_SMEM);

    // ---- prep: bf16 hi/lo conversions (A once, weights once, transposed) ---
    cvt_a_kernel<<<BL_ * H_ / 1024, 256>>>(hs, ahi, alo);
    cvt_wt_kernel<<<dim3(32, 32), 256>>>(Wq, wqh,             wql,             H_, H_);
    cvt_wt_kernel<<<dim3(32, 32), 256>>>(Wk, wqh + 1024 * H_, wql + 1024 * H_, H_, H_);
    cvt_wt_kernel<<<dim3(32, 32), 256>>>(Wv, wqh + 2048 * H_, wql + 2048 * H_, H_, H_);
    cvt_wt_kernel<<<dim3(64, 32), 256>>>(Wf1, wf1h, wf1l, H_, F1_);
    cvt_wt_kernel<<<dim3(32, 32), 256>>>(Wo, woh, wol, H_, H_);

    // ---- fused qkv projection + gate-MLP first layer -----------------------
    mma_gemm2_kernel<<<dim3(NQKV / 128, BL_ / 128), 256, MG_SMEM>>>(
        ahi, alo, wqh, wql, nullptr, qkvp, NQKV, H_, 0);
    mma_gemm2_kernel<<<dim3(F1_ / 128, BL_ / 128), 256, MG_SMEM>>>(
        ahi, alo, wf1h, wf1l, bf1, h1, F1_, H_, 1);

    // short conv + silu (reads packed qkv)
    conv4_silu_kernel<<<BL_ * H_ / 256, 256>>>(qkvp, cq, qs, NQKV, 0);
    conv4_silu_kernel<<<BL_ * H_ / 256, 256>>>(qkvp, ck, ks, NQKV, 1024);
    conv4_silu_kernel<<<BL_ * H_ / 256, 256>>>(qkvp, cv, vs, NQKV, 2048);

    // beta, l2norm + transpose
    beta_kernel<<<BL_, 128>>>(hs, Wb, beta);
    normtr_kernel<<<dim3(BL_, NH_), 256>>>(qs, ks, vs, beta, qn, kn, kb, vb);

    // delta rule
    chunk_kernel<<<dim3(BH_, NC_), 256, 102528>>>(qn, kn, kb, vb, u, w, att);
    scan_kernel<<<dim3(BH_, 16), 256, SCAN_SMEM>>>(qn, kn, u, w, att, delta);

    // FIR branches
    fir7_kernel<<<BL_ * H_ / 256, 256>>>(vs, fsw, shrt);
    fir64_smem_kernel<<<1024, 256, FIR64_SMEM>>>(vs, flw, lng);

    // gate, mix+rmsnorm (emits bf16 hi/lo), output projection
    gate_kernel<<<BL_, 128>>>(h1, Wf2, bf2, fw);
    mix_rms_kernel<<<dim3(BL_, NH_), 256>>>(shrt, lng, delta, vs, fw, rmsw, mhi, mlo);
    mma_gemm2_kernel<<<dim3(H_ / 128, BL_ / 128), 256, MG_SMEM>>>(
        mhi, mlo, woh, wol, nullptr, out, H_, H_, 0);
}

// round 10
// speedup vs baseline: 1.0565x; 1.0565x over previous
#include <cuda_runtime.h>
#include <cuda_bf16.h>
#include <math.h>
#include <stdint.h>

#define B_   2
#define L_   4096
#define H_   1024
#define NH_  4
#define DK_  256
#define DV_  256
#define C_   32
#define NC_  128
#define BL_  8192
#define BH_  8
#define F1_  2048
#define NQKV 3072

// ------------------------- scratch (static device memory; no allocs) -------
__device__ float g_qkvp[BL_*NQKV];
__device__ float g_qs[BL_*H_], g_ks[BL_*H_], g_vs[BL_*H_];
__device__ float g_qn[BL_*H_], g_kn[BL_*H_], g_kb[BL_*H_], g_vb[BL_*H_];
__device__ float g_u [BL_*H_], g_w [BL_*H_];
__device__ float g_delta[BL_*H_], g_shrt[BL_*H_], g_long[BL_*H_];
__device__ float g_h1[BL_*F1_];
__device__ float g_att[BH_*NC_*C_*C_];
__device__ float g_beta[BL_*NH_];
__device__ float g_fw[BL_*16];
// bf16 hi/lo staging
__device__ __nv_bfloat16 g_ahi[BL_*H_],  g_alo[BL_*H_];
__device__ __nv_bfloat16 g_mhi[BL_*H_],  g_mlo[BL_*H_];
__device__ __nv_bfloat16 g_wqkv_hi[NQKV*H_], g_wqkv_lo[NQKV*H_];
__device__ __nv_bfloat16 g_wf1_hi[F1_*H_],   g_wf1_lo[F1_*H_];
__device__ __nv_bfloat16 g_wo_hi[H_*H_],     g_wo_lo[H_*H_];

__device__ __forceinline__ float sigmoidf_(float x) { return 1.f / (1.f + expf(-x)); }
__device__ __forceinline__ float geluf_(float x) {
    return 0.5f * x * (1.f + erff(x * 0.70710678118654752440f));
}
__device__ __forceinline__ uint32_t smem_u32_(const void* p) {
    uint32_t a;
    asm("{ .reg .u64 t; cvta.to.shared.u64 t, %1; cvt.u32.u64 %0, t; }" : "=r"(a) : "l"(p));
    return a;
}
__device__ __forceinline__ uint32_t pack_bf16_hi_(float x, float y) {
    __nv_bfloat162 h = __halves2bfloat162(__float2bfloat16(x), __float2bfloat16(y));
    return *reinterpret_cast<uint32_t*>(&h);
}
__device__ __forceinline__ uint32_t pack_bf16_lo_(float x, float y) {
    float hx = __bfloat162float(__float2bfloat16(x));
    float hy = __bfloat162float(__float2bfloat16(y));
    __nv_bfloat162 l = __halves2bfloat162(__float2bfloat16(x - hx), __float2bfloat16(y - hy));
    return *reinterpret_cast<uint32_t*>(&l);
}
__device__ __forceinline__ void cp16_(uint32_t dst, const void* src) {
    asm volatile("cp.async.ca.shared.global [%0], [%1], 16;" :: "r"(dst), "l"(src));
}

// ------------------------- prep: fp32 -> bf16 hi/lo ------------------------
__global__ __launch_bounds__(256) void cvt_a_kernel(
    const float* __restrict__ x, __nv_bfloat16* __restrict__ hi, __nv_bfloat16* __restrict__ lo)
{
    int i = (blockIdx.x * 256 + threadIdx.x) * 4;
    float4 v = *(const float4*)(x + i);
    uint2 oh, ol;
    oh.x = pack_bf16_hi_(v.x, v.y); oh.y = pack_bf16_hi_(v.z, v.w);
    ol.x = pack_bf16_lo_(v.x, v.y); ol.y = pack_bf16_lo_(v.z, v.w);
    *(uint2*)(hi + i) = oh;
    *(uint2*)(lo + i) = ol;
}

// W [K][N] -> Wt hi/lo [N][K]  (32x32 smem transpose)
__global__ __launch_bounds__(256) void cvt_wt_kernel(
    const float* __restrict__ W, __nv_bfloat16* __restrict__ hi, __nv_bfloat16* __restrict__ lo,
    int K, int N)
{
    __shared__ float tile[32][33];
    int n0 = blockIdx.x * 32, k0 = blockIdx.y * 32;
    int tx = threadIdx.x & 31, ty = threadIdx.x >> 5;   // 32 x 8
#pragma unroll
    for (int i = 0; i < 4; i++)
        tile[ty + 8 * i][tx] = W[(size_t)(k0 + ty + 8 * i) * N + n0 + tx];
    __syncthreads();
#pragma unroll
    for (int i = 0; i < 4; i++) {
        float v = tile[tx][ty + 8 * i];
        __nv_bfloat16 h = __float2bfloat16(v);
        size_t o = (size_t)(n0 + ty + 8 * i) * K + k0 + tx;
        hi[o] = h;
        lo[o] = __float2bfloat16(v - __bfloat162float(h));
    }
}

// ===================== pipelined warp-mma bf16 split-x3 GEMM ================
// C[M,N] = A[M,K] @ B^T[N,K], bf16 hi/lo inputs. act==1: gelu(+bias).
// CTA 128x128, 8 warps, BK=32, 2-stage cp.async double buffer.
#define MMA_BF16_(c, a0, a1, a2, a3, b0, b1) \
    asm volatile("mma.sync.aligned.m16n8k16.row.col.f32.bf16.bf16.f32 " \
        "{%0,%1,%2,%3}, {%4,%5,%6,%7}, {%8,%9}, {%0,%1,%2,%3};" \
        : "+f"((c)[0]), "+f"((c)[1]), "+f"((c)[2]), "+f"((c)[3]) \
        : "r"(a0), "r"(a1), "r"(a2), "r"(a3), "r"(b0), "r"(b1))

#define MG_SMEM 65536

__device__ __forceinline__ uint32_t frag2_(const uint32_t* sm, int base, int row, int j) {
    return sm[base + row * 16 + ((((j >> 2) ^ ((row >> 1) & 3)) << 2) | (j & 3))];
}

__device__ __forceinline__ void fill_stage_(
    uint32_t smem_b, int stage,
    const __nv_bfloat16* __restrict__ Ahi_g, const __nv_bfloat16* __restrict__ Alo_g,
    const __nv_bfloat16* __restrict__ Bhi_g, const __nv_bfloat16* __restrict__ Blo_g,
    int row0, int col0, int K, int k0, int tid)
{
#pragma unroll
    for (int i = 0; i < 8; i++) {
        int task = i * 256 + tid;            // 0..2047
        int op = task >> 9;                  // 0..3
        int rem = task & 511;
        int row = rem >> 2, chunk = rem & 3;
        const __nv_bfloat16* gp =
            (op == 0) ? Ahi_g + (size_t)(row0 + row) * K :
            (op == 1) ? Alo_g + (size_t)(row0 + row) * K :
            (op == 2) ? Bhi_g + (size_t)(col0 + row) * K :
                        Blo_g + (size_t)(col0 + row) * K;
        gp += k0 + chunk * 8;
        uint32_t word = (uint32_t)(stage * 8192 + op * 2048 + row * 16
                        + ((chunk ^ ((row >> 1) & 3)) << 2));
        cp16_(smem_b + word * 4, gp);
    }
}

__global__ __launch_bounds__(256, 2) void mma_gemm2_kernel(
    const __nv_bfloat16* __restrict__ Ahi_g, const __nv_bfloat16* __restrict__ Alo_g,
    const __nv_bfloat16* __restrict__ Bhi_g, const __nv_bfloat16* __restrict__ Blo_g,
    const float* __restrict__ bias, float* __restrict__ C,
    int N, int K, int act)
{
    extern __shared__ __align__(16) uint32_t smem_u[];
    const uint32_t smem_b = smem_u32_(smem_u);
    const int tid = threadIdx.x;
    const int wid = tid >> 5, lane = tid & 31;
    const int g = lane >> 2, t = lane & 3;
    const int warp_m = (wid & 3) * 32;
    const int warp_n = (wid >> 2) * 64;
    const int row0 = blockIdx.y * 128, col0 = blockIdx.x * 128;

    float acc[2][8][4];
#pragma unroll
    for (int mt = 0; mt < 2; mt++)
#pragma unroll
        for (int nt = 0; nt < 8; nt++)
#pragma unroll
            for (int e = 0; e < 4; e++) acc[mt][nt][e] = 0.f;

    const int ntl = K >> 5;
    fill_stage_(smem_b, 0, Ahi_g, Alo_g, Bhi_g, Blo_g, row0, col0, K, 0, tid);
    asm volatile("cp.async.commit_group;");

    for (int tt = 0; tt < ntl; tt++) {
        if (tt + 1 < ntl) {
            fill_stage_(smem_b, (tt + 1) & 1, Ahi_g, Alo_g, Bhi_g, Blo_g,
                        row0, col0, K, (tt + 1) * 32, tid);
            asm volatile("cp.async.commit_group;");
            asm volatile("cp.async.wait_group 1;");
        } else {
            asm volatile("cp.async.wait_group 0;");
        }
        __syncthreads();

        const int sb = (tt & 1) * 8192;
#pragma unroll
        for (int ks = 0; ks < 2; ks++) {
            const int cA = ks * 8 + t, cB = cA + 4;
            uint32_t ah[2][4], al[2][4];
#pragma unroll
            for (int mt = 0; mt < 2; mt++) {
                int r = warp_m + mt * 16 + g;
                ah[mt][0] = frag2_(smem_u, sb, r, cA);
                ah[mt][1] = frag2_(smem_u, sb, r + 8, cA);
                ah[mt][2] = frag2_(smem_u, sb, r, cB);
                ah[mt][3] = frag2_(smem_u, sb, r + 8, cB);
                al[mt][0] = frag2_(smem_u, sb + 2048, r, cA);
                al[mt][1] = frag2_(smem_u, sb + 2048, r + 8, cA);
                al[mt][2] = frag2_(smem_u, sb + 2048, r, cB);
                al[mt][3] = frag2_(smem_u, sb + 2048, r + 8, cB);
            }
#pragma unroll
            for (int nt = 0; nt < 8; nt++) {
                int n = warp_n + nt * 8 + g;
                uint32_t bh0 = frag2_(smem_u, sb + 4096, n, cA);
                uint32_t bh1 = frag2_(smem_u, sb + 4096, n, cB);
                uint32_t bl0 = frag2_(smem_u, sb + 6144, n, cA);
                uint32_t bl1 = frag2_(smem_u, sb + 6144, n, cB);
#pragma unroll
                for (int mt = 0; mt < 2; mt++) {
                    MMA_BF16_(acc[mt][nt], ah[mt][0], ah[mt][1], ah[mt][2], ah[mt][3], bh0, bh1);
                    MMA_BF16_(acc[mt][nt], ah[mt][0], ah[mt][1], ah[mt][2], ah[mt][3], bl0, bl1);
                    MMA_BF16_(acc[mt][nt], al[mt][0], al[mt][1], al[mt][2], al[mt][3], bh0, bh1);
                }
            }
        }
        __syncthreads();
    }

    // ---- epilogue -----------------------------------------------------------
#pragma unroll
    for (int mt = 0; mt < 2; mt++) {
        int r0g = row0 + warp_m + mt * 16 + g;
#pragma unroll
        for (int nt = 0; nt < 8; nt++) {
            int c = col0 + warp_n + nt * 8 + 2 * t;
            float2 v0, v1;
            v0.x = acc[mt][nt][0]; v0.y = acc[mt][nt][1];
            v1.x = acc[mt][nt][2]; v1.y = acc[mt][nt][3];
            if (act == 1) {
                float b0 = bias[c], b1 = bias[c + 1];
                v0.x = geluf_(v0.x + b0); v0.y = geluf_(v0.y + b1);
                v1.x = geluf_(v1.x + b0); v1.y = geluf_(v1.y + b1);
            }
            *(float2*)(C + (size_t)r0g * N + c) = v0;
            *(float2*)(C + (size_t)(r0g + 8) * N + c) = v1;
        }
    }
}

// ------------------------- short causal depthwise conv (K=4) + silu ---------
__global__ __launch_bounds__(256) void conv4_silu_kernel(
    const float* __restrict__ x, const float* __restrict__ f, float* __restrict__ y,
    int xstride, int xoff)
{
    int idx = blockIdx.x * 256 + threadIdx.x;      // (bl, c)
    int c  = idx & (H_ - 1);
    int bl = idx >> 10;
    int l  = bl & (L_ - 1);
    const float* xp = x + (size_t)bl * xstride + xoff + c;
    float4 fv = *(const float4*)(f + c * 4);
    float acc = fv.w * xp[0];
    if (l >= 1) acc += fv.z * xp[-xstride];
    if (l >= 2) acc += fv.y * xp[-2 * xstride];
    if (l >= 3) acc += fv.x * xp[-3 * xstride];
    y[idx] = acc * sigmoidf_(acc);
}

// ------------------------- beta = sigmoid(hs @ Wb) --------------------------
__global__ __launch_bounds__(128) void beta_kernel(
    const float* __restrict__ hs, const float* __restrict__ Wb, float* __restrict__ beta)
{
    int bl = blockIdx.x;
    int wrp = threadIdx.x >> 5, lane = threadIdx.x & 31;
    const float* hp = hs + (size_t)bl * H_;
    float acc = 0.f;
    for (int d = lane; d < H_; d += 32) acc += hp[d] * Wb[d * NH_ + wrp];
#pragma unroll
    for (int o = 16; o; o >>= 1) acc += __shfl_xor_sync(0xffffffffu, acc, o);
    if (lane == 0) beta[bl * NH_ + wrp] = sigmoidf_(acc);
}

// ------------------------- l2norm + beta-scale + [B,H,L,D] transpose --------
__global__ __launch_bounds__(256) void normtr_kernel(
    const float* __restrict__ qs, const float* __restrict__ ks, const float* __restrict__ vs,
    const float* __restrict__ beta,
    float* __restrict__ qn, float* __restrict__ kn, float* __restrict__ kb, float* __restrict__ vb)
{
    int bl = blockIdx.x, h = blockIdx.y, d = threadIdx.x;
    int b = bl >> 12;
    int l = bl & (L_ - 1);
    size_t src = (size_t)bl * H_ + h * DK_ + d;
    float qv = qs[src], kv = ks[src], vv = vs[src];
    float s1 = qv * qv, s2 = kv * kv;
#pragma unroll
    for (int o = 16; o; o >>= 1) {
        s1 += __shfl_xor_sync(0xffffffffu, s1, o);
        s2 += __shfl_xor_sync(0xffffffffu, s2, o);
    }
    __shared__ float r1[8], r2[8];
    __shared__ float inv1, inv2;
    int lane = d & 31, wid = d >> 5;
    if (lane == 0) { r1[wid] = s1; r2[wid] = s2; }
    __syncthreads();
    if (d == 0) {
        float t1 = 0.f, t2 = 0.f;
        for (int i = 0; i < 8; i++) { t1 += r1[i]; t2 += r2[i]; }
        inv1 = rsqrtf(t1);
        inv2 = rsqrtf(t2);
    }
    __syncthreads();
    float bt = beta[bl * NH_ + h];
    size_t dst = (((size_t)b * NH_ + h) * L_ + l) * DK_ + d;
    float knv = kv * inv2;
    qn[dst] = qv * inv1;
    kn[dst] = knv;
    kb[dst] = knv * bt;
    vb[dst] = vv * bt;
}

// ------------------------- per-chunk: UT transform, u, w, attn --------------
__global__ __launch_bounds__(256) void chunk_kernel(
    const float* __restrict__ qn, const float* __restrict__ kn,
    const float* __restrict__ kb, const float* __restrict__ vb,
    float* __restrict__ U, float* __restrict__ Wm, float* __restrict__ ATT)
{
    extern __shared__ float sm[];
    float* sk  = sm;            // 32x256
    float* skb = sm + 8192;     // 32x256
    float* sx  = sm + 16384;    // 32x256 (vb then qn)
    float* T   = sm + 24576;    // 32x33
    int bh = blockIdx.x, n = blockIdx.y;
    int tid = threadIdx.x;
    size_t base = ((size_t)bh * L_ + n * C_) * DK_;

    for (int i = tid; i < 2048; i += 256) {
        ((float4*)sk)[i]  = ((const float4*)(kn + base))[i];
        ((float4*)skb)[i] = ((const float4*)(kb + base))[i];
        ((float4*)sx)[i]  = ((const float4*)(vb + base))[i];
    }
    __syncthreads();

    // A = -(kb @ kn^T) * strict_lower
    for (int e = tid; e < 1024; e += 256) {
        int i = e >> 5, j = e & 31;
        float a = 0.f;
        if (j < i) {
            const float* pi = skb + i * 256;
            const float* pj = sk + j * 256;
            for (int d = 0; d < 256; d++) a -= pi[d] * pj[d];
        }
        T[i * 33 + j] = a;
    }
    __syncthreads();

    // forward substitution (warp 0)
    if (tid < 32) {
        int j = tid;
        for (int i = 1; i < 32; i++) {
            float rv = T[i * 33 + j];
            float acc = rv;
            for (int m = 1; m < i; m++)
                acc += __shfl_sync(0xffffffffu, rv, m) * T[m * 33 + j];
            __syncwarp();
            T[i * 33 + j] = acc;
            __syncwarp();
        }
        T[j * 33 + j] = 1.f;
    }
    __syncthreads();

    // u = T @ vb, w = T @ kb
    for (int idx = tid; idx < 8192; idx += 256) {
        int c = idx >> 8, d = idx & 255;
        float au = 0.f, aw = 0.f;
#pragma unroll
        for (int j = 0; j < 32; j++) {
            float t = T[c * 33 + j];
            au += t * sx[j * 256 + d];
            aw += t * skb[j * 256 + d];
        }
        U[base + idx]  = au;
        Wm[base + idx] = aw;
    }
    __syncthreads();

    // attn = (qn @ kn^T) * causal
    for (int i = tid; i < 2048; i += 256)
        ((float4*)sx)[i] = ((const float4*)(qn + base))[i];
    __syncthreads();
    float* att = ATT + ((size_t)bh * NC_ + n) * 1024;
    for (int e = tid; e < 1024; e += 256) {
        int c = e >> 5, j = e & 31;
        float a = 0.f;
        if (j <= c) {
            const float* pq = sx + c * 256;
            const float* pk = sk + j * 256;
            for (int d = 0; d < 256; d++) a += pq[d] * pk[d];
        }
        att[e] = a;
    }
}

// ------------------------- sequential chunk scan (dv tiled by 16) -----------
// R7 layout (verified): S [256][16]; S-read is broadcast + 16-bank spread.
#define SCAN_SMEM (30720 * 4)
__global__ __launch_bounds__(256) void scan_kernel(
    const float* __restrict__ qn, const float* __restrict__ kn,
    const float* __restrict__ U, const float* __restrict__ Wm,
    const float* __restrict__ ATT, float* __restrict__ OUT)
{
    extern __shared__ float sm[];
    float* S   = sm;            // [256][16]
    float* sq  = sm + 4096;     // [32][256]
    float* sk  = sm + 12288;    // [32][256]
    float* sw  = sm + 20480;    // [32][256]
    float* su  = sm + 28672;    // [32][16]
    float* sut = sm + 29184;    // [32][16]
    float* sat = sm + 29696;    // [32][32]
    const int bh = blockIdx.x, tile = blockIdx.y;
    const int tid = threadIdx.x;
    const int b = bh >> 2, h = bh & 3;
    const int g = tid >> 3, eg = tid & 7;

    for (int i = tid; i < 4096; i += 256) S[i] = 0.f;

    for (int n = 0; n < NC_; n++) {
        __syncthreads();
        size_t base = ((size_t)bh * L_ + n * C_) * 256;
        for (int i = tid; i < 2048; i += 256) {
            ((float4*)sq)[i] = ((const float4*)(qn + base))[i];
            ((float4*)sk)[i] = ((const float4*)(kn + base))[i];
            ((float4*)sw)[i] = ((const float4*)(Wm + base))[i];
        }
        if (tid < 128) {
            int c = tid >> 2, e4 = tid & 3;
            ((float4*)su)[tid] = *(const float4*)(U + base + c * 256 + tile * 16 + e4 * 4);
        }
        ((float4*)sat)[tid] = ((const float4*)(ATT + ((size_t)bh * NC_ + n) * 1024))[tid];
        __syncthreads();

        // u_t = u - w@S ; o_partial = q@S   (full dk = 256)
        float2 aw = make_float2(0.f, 0.f);
        float2 aq = make_float2(0.f, 0.f);
        const float* wr = sw + g * 256;
        const float* qr = sq + g * 256;
#pragma unroll 8
        for (int d = 0; d < 256; d++) {
            float2 s2 = *(float2*)(S + d * 16 + eg * 2);
            float wv = wr[d], qv = qr[d];
            aw.x += wv * s2.x; aw.y += wv * s2.y;
            aq.x += qv * s2.x; aq.y += qv * s2.y;
        }
        float2 uv = *(float2*)(su + g * 16 + eg * 2);
        float2 ut = make_float2(uv.x - aw.x, uv.y - aw.y);
        *(float2*)(sut + g * 16 + eg * 2) = ut;
        __syncthreads();

        // o = q@S + attn @ u_t
        const float* ar = sat + g * 32;
#pragma unroll
        for (int j = 0; j < 32; j++) {
            float av = ar[j];
            float2 u2 = *(float2*)(sut + j * 16 + eg * 2);
            aq.x += av * u2.x; aq.y += av * u2.y;
        }
        *(float2*)(OUT + (size_t)(b * L_ + n * C_ + g) * H_ + h * 256 + tile * 16 + eg * 2) = aq;

        // S += k^T @ u_t : thread owns d octet g*8.., e pair eg
        float2 accS[8];
#pragma unroll
        for (int i = 0; i < 8; i++) accS[i] = make_float2(0.f, 0.f);
        for (int c2 = 0; c2 < 32; c2++) {
            float2 u2 = *(float2*)(sut + c2 * 16 + eg * 2);
            const float* kr = sk + c2 * 256 + g * 8;
            float4 k0 = *(const float4*)(kr);
            float4 k1 = *(const float4*)(kr + 4);
            accS[0].x += k0.x * u2.x; accS[0].y += k0.x * u2.y;
            accS[1].x += k0.y * u2.x; accS[1].y += k0.y * u2.y;
            accS[2].x += k0.z * u2.x; accS[2].y += k0.z * u2.y;
            accS[3].x += k0.w * u2.x; accS[3].y += k0.w * u2.y;
            accS[4].x += k1.x * u2.x; accS[4].y += k1.x * u2.y;
            accS[5].x += k1.y * u2.x; accS[5].y += k1.y * u2.y;
            accS[6].x += k1.z * u2.x; accS[6].y += k1.z * u2.y;
            accS[7].x += k1.w * u2.x; accS[7].y += k1.w * u2.y;
        }
#pragma unroll
        for (int i = 0; i < 8; i++) {
            float2 s2 = *(float2*)(S + (g * 8 + i) * 16 + eg * 2);
            s2.x += accS[i].x; s2.y += accS[i].y;
            *(float2*)(S + (g * 8 + i) * 16 + eg * 2) = s2;
        }
    }
}

// ------------------------- FIR K=7 (unrolled) -------------------------------
__global__ __launch_bounds__(256) void fir7_kernel(
    const float* __restrict__ x, const float* __restrict__ f, float* __restrict__ y)
{
    int idx = blockIdx.x * 256 + threadIdx.x;
    int c  = idx & (H_ - 1);
    int bl = idx >> 10;
    int l  = bl & (L_ - 1);
    const float* fp = f + (size_t)c * 7;
    float acc = 0.f;
#pragma unroll
    for (int t = 0; t < 7; t++) {
        int dl = t - 6;
        if (l + dl >= 0) acc += x[idx + dl * H_] * fp[t];
    }
    y[idx] = acc;
}

// ------------------------- FIR K=64: smem tile + register sliding window ----
#define FIR64_SMEM ((127 * 128 + 64 * 129) * 4)
__global__ __launch_bounds__(256) void fir64_smem_kernel(
    const float* __restrict__ x, const float* __restrict__ f, float* __restrict__ y)
{
    extern __shared__ float fsm[];
    float* sx = fsm;                 // 127 x 128
    float* sf = fsm + 127 * 128;     // 64 x 129
    const int ctile = blockIdx.x & 7;
    const int ltile = blockIdx.x >> 3;
    const int l0 = ltile * 64;
    const int lb = l0 & (L_ - 1);
    const int c0 = ctile * 128;
    const int tid = threadIdx.x;

    for (int i = tid; i < 64 * 128; i += 256) {
        int c = i >> 6, t = i & 63;
        sf[t * 129 + c] = f[(size_t)(c0 + c) * 64 + t];
    }
    for (int i = tid; i < 127 * 128; i += 256) {
        int j = i >> 7, c = i & 127;
        int lrel = lb + j - 63;
        float v = 0.f;
        if (lrel >= 0)
            v = x[(size_t)(l0 + j - 63) * H_ + c0 + c];
        sx[j * 128 + c] = v;
    }
    __syncthreads();

    const int c = tid & 127;
    const int lg = (tid >> 7) * 32;
    float acc[32], win[32];
#pragma unroll
    for (int i = 0; i < 32; i++) acc[i] = 0.f;
#pragma unroll
    for (int i = 0; i < 32; i++) win[i] = sx[(lg + i) * 128 + c];
#pragma unroll
    for (int t = 0; t < 64; t++) {
        float ft = sf[t * 129 + c];
#pragma unroll
        for (int i = 0; i < 32; i++) acc[i] += ft * win[i];
        if (t < 63) {
#pragma unroll
            for (int i = 0; i < 31; i++) win[i] = win[i + 1];
            win[31] = sx[(lg + t + 32) * 128 + c];
        }
    }
#pragma unroll
    for (int i = 0; i < 32; i++)
        y[(size_t)(l0 + lg + i) * H_ + c0 + c] = acc[i];
}

// ------------------------- fusion gate: h1 @ Wf2 + bf2 -> softmax4 ----------
__global__ __launch_bounds__(128) void gate_kernel(
    const float* __restrict__ h1, const float* __restrict__ Wf2,
    const float* __restrict__ bf2, float* __restrict__ fw)
{
    int bl = blockIdx.x, tid = threadIdx.x;
    float acc[16];
#pragma unroll
    for (int j = 0; j < 16; j++) acc[j] = 0.f;
    const float* hp = h1 + (size_t)bl * F1_;
    for (int d = tid; d < F1_; d += 128) {
        float hv = hp[d];
        const float4* w4 = (const float4*)(Wf2 + d * 16);
        float4 w0 = w4[0], w1 = w4[1], w2 = w4[2], w3 = w4[3];
        acc[0] += hv * w0.x; acc[1] += hv * w0.y; acc[2] += hv * w0.z; acc[3] += hv * w0.w;
        acc[4] += hv * w1.x; acc[5] += hv * w1.y; acc[6] += hv * w1.z; acc[7] += hv * w1.w;
        acc[8] += hv * w2.x; acc[9] += hv * w2.y; acc[10] += hv * w2.z; acc[11] += hv * w2.w;
        acc[12] += hv * w3.x; acc[13] += hv * w3.y; acc[14] += hv * w3.z; acc[15] += hv * w3.w;
    }
    __shared__ float red[16][129];
    __shared__ float logit[16];
#pragma unroll
    for (int j = 0; j < 16; j++) red[j][tid] = acc[j];
    __syncthreads();
    if (tid < 16) {
        float s = bf2[tid];
        for (int i = 0; i < 128; i++) s += red[tid][i];
        logit[tid] = s;
    }
    __syncthreads();
    if (tid < 4) {
        float l0 = logit[tid * 4], l1 = logit[tid * 4 + 1];
        float l2 = logit[tid * 4 + 2], l3 = logit[tid * 4 + 3];
        float m = fmaxf(fmaxf(l0, l1), fmaxf(l2, l3));
        float e0 = expf(l0 - m), e1 = expf(l1 - m), e2 = expf(l2 - m), e3 = expf(l3 - m);
        float inv = 1.f / (e0 + e1 + e2 + e3);
        float* o = fw + (size_t)bl * 16 + tid * 4;
        o[0] = e0 * inv; o[1] = e1 * inv; o[2] = e2 * inv; o[3] = e3 * inv;
    }
}

// ------------------------- branch mix + per-head rmsnorm -> bf16 hi/lo ------
__global__ __launch_bounds__(256) void mix_rms_kernel(
    const float* __restrict__ br_s, const float* __restrict__ br_l,
    const float* __restrict__ br_d, const float* __restrict__ br_v,
    const float* __restrict__ fw, const float* __restrict__ rmsw,
    __nv_bfloat16* __restrict__ Mhi, __nv_bfloat16* __restrict__ Mlo)
{
    int bl = blockIdx.x, h = blockIdx.y, d = threadIdx.x;
    size_t i = (size_t)bl * H_ + h * 256 + d;
    const float* f = fw + (size_t)bl * 16 + h * 4;
    float val = f[0] * br_s[i] + f[1] * br_l[i] + f[2] * br_d[i] + f[3] * br_v[i];
    float ss = val * val;
#pragma unroll
    for (int o = 16; o; o >>= 1) ss += __shfl_xor_sync(0xffffffffu, ss, o);
    __shared__ float red[8];
    __shared__ float scale;
    if ((d & 31) == 0) red[d >> 5] = ss;
    __syncthreads();
    if (d == 0) {
        float t = 0.f;
        for (int k = 0; k < 8; k++) t += red[k];
        scale = rsqrtf(t * (1.f / 256.f) + 1e-5f);
    }
    __syncthreads();
    float o = val * scale * rmsw[d];
    __nv_bfloat16 hb = __float2bfloat16(o);
    Mhi[i] = hb;
    Mlo[i] = __float2bfloat16(o - __bfloat162float(hb));
}

// ------------------------- launcher ----------------------------------------
extern "C" void kernel_launch(void* const* d_in, const int* in_sizes, int n_in,
                              void* d_out, int out_size)
{
    const float* hs   = (const float*)d_in[0];
    const float* Wq   = (const float*)d_in[1];
    const float* Wk   = (const float*)d_in[2];
    const float* Wv   = (const float*)d_in[3];
    const float* Wb   = (const float*)d_in[4];
    const float* cq   = (const float*)d_in[5];
    const float* ck   = (const float*)d_in[6];
    const float* cv   = (const float*)d_in[7];
    const float* fsw  = (const float*)d_in[8];
    const float* flw  = (const float*)d_in[9];
    const float* Wf1  = (const float*)d_in[10];
    const float* bf1  = (const float*)d_in[11];
    const float* Wf2  = (const float*)d_in[12];
    const float* bf2  = (const float*)d_in[13];
    const float* rmsw = (const float*)d_in[14];
    const float* Wo   = (const float*)d_in[15];
    float* out = (float*)d_out;

    float *qkvp, *qs, *ks, *vs, *qn, *kn, *kb, *vb;
    float *u, *w, *delta, *shrt, *lng, *h1, *att, *beta, *fw;
    __nv_bfloat16 *ahi, *alo, *mhi, *mlo, *wqh, *wql, *wf1h, *wf1l, *woh, *wol;
    cudaGetSymbolAddress((void**)&qkvp, g_qkvp);
    cudaGetSymbolAddress((void**)&qs, g_qs);
    cudaGetSymbolAddress((void**)&ks, g_ks);
    cudaGetSymbolAddress((void**)&vs, g_vs);
    cudaGetSymbolAddress((void**)&qn, g_qn);
    cudaGetSymbolAddress((void**)&kn, g_kn);
    cudaGetSymbolAddress((void**)&kb, g_kb);
    cudaGetSymbolAddress((void**)&vb, g_vb);
    cudaGetSymbolAddress((void**)&u, g_u);
    cudaGetSymbolAddress((void**)&w, g_w);
    cudaGetSymbolAddress((void**)&delta, g_delta);
    cudaGetSymbolAddress((void**)&shrt, g_shrt);
    cudaGetSymbolAddress((void**)&lng, g_long);
    cudaGetSymbolAddress((void**)&h1, g_h1);
    cudaGetSymbolAddress((void**)&att, g_att);
    cudaGetSymbolAddress((void**)&beta, g_beta);
    cudaGetSymbolAddress((void**)&fw, g_fw);
    cudaGetSymbolAddress((void**)&ahi, g_ahi);
    cudaGetSymbolAddress((void**)&alo, g_alo);
    cudaGetSymbolAddress((void**)&mhi, g_mhi);
    cudaGetSymbolAddress((void**)&mlo, g_mlo);
    cudaGetSymbolAddress((void**)&wqh, g_wqkv_hi);
    cudaGetSymbolAddress((void**)&wql, g_wqkv_lo);
    cudaGetSymbolAddress((void**)&wf1h, g_wf1_hi);
    cudaGetSymbolAddress((void**)&wf1l, g_wf1_lo);
    cudaGetSymbolAddress((void**)&woh, g_wo_hi);
    cudaGetSymbolAddress((void**)&wol, g_wo_lo);

    cudaFuncSetAttribute(mma_gemm2_kernel, cudaFuncAttributeMaxDynamicSharedMemorySize, MG_SMEM);
    cudaFuncSetAttribute(chunk_kernel, cudaFuncAttributeMaxDynamicSharedMemorySize, 102528);
    cudaFuncSetAttribute(scan_kernel,  cudaFuncAttributeMaxDynamicSharedMemorySize, SCAN_SMEM);
    cudaFuncSetAttribute(fir64_smem_kernel, cudaFuncAttributeMaxDynamicSharedMemorySize, FIR64_SMEM);

    // ---- prep: bf16 hi/lo conversions (A once, weights once, transposed) ---
    cvt_a_kernel<<<BL_ * H_ / 1024, 256>>>(hs, ahi, alo);
    cvt_wt_kernel<<<dim3(32, 32), 256>>>(Wq, wqh,             wql,             H_, H_);
    cvt_wt_kernel<<<dim3(32, 32), 256>>>(Wk, wqh + 1024 * H_, wql + 1024 * H_, H_, H_);
    cvt_wt_kernel<<<dim3(32, 32), 256>>>(Wv, wqh + 2048 * H_, wql + 2048 * H_, H_, H_);
    cvt_wt_kernel<<<dim3(64, 32), 256>>>(Wf1, wf1h, wf1l, H_, F1_);
    cvt_wt_kernel<<<dim3(32, 32), 256>>>(Wo, woh, wol, H_, H_);

    // ---- fused qkv projection + gate-MLP first layer -----------------------
    mma_gemm2_kernel<<<dim3(NQKV / 128, BL_ / 128), 256, MG_SMEM>>>(
        ahi, alo, wqh, wql, nullptr, qkvp, NQKV, H_, 0);
    mma_gemm2_kernel<<<dim3(F1_ / 128, BL_ / 128), 256, MG_SMEM>>>(
        ahi, alo, wf1h, wf1l, bf1, h1, F1_, H_, 1);

    // short conv + silu (reads packed qkv)
    conv4_silu_kernel<<<BL_ * H_ / 256, 256>>>(qkvp, cq, qs, NQKV, 0);
    conv4_silu_kernel<<<BL_ * H_ / 256, 256>>>(qkvp, ck, ks, NQKV, 1024);
    conv4_silu_kernel<<<BL_ * H_ / 256, 256>>>(qkvp, cv, vs, NQKV, 2048);

    // beta, l2norm + transpose
    beta_kernel<<<BL_, 128>>>(hs, Wb, beta);
    normtr_kernel<<<dim3(BL_, NH_), 256>>>(qs, ks, vs, beta, qn, kn, kb, vb);

    // delta rule
    chunk_kernel<<<dim3(BH_, NC_), 256, 102528>>>(qn, kn, kb, vb, u, w, att);
    scan_kernel<<<dim3(BH_, 16), 256, SCAN_SMEM>>>(qn, kn, u, w, att, delta);

    // FIR branches
    fir7_kernel<<<BL_ * H_ / 256, 256>>>(vs, fsw, shrt);
    fir64_smem_kernel<<<1024, 256, FIR64_SMEM>>>(vs, flw, lng);

    // gate, mix+rmsnorm (emits bf16 hi/lo), output projection
    gate_kernel<<<BL_, 128>>>(h1, Wf2, bf2, fw);
    mix_rms_kernel<<<dim3(BL_, NH_), 256>>>(shrt, lng, delta, vs, fw, rmsw, mhi, mlo);
    mma_gemm2_kernel<<<dim3(H_ / 128, BL_ / 128), 256, MG_SMEM>>>(
        mhi, mlo, woh, wol, nullptr, out, H_, H_, 0);
}

// round 11
// speedup vs baseline: 1.1931x; 1.1293x over previous
#include <cuda_runtime.h>
#include <cuda_bf16.h>
#include <math.h>
#include <stdint.h>

#define B_   2
#define L_   4096
#define H_   1024
#define NH_  4
#define DK_  256
#define DV_  256
#define C_   32
#define NC_  128
#define BL_  8192
#define BH_  8
#define F1_  2048
#define NQKV 3072

// ------------------------- scratch (static device memory; no allocs) -------
__device__ float g_qkvp[BL_*NQKV];
__device__ float g_qs[BL_*H_], g_ks[BL_*H_], g_vs[BL_*H_];
__device__ float g_qn[BL_*H_], g_kn[BL_*H_], g_kb[BL_*H_], g_vb[BL_*H_];
__device__ float g_u [BL_*H_], g_w [BL_*H_];
__device__ float g_delta[BL_*H_], g_shrt[BL_*H_], g_long[BL_*H_];
__device__ float g_h1[BL_*F1_];
__device__ float g_att[BH_*NC_*C_*C_];
__device__ float g_beta[BL_*NH_];
__device__ float g_fw[BL_*16];
// bf16 hi/lo staging
__device__ __nv_bfloat16 g_ahi[BL_*H_],  g_alo[BL_*H_];
__device__ __nv_bfloat16 g_mhi[BL_*H_],  g_mlo[BL_*H_];
__device__ __nv_bfloat16 g_wqkv_hi[NQKV*H_], g_wqkv_lo[NQKV*H_];
__device__ __nv_bfloat16 g_wf1_hi[F1_*H_],   g_wf1_lo[F1_*H_];
__device__ __nv_bfloat16 g_wo_hi[H_*H_],     g_wo_lo[H_*H_];

__device__ __forceinline__ float sigmoidf_(float x) { return 1.f / (1.f + expf(-x)); }
__device__ __forceinline__ float geluf_(float x) {
    return 0.5f * x * (1.f + erff(x * 0.70710678118654752440f));
}
__device__ __forceinline__ uint32_t smem_u32_(const void* p) {
    uint32_t a;
    asm("{ .reg .u64 t; cvta.to.shared.u64 t, %1; cvt.u32.u64 %0, t; }" : "=r"(a) : "l"(p));
    return a;
}
__device__ __forceinline__ uint32_t pack_bf16_hi_(float x, float y) {
    __nv_bfloat162 h = __halves2bfloat162(__float2bfloat16(x), __float2bfloat16(y));
    return *reinterpret_cast<uint32_t*>(&h);
}
__device__ __forceinline__ uint32_t pack_bf16_lo_(float x, float y) {
    float hx = __bfloat162float(__float2bfloat16(x));
    float hy = __bfloat162float(__float2bfloat16(y));
    __nv_bfloat162 l = __halves2bfloat162(__float2bfloat16(x - hx), __float2bfloat16(y - hy));
    return *reinterpret_cast<uint32_t*>(&l);
}
__device__ __forceinline__ void cp16_(uint32_t dst, const void* src) {
    asm volatile("cp.async.ca.shared.global [%0], [%1], 16;" :: "r"(dst), "l"(src));
}

// ------------------------- prep: fp32 -> bf16 hi/lo ------------------------
__global__ __launch_bounds__(256) void cvt_a_kernel(
    const float* __restrict__ x, __nv_bfloat16* __restrict__ hi, __nv_bfloat16* __restrict__ lo)
{
    int i = (blockIdx.x * 256 + threadIdx.x) * 4;
    float4 v = *(const float4*)(x + i);
    uint2 oh, ol;
    oh.x = pack_bf16_hi_(v.x, v.y); oh.y = pack_bf16_hi_(v.z, v.w);
    ol.x = pack_bf16_lo_(v.x, v.y); ol.y = pack_bf16_lo_(v.z, v.w);
    *(uint2*)(hi + i) = oh;
    *(uint2*)(lo + i) = ol;
}

// W [K][N] -> Wt hi/lo [N][K]  (32x32 smem transpose)
__global__ __launch_bounds__(256) void cvt_wt_kernel(
    const float* __restrict__ W, __nv_bfloat16* __restrict__ hi, __nv_bfloat16* __restrict__ lo,
    int K, int N)
{
    __shared__ float tile[32][33];
    int n0 = blockIdx.x * 32, k0 = blockIdx.y * 32;
    int tx = threadIdx.x & 31, ty = threadIdx.x >> 5;   // 32 x 8
#pragma unroll
    for (int i = 0; i < 4; i++)
        tile[ty + 8 * i][tx] = W[(size_t)(k0 + ty + 8 * i) * N + n0 + tx];
    __syncthreads();
#pragma unroll
    for (int i = 0; i < 4; i++) {
        float v = tile[tx][ty + 8 * i];
        __nv_bfloat16 h = __float2bfloat16(v);
        size_t o = (size_t)(n0 + ty + 8 * i) * K + k0 + tx;
        hi[o] = h;
        lo[o] = __float2bfloat16(v - __bfloat162float(h));
    }
}

// ===================== warp-mma bf16 split-x3 GEMM (ldmatrix) ===============
// C[M,N] = A[M,K] @ B^T[N,K], bf16 hi/lo inputs. act==1: gelu(+bias).
// CTA 128x128, 8 warps (each 32x64), BK=64, single-buffered (2 CTAs/SM hide
// the fill). Fragment loads via ldmatrix.x4 (12 LDSM vs 48 LDS per k16).
// smem tile: word(row, j) = row*32 + (((j>>2) ^ (row&7))<<2 | (j&3)),
// 16B chunk (row, c) at phys chunk c ^ (row&7) — ldmatrix tiles (8 rows, one
// chunk) hit 8 distinct bank quads -> conflict-free.
#define MMA_BF16_(c, a0, a1, a2, a3, b0, b1) \
    asm volatile("mma.sync.aligned.m16n8k16.row.col.f32.bf16.bf16.f32 " \
        "{%0,%1,%2,%3}, {%4,%5,%6,%7}, {%8,%9}, {%0,%1,%2,%3};" \
        : "+f"((c)[0]), "+f"((c)[1]), "+f"((c)[2]), "+f"((c)[3]) \
        : "r"(a0), "r"(a1), "r"(a2), "r"(a3), "r"(b0), "r"(b1))

#define LDSM_X4_(r0, r1, r2, r3, addr) \
    asm volatile("ldmatrix.sync.aligned.m8n8.x4.shared.b16 {%0,%1,%2,%3}, [%4];" \
        : "=r"(r0), "=r"(r1), "=r"(r2), "=r"(r3) : "r"(addr))

#define MG_SMEM 65536

__global__ __launch_bounds__(256, 2) void mma_gemm2_kernel(
    const __nv_bfloat16* __restrict__ Ahi_g, const __nv_bfloat16* __restrict__ Alo_g,
    const __nv_bfloat16* __restrict__ Bhi_g, const __nv_bfloat16* __restrict__ Blo_g,
    const float* __restrict__ bias, float* __restrict__ C,
    int N, int K, int act)
{
    extern __shared__ __align__(16) uint32_t smem_u[];
    const uint32_t smem_b = smem_u32_(smem_u);
    const int tid = threadIdx.x;
    const int wid = tid >> 5, lane = tid & 31;
    const int g = lane >> 2, t = lane & 3;
    const int warp_m = (wid & 3) * 32;
    const int warp_n = (wid >> 2) * 64;
    const int row0 = blockIdx.y * 128, col0 = blockIdx.x * 128;

    // ldmatrix per-lane addressing:
    // A tiles (per mt): q0 rows +0..7 klo | q1 rows +8..15 klo | q2 +0..7 khi | q3 +8..15 khi
    // B tiles (per nt-pair p): q0 n+0..7 klo | q1 n+0..7 khi | q2 n+8..15 klo | q3 n+8..15 khi
    const int qq = lane >> 3, rr = lane & 7;
    const int arow = warp_m + ((qq & 1) << 3) + rr;       // mt=0 row
    const int aqb  = (qq >> 1) & 1;                       // k chunk bit
    const int brow = warp_n + ((qq >> 1) << 3) + rr;      // p=0 n row
    const int bqb  = qq & 1;                              // k chunk bit

    float acc[2][8][4];
#pragma unroll
    for (int mt = 0; mt < 2; mt++)
#pragma unroll
        for (int nt = 0; nt < 8; nt++)
#pragma unroll
            for (int e = 0; e < 4; e++) acc[mt][nt][e] = 0.f;

    for (int k0 = 0; k0 < K; k0 += 64) {
        __syncthreads();
        // ---- fill 4 tiles via cp.async: op 0=Ahi 1=Alo 2=Bhi 3=Blo ---------
#pragma unroll
        for (int i = 0; i < 16; i++) {
            const int op = i >> 2;
            int rem = (i & 3) * 256 + tid;     // 0..1023
            int row = rem >> 3, c = rem & 7;
            const __nv_bfloat16* gsrc =
                (op == 0) ? Ahi_g + (size_t)(row0 + row) * K + k0 + c * 8 :
                (op == 1) ? Alo_g + (size_t)(row0 + row) * K + k0 + c * 8 :
                (op == 2) ? Bhi_g + (size_t)(col0 + row) * K + k0 + c * 8 :
                            Blo_g + (size_t)(col0 + row) * K + k0 + c * 8;
            uint32_t dst = smem_b + (uint32_t)(((op << 12) + row * 32 + ((c ^ (row & 7)) << 2)) << 2);
            cp16_(dst, gsrc);
        }
        asm volatile("cp.async.commit_group;");
        asm volatile("cp.async.wait_group 0;");
        __syncthreads();

        // ---- compute: 4 k16 sub-steps, ldmatrix fragments ------------------
#pragma unroll
        for (int ks = 0; ks < 4; ks++) {
            uint32_t ah[2][4], al[2][4];
#pragma unroll
            for (int mt = 0; mt < 2; mt++) {
                int row = arow + mt * 16;
                int pc = (2 * ks + aqb) ^ (row & 7);
                uint32_t ad = smem_b + (uint32_t)((row * 32 + pc * 4) << 2);
                LDSM_X4_(ah[mt][0], ah[mt][1], ah[mt][2], ah[mt][3], ad);
                LDSM_X4_(al[mt][0], al[mt][1], al[mt][2], al[mt][3], ad + 16384);
            }
#pragma unroll
            for (int p = 0; p < 4; p++) {
                int n = brow + p * 16;
                int pc = (2 * ks + bqb) ^ (n & 7);
                uint32_t bd = smem_b + (uint32_t)(((8192 + n * 32 + pc * 4)) << 2);
                uint32_t bh0, bh1, bh2, bh3, bl0, bl1, bl2, bl3;
                LDSM_X4_(bh0, bh1, bh2, bh3, bd);
                LDSM_X4_(bl0, bl1, bl2, bl3, bd + 16384);
#pragma unroll
                for (int mt = 0; mt < 2; mt++) {
                    MMA_BF16_(acc[mt][2*p],   ah[mt][0], ah[mt][1], ah[mt][2], ah[mt][3], bh0, bh1);
                    MMA_BF16_(acc[mt][2*p],   ah[mt][0], ah[mt][1], ah[mt][2], ah[mt][3], bl0, bl1);
                    MMA_BF16_(acc[mt][2*p],   al[mt][0], al[mt][1], al[mt][2], al[mt][3], bh0, bh1);
                    MMA_BF16_(acc[mt][2*p+1], ah[mt][0], ah[mt][1], ah[mt][2], ah[mt][3], bh2, bh3);
                    MMA_BF16_(acc[mt][2*p+1], ah[mt][0], ah[mt][1], ah[mt][2], ah[mt][3], bl2, bl3);
                    MMA_BF16_(acc[mt][2*p+1], al[mt][0], al[mt][1], al[mt][2], al[mt][3], bh2, bh3);
                }
            }
        }
    }

    // ---- epilogue -----------------------------------------------------------
#pragma unroll
    for (int mt = 0; mt < 2; mt++) {
        int r0g = row0 + warp_m + mt * 16 + g;
#pragma unroll
        for (int nt = 0; nt < 8; nt++) {
            int c = col0 + warp_n + nt * 8 + 2 * t;
            float2 v0, v1;
            v0.x = acc[mt][nt][0]; v0.y = acc[mt][nt][1];
            v1.x = acc[mt][nt][2]; v1.y = acc[mt][nt][3];
            if (act == 1) {
                float b0 = bias[c], b1 = bias[c + 1];
                v0.x = geluf_(v0.x + b0); v0.y = geluf_(v0.y + b1);
                v1.x = geluf_(v1.x + b0); v1.y = geluf_(v1.y + b1);
            }
            *(float2*)(C + (size_t)r0g * N + c) = v0;
            *(float2*)(C + (size_t)(r0g + 8) * N + c) = v1;
        }
    }
}

// ------------------------- short causal depthwise conv (K=4) + silu ---------
__global__ __launch_bounds__(256) void conv4_silu_kernel(
    const float* __restrict__ x, const float* __restrict__ f, float* __restrict__ y,
    int xstride, int xoff)
{
    int idx = blockIdx.x * 256 + threadIdx.x;      // (bl, c)
    int c  = idx & (H_ - 1);
    int bl = idx >> 10;
    int l  = bl & (L_ - 1);
    const float* xp = x + (size_t)bl * xstride + xoff + c;
    float4 fv = *(const float4*)(f + c * 4);
    float acc = fv.w * xp[0];
    if (l >= 1) acc += fv.z * xp[-xstride];
    if (l >= 2) acc += fv.y * xp[-2 * xstride];
    if (l >= 3) acc += fv.x * xp[-3 * xstride];
    y[idx] = acc * sigmoidf_(acc);
}

// ------------------------- beta = sigmoid(hs @ Wb) --------------------------
__global__ __launch_bounds__(128) void beta_kernel(
    const float* __restrict__ hs, const float* __restrict__ Wb, float* __restrict__ beta)
{
    int bl = blockIdx.x;
    int wrp = threadIdx.x >> 5, lane = threadIdx.x & 31;
    const float* hp = hs + (size_t)bl * H_;
    float acc = 0.f;
    for (int d = lane; d < H_; d += 32) acc += hp[d] * Wb[d * NH_ + wrp];
#pragma unroll
    for (int o = 16; o; o >>= 1) acc += __shfl_xor_sync(0xffffffffu, acc, o);
    if (lane == 0) beta[bl * NH_ + wrp] = sigmoidf_(acc);
}

// ------------------------- l2norm + beta-scale + [B,H,L,D] transpose --------
__global__ __launch_bounds__(256) void normtr_kernel(
    const float* __restrict__ qs, const float* __restrict__ ks, const float* __restrict__ vs,
    const float* __restrict__ beta,
    float* __restrict__ qn, float* __restrict__ kn, float* __restrict__ kb, float* __restrict__ vb)
{
    int bl = blockIdx.x, h = blockIdx.y, d = threadIdx.x;
    int b = bl >> 12;
    int l = bl & (L_ - 1);
    size_t src = (size_t)bl * H_ + h * DK_ + d;
    float qv = qs[src], kv = ks[src], vv = vs[src];
    float s1 = qv * qv, s2 = kv * kv;
#pragma unroll
    for (int o = 16; o; o >>= 1) {
        s1 += __shfl_xor_sync(0xffffffffu, s1, o);
        s2 += __shfl_xor_sync(0xffffffffu, s2, o);
    }
    __shared__ float r1[8], r2[8];
    __shared__ float inv1, inv2;
    int lane = d & 31, wid = d >> 5;
    if (lane == 0) { r1[wid] = s1; r2[wid] = s2; }
    __syncthreads();
    if (d == 0) {
        float t1 = 0.f, t2 = 0.f;
        for (int i = 0; i < 8; i++) { t1 += r1[i]; t2 += r2[i]; }
        inv1 = rsqrtf(t1);
        inv2 = rsqrtf(t2);
    }
    __syncthreads();
    float bt = beta[bl * NH_ + h];
    size_t dst = (((size_t)b * NH_ + h) * L_ + l) * DK_ + d;
    float knv = kv * inv2;
    qn[dst] = qv * inv1;
    kn[dst] = knv;
    kb[dst] = knv * bt;
    vb[dst] = vv * bt;
}

// ------------------------- per-chunk: UT transform, u, w, attn --------------
__global__ __launch_bounds__(256) void chunk_kernel(
    const float* __restrict__ qn, const float* __restrict__ kn,
    const float* __restrict__ kb, const float* __restrict__ vb,
    float* __restrict__ U, float* __restrict__ Wm, float* __restrict__ ATT)
{
    extern __shared__ float sm[];
    float* sk  = sm;            // 32x256
    float* skb = sm + 8192;     // 32x256
    float* sx  = sm + 16384;    // 32x256 (vb then qn)
    float* T   = sm + 24576;    // 32x33
    int bh = blockIdx.x, n = blockIdx.y;
    int tid = threadIdx.x;
    size_t base = ((size_t)bh * L_ + n * C_) * DK_;

    for (int i = tid; i < 2048; i += 256) {
        ((float4*)sk)[i]  = ((const float4*)(kn + base))[i];
        ((float4*)skb)[i] = ((const float4*)(kb + base))[i];
        ((float4*)sx)[i]  = ((const float4*)(vb + base))[i];
    }
    __syncthreads();

    // A = -(kb @ kn^T) * strict_lower
    for (int e = tid; e < 1024; e += 256) {
        int i = e >> 5, j = e & 31;
        float a = 0.f;
        if (j < i) {
            const float* pi = skb + i * 256;
            const float* pj = sk + j * 256;
            for (int d = 0; d < 256; d++) a -= pi[d] * pj[d];
        }
        T[i * 33 + j] = a;
    }
    __syncthreads();

    // forward substitution (warp 0)
    if (tid < 32) {
        int j = tid;
        for (int i = 1; i < 32; i++) {
            float rv = T[i * 33 + j];
            float acc = rv;
            for (int m = 1; m < i; m++)
                acc += __shfl_sync(0xffffffffu, rv, m) * T[m * 33 + j];
            __syncwarp();
            T[i * 33 + j] = acc;
            __syncwarp();
        }
        T[j * 33 + j] = 1.f;
    }
    __syncthreads();

    // u = T @ vb, w = T @ kb
    for (int idx = tid; idx < 8192; idx += 256) {
        int c = idx >> 8, d = idx & 255;
        float au = 0.f, aw = 0.f;
#pragma unroll
        for (int j = 0; j < 32; j++) {
            float t = T[c * 33 + j];
            au += t * sx[j * 256 + d];
            aw += t * skb[j * 256 + d];
        }
        U[base + idx]  = au;
        Wm[base + idx] = aw;
    }
    __syncthreads();

    // attn = (qn @ kn^T) * causal
    for (int i = tid; i < 2048; i += 256)
        ((float4*)sx)[i] = ((const float4*)(qn + base))[i];
    __syncthreads();
    float* att = ATT + ((size_t)bh * NC_ + n) * 1024;
    for (int e = tid; e < 1024; e += 256) {
        int c = e >> 5, j = e & 31;
        float a = 0.f;
        if (j <= c) {
            const float* pq = sx + c * 256;
            const float* pk = sk + j * 256;
            for (int d = 0; d < 256; d++) a += pq[d] * pk[d];
        }
        att[e] = a;
    }
}

// ------------------------- sequential chunk scan (dv tiled by 16) -----------
// R7 layout (verified): S [256][16]; S-read is broadcast + 16-bank spread.
#define SCAN_SMEM (30720 * 4)
__global__ __launch_bounds__(256) void scan_kernel(
    const float* __restrict__ qn, const float* __restrict__ kn,
    const float* __restrict__ U, const float* __restrict__ Wm,
    const float* __restrict__ ATT, float* __restrict__ OUT)
{
    extern __shared__ float sm[];
    float* S   = sm;            // [256][16]
    float* sq  = sm + 4096;     // [32][256]
    float* sk  = sm + 12288;    // [32][256]
    float* sw  = sm + 20480;    // [32][256]
    float* su  = sm + 28672;    // [32][16]
    float* sut = sm + 29184;    // [32][16]
    float* sat = sm + 29696;    // [32][32]
    const int bh = blockIdx.x, tile = blockIdx.y;
    const int tid = threadIdx.x;
    const int b = bh >> 2, h = bh & 3;
    const int g = tid >> 3, eg = tid & 7;

    for (int i = tid; i < 4096; i += 256) S[i] = 0.f;

    for (int n = 0; n < NC_; n++) {
        __syncthreads();
        size_t base = ((size_t)bh * L_ + n * C_) * 256;
        for (int i = tid; i < 2048; i += 256) {
            ((float4*)sq)[i] = ((const float4*)(qn + base))[i];
            ((float4*)sk)[i] = ((const float4*)(kn + base))[i];
            ((float4*)sw)[i] = ((const float4*)(Wm + base))[i];
        }
        if (tid < 128) {
            int c = tid >> 2, e4 = tid & 3;
            ((float4*)su)[tid] = *(const float4*)(U + base + c * 256 + tile * 16 + e4 * 4);
        }
        ((float4*)sat)[tid] = ((const float4*)(ATT + ((size_t)bh * NC_ + n) * 1024))[tid];
        __syncthreads();

        // u_t = u - w@S ; o_partial = q@S   (full dk = 256)
        float2 aw = make_float2(0.f, 0.f);
        float2 aq = make_float2(0.f, 0.f);
        const float* wr = sw + g * 256;
        const float* qr = sq + g * 256;
#pragma unroll 8
        for (int d = 0; d < 256; d++) {
            float2 s2 = *(float2*)(S + d * 16 + eg * 2);
            float wv = wr[d], qv = qr[d];
            aw.x += wv * s2.x; aw.y += wv * s2.y;
            aq.x += qv * s2.x; aq.y += qv * s2.y;
        }
        float2 uv = *(float2*)(su + g * 16 + eg * 2);
        float2 ut = make_float2(uv.x - aw.x, uv.y - aw.y);
        *(float2*)(sut + g * 16 + eg * 2) = ut;
        __syncthreads();

        // o = q@S + attn @ u_t
        const float* ar = sat + g * 32;
#pragma unroll
        for (int j = 0; j < 32; j++) {
            float av = ar[j];
            float2 u2 = *(float2*)(sut + j * 16 + eg * 2);
            aq.x += av * u2.x; aq.y += av * u2.y;
        }
        *(float2*)(OUT + (size_t)(b * L_ + n * C_ + g) * H_ + h * 256 + tile * 16 + eg * 2) = aq;

        // S += k^T @ u_t : thread owns d octet g*8.., e pair eg
        float2 accS[8];
#pragma unroll
        for (int i = 0; i < 8; i++) accS[i] = make_float2(0.f, 0.f);
        for (int c2 = 0; c2 < 32; c2++) {
            float2 u2 = *(float2*)(sut + c2 * 16 + eg * 2);
            const float* kr = sk + c2 * 256 + g * 8;
            float4 k0 = *(const float4*)(kr);
            float4 k1 = *(const float4*)(kr + 4);
            accS[0].x += k0.x * u2.x; accS[0].y += k0.x * u2.y;
            accS[1].x += k0.y * u2.x; accS[1].y += k0.y * u2.y;
            accS[2].x += k0.z * u2.x; accS[2].y += k0.z * u2.y;
            accS[3].x += k0.w * u2.x; accS[3].y += k0.w * u2.y;
            accS[4].x += k1.x * u2.x; accS[4].y += k1.x * u2.y;
            accS[5].x += k1.y * u2.x; accS[5].y += k1.y * u2.y;
            accS[6].x += k1.z * u2.x; accS[6].y += k1.z * u2.y;
            accS[7].x += k1.w * u2.x; accS[7].y += k1.w * u2.y;
        }
#pragma unroll
        for (int i = 0; i < 8; i++) {
            float2 s2 = *(float2*)(S + (g * 8 + i) * 16 + eg * 2);
            s2.x += accS[i].x; s2.y += accS[i].y;
            *(float2*)(S + (g * 8 + i) * 16 + eg * 2) = s2;
        }
    }
}

// ------------------------- FIR K=7 (unrolled) -------------------------------
__global__ __launch_bounds__(256) void fir7_kernel(
    const float* __restrict__ x, const float* __restrict__ f, float* __restrict__ y)
{
    int idx = blockIdx.x * 256 + threadIdx.x;
    int c  = idx & (H_ - 1);
    int bl = idx >> 10;
    int l  = bl & (L_ - 1);
    const float* fp = f + (size_t)c * 7;
    float acc = 0.f;
#pragma unroll
    for (int t = 0; t < 7; t++) {
        int dl = t - 6;
        if (l + dl >= 0) acc += x[idx + dl * H_] * fp[t];
    }
    y[idx] = acc;
}

// ------------------------- FIR K=64: smem tile + register sliding window ----
#define FIR64_SMEM ((127 * 128 + 64 * 129) * 4)
__global__ __launch_bounds__(256) void fir64_smem_kernel(
    const float* __restrict__ x, const float* __restrict__ f, float* __restrict__ y)
{
    extern __shared__ float fsm[];
    float* sx = fsm;                 // 127 x 128
    float* sf = fsm + 127 * 128;     // 64 x 129
    const int ctile = blockIdx.x & 7;
    const int ltile = blockIdx.x >> 3;
    const int l0 = ltile * 64;
    const int lb = l0 & (L_ - 1);
    const int c0 = ctile * 128;
    const int tid = threadIdx.x;

    for (int i = tid; i < 64 * 128; i += 256) {
        int c = i >> 6, t = i & 63;
        sf[t * 129 + c] = f[(size_t)(c0 + c) * 64 + t];
    }
    for (int i = tid; i < 127 * 128; i += 256) {
        int j = i >> 7, c = i & 127;
        int lrel = lb + j - 63;
        float v = 0.f;
        if (lrel >= 0)
            v = x[(size_t)(l0 + j - 63) * H_ + c0 + c];
        sx[j * 128 + c] = v;
    }
    __syncthreads();

    const int c = tid & 127;
    const int lg = (tid >> 7) * 32;
    float acc[32], win[32];
#pragma unroll
    for (int i = 0; i < 32; i++) acc[i] = 0.f;
#pragma unroll
    for (int i = 0; i < 32; i++) win[i] = sx[(lg + i) * 128 + c];
#pragma unroll
    for (int t = 0; t < 64; t++) {
        float ft = sf[t * 129 + c];
#pragma unroll
        for (int i = 0; i < 32; i++) acc[i] += ft * win[i];
        if (t < 63) {
#pragma unroll
            for (int i = 0; i < 31; i++) win[i] = win[i + 1];
            win[31] = sx[(lg + t + 32) * 128 + c];
        }
    }
#pragma unroll
    for (int i = 0; i < 32; i++)
        y[(size_t)(l0 + lg + i) * H_ + c0 + c] = acc[i];
}

// ------------------------- fusion gate: h1 @ Wf2 + bf2 -> softmax4 ----------
__global__ __launch_bounds__(128) void gate_kernel(
    const float* __restrict__ h1, const float* __restrict__ Wf2,
    const float* __restrict__ bf2, float* __restrict__ fw)
{
    int bl = blockIdx.x, tid = threadIdx.x;
    float acc[16];
#pragma unroll
    for (int j = 0; j < 16; j++) acc[j] = 0.f;
    const float* hp = h1 + (size_t)bl * F1_;
    for (int d = tid; d < F1_; d += 128) {
        float hv = hp[d];
        const float4* w4 = (const float4*)(Wf2 + d * 16);
        float4 w0 = w4[0], w1 = w4[1], w2 = w4[2], w3 = w4[3];
        acc[0] += hv * w0.x; acc[1] += hv * w0.y; acc[2] += hv * w0.z; acc[3] += hv * w0.w;
        acc[4] += hv * w1.x; acc[5] += hv * w1.y; acc[6] += hv * w1.z; acc[7] += hv * w1.w;
        acc[8] += hv * w2.x; acc[9] += hv * w2.y; acc[10] += hv * w2.z; acc[11] += hv * w2.w;
        acc[12] += hv * w3.x; acc[13] += hv * w3.y; acc[14] += hv * w3.z; acc[15] += hv * w3.w;
    }
    __shared__ float red[16][129];
    __shared__ float logit[16];
#pragma unroll
    for (int j = 0; j < 16; j++) red[j][tid] = acc[j];
    __syncthreads();
    if (tid < 16) {
        float s = bf2[tid];
        for (int i = 0; i < 128; i++) s += red[tid][i];
        logit[tid] = s;
    }
    __syncthreads();
    if (tid < 4) {
        float l0 = logit[tid * 4], l1 = logit[tid * 4 + 1];
        float l2 = logit[tid * 4 + 2], l3 = logit[tid * 4 + 3];
        float m = fmaxf(fmaxf(l0, l1), fmaxf(l2, l3));
        float e0 = expf(l0 - m), e1 = expf(l1 - m), e2 = expf(l2 - m), e3 = expf(l3 - m);
        float inv = 1.f / (e0 + e1 + e2 + e3);
        float* o = fw + (size_t)bl * 16 + tid * 4;
        o[0] = e0 * inv; o[1] = e1 * inv; o[2] = e2 * inv; o[3] = e3 * inv;
    }
}

// ------------------------- branch mix + per-head rmsnorm -> bf16 hi/lo ------
__global__ __launch_bounds__(256) void mix_rms_kernel(
    const float* __restrict__ br_s, const float* __restrict__ br_l,
    const float* __restrict__ br_d, const float* __restrict__ br_v,
    const float* __restrict__ fw, const float* __restrict__ rmsw,
    __nv_bfloat16* __restrict__ Mhi, __nv_bfloat16* __restrict__ Mlo)
{
    int bl = blockIdx.x, h = blockIdx.y, d = threadIdx.x;
    size_t i = (size_t)bl * H_ + h * 256 + d;
    const float* f = fw + (size_t)bl * 16 + h * 4;
    float val = f[0] * br_s[i] + f[1] * br_l[i] + f[2] * br_d[i] + f[3] * br_v[i];
    float ss = val * val;
#pragma unroll
    for (int o = 16; o; o >>= 1) ss += __shfl_xor_sync(0xffffffffu, ss, o);
    __shared__ float red[8];
    __shared__ float scale;
    if ((d & 31) == 0) red[d >> 5] = ss;
    __syncthreads();
    if (d == 0) {
        float t = 0.f;
        for (int k = 0; k < 8; k++) t += red[k];
        scale = rsqrtf(t * (1.f / 256.f) + 1e-5f);
    }
    __syncthreads();
    float o = val * scale * rmsw[d];
    __nv_bfloat16 hb = __float2bfloat16(o);
    Mhi[i] = hb;
    Mlo[i] = __float2bfloat16(o - __bfloat162float(hb));
}

// ------------------------- launcher ----------------------------------------
extern "C" void kernel_launch(void* const* d_in, const int* in_sizes, int n_in,
                              void* d_out, int out_size)
{
    const float* hs   = (const float*)d_in[0];
    const float* Wq   = (const float*)d_in[1];
    const float* Wk   = (const float*)d_in[2];
    const float* Wv   = (const float*)d_in[3];
    const float* Wb   = (const float*)d_in[4];
    const float* cq   = (const float*)d_in[5];
    const float* ck   = (const float*)d_in[6];
    const float* cv   = (const float*)d_in[7];
    const float* fsw  = (const float*)d_in[8];
    const float* flw  = (const float*)d_in[9];
    const float* Wf1  = (const float*)d_in[10];
    const float* bf1  = (const float*)d_in[11];
    const float* Wf2  = (const float*)d_in[12];
    const float* bf2  = (const float*)d_in[13];
    const float* rmsw = (const float*)d_in[14];
    const float* Wo   = (const float*)d_in[15];
    float* out = (float*)d_out;

    float *qkvp, *qs, *ks, *vs, *qn, *kn, *kb, *vb;
    float *u, *w, *delta, *shrt, *lng, *h1, *att, *beta, *fw;
    __nv_bfloat16 *ahi, *alo, *mhi, *mlo, *wqh, *wql, *wf1h, *wf1l, *woh, *wol;
    cudaGetSymbolAddress((void**)&qkvp, g_qkvp);
    cudaGetSymbolAddress((void**)&qs, g_qs);
    cudaGetSymbolAddress((void**)&ks, g_ks);
    cudaGetSymbolAddress((void**)&vs, g_vs);
    cudaGetSymbolAddress((void**)&qn, g_qn);
    cudaGetSymbolAddress((void**)&kn, g_kn);
    cudaGetSymbolAddress((void**)&kb, g_kb);
    cudaGetSymbolAddress((void**)&vb, g_vb);
    cudaGetSymbolAddress((void**)&u, g_u);
    cudaGetSymbolAddress((void**)&w, g_w);
    cudaGetSymbolAddress((void**)&delta, g_delta);
    cudaGetSymbolAddress((void**)&shrt, g_shrt);
    cudaGetSymbolAddress((void**)&lng, g_long);
    cudaGetSymbolAddress((void**)&h1, g_h1);
    cudaGetSymbolAddress((void**)&att, g_att);
    cudaGetSymbolAddress((void**)&beta, g_beta);
    cudaGetSymbolAddress((void**)&fw, g_fw);
    cudaGetSymbolAddress((void**)&ahi, g_ahi);
    cudaGetSymbolAddress((void**)&alo, g_alo);
    cudaGetSymbolAddress((void**)&mhi, g_mhi);
    cudaGetSymbolAddress((void**)&mlo, g_mlo);
    cudaGetSymbolAddress((void**)&wqh, g_wqkv_hi);
    cudaGetSymbolAddress((void**)&wql, g_wqkv_lo);
    cudaGetSymbolAddress((void**)&wf1h, g_wf1_hi);
    cudaGetSymbolAddress((void**)&wf1l, g_wf1_lo);
    cudaGetSymbolAddress((void**)&woh, g_wo_hi);
    cudaGetSymbolAddress((void**)&wol, g_wo_lo);

    cudaFuncSetAttribute(mma_gemm2_kernel, cudaFuncAttributeMaxDynamicSharedMemorySize, MG_SMEM);
    cudaFuncSetAttribute(chunk_kernel, cudaFuncAttributeMaxDynamicSharedMemorySize, 102528);
    cudaFuncSetAttribute(scan_kernel,  cudaFuncAttributeMaxDynamicSharedMemorySize, SCAN_SMEM);
    cudaFuncSetAttribute(fir64_smem_kernel, cudaFuncAttributeMaxDynamicSharedMemorySize, FIR64_SMEM);

    // ---- prep: bf16 hi/lo conversions (A once, weights once, transposed) ---
    cvt_a_kernel<<<BL_ * H_ / 1024, 256>>>(hs, ahi, alo);
    cvt_wt_kernel<<<dim3(32, 32), 256>>>(Wq, wqh,             wql,             H_, H_);
    cvt_wt_kernel<<<dim3(32, 32), 256>>>(Wk, wqh + 1024 * H_, wql + 1024 * H_, H_, H_);
    cvt_wt_kernel<<<dim3(32, 32), 256>>>(Wv, wqh + 2048 * H_, wql + 2048 * H_, H_, H_);
    cvt_wt_kernel<<<dim3(64, 32), 256>>>(Wf1, wf1h, wf1l, H_, F1_);
    cvt_wt_kernel<<<dim3(32, 32), 256>>>(Wo, woh, wol, H_, H_);

    // ---- fused qkv projection + gate-MLP first layer -----------------------
    mma_gemm2_kernel<<<dim3(NQKV / 128, BL_ / 128), 256, MG_SMEM>>>(
        ahi, alo, wqh, wql, nullptr, qkvp, NQKV, H_, 0);
    mma_gemm2_kernel<<<dim3(F1_ / 128, BL_ / 128), 256, MG_SMEM>>>(
        ahi, alo, wf1h, wf1l, bf1, h1, F1_, H_, 1);

    // short conv + silu (reads packed qkv)
    conv4_silu_kernel<<<BL_ * H_ / 256, 256>>>(qkvp, cq, qs, NQKV, 0);
    conv4_silu_kernel<<<BL_ * H_ / 256, 256>>>(qkvp, ck, ks, NQKV, 1024);
    conv4_silu_kernel<<<BL_ * H_ / 256, 256>>>(qkvp, cv, vs, NQKV, 2048);

    // beta, l2norm + transpose
    beta_kernel<<<BL_, 128>>>(hs, Wb, beta);
    normtr_kernel<<<dim3(BL_, NH_), 256>>>(qs, ks, vs, beta, qn, kn, kb, vb);

    // delta rule
    chunk_kernel<<<dim3(BH_, NC_), 256, 102528>>>(qn, kn, kb, vb, u, w, att);
    scan_kernel<<<dim3(BH_, 16), 256, SCAN_SMEM>>>(qn, kn, u, w, att, delta);

    // FIR branches
    fir7_kernel<<<BL_ * H_ / 256, 256>>>(vs, fsw, shrt);
    fir64_smem_kernel<<<1024, 256, FIR64_SMEM>>>(vs, flw, lng);

    // gate, mix+rmsnorm (emits bf16 hi/lo), output projection
    gate_kernel<<<BL_, 128>>>(h1, Wf2, bf2, fw);
    mix_rms_kernel<<<dim3(BL_, NH_), 256>>>(shrt, lng, delta, vs, fw, rmsw, mhi, mlo);
    mma_gemm2_kernel<<<dim3(H_ / 128, BL_ / 128), 256, MG_SMEM>>>(
        mhi, mlo, woh, wol, nullptr, out, H_, H_, 0);
}

// round 12
// speedup vs baseline: 1.3162x; 1.1032x over previous
#include <cuda_runtime.h>
#include <cuda_bf16.h>
#include <math.h>
#include <stdint.h>

#define B_   2
#define L_   4096
#define H_   1024
#define NH_  4
#define DK_  256
#define DV_  256
#define C_   32
#define NC_  128
#define BL_  8192
#define BH_  8
#define F1_  2048
#define NQKV 3072

// ------------------------- scratch (static device memory; no allocs) -------
__device__ float g_qkvp[BL_*NQKV];
__device__ float g_qs[BL_*H_], g_ks[BL_*H_], g_vs[BL_*H_];
__device__ float g_qn[BL_*H_], g_kn[BL_*H_], g_kb[BL_*H_], g_vb[BL_*H_];
__device__ float g_u [BL_*H_], g_w [BL_*H_];
__device__ float g_delta[BL_*H_], g_shrt[BL_*H_], g_long[BL_*H_];
__device__ float g_h1[BL_*F1_];
__device__ float g_att[BH_*NC_*C_*C_];
__device__ float g_beta[BL_*NH_];
__device__ float g_fw[BL_*16];
// bf16 hi/lo staging
__device__ __nv_bfloat16 g_ahi[BL_*H_],  g_alo[BL_*H_];
__device__ __nv_bfloat16 g_mhi[BL_*H_],  g_mlo[BL_*H_];
__device__ __nv_bfloat16 g_wqkv_hi[NQKV*H_], g_wqkv_lo[NQKV*H_];
__device__ __nv_bfloat16 g_wf1_hi[F1_*H_],   g_wf1_lo[F1_*H_];
__device__ __nv_bfloat16 g_wo_hi[H_*H_],     g_wo_lo[H_*H_];

__device__ __forceinline__ float sigmoidf_(float x) { return 1.f / (1.f + expf(-x)); }
__device__ __forceinline__ float geluf_(float x) {
    return 0.5f * x * (1.f + erff(x * 0.70710678118654752440f));
}
__device__ __forceinline__ uint32_t smem_u32_(const void* p) {
    uint32_t a;
    asm("{ .reg .u64 t; cvta.to.shared.u64 t, %1; cvt.u32.u64 %0, t; }" : "=r"(a) : "l"(p));
    return a;
}
__device__ __forceinline__ uint32_t pack_bf16_hi_(float x, float y) {
    __nv_bfloat162 h = __halves2bfloat162(__float2bfloat16(x), __float2bfloat16(y));
    return *reinterpret_cast<uint32_t*>(&h);
}
__device__ __forceinline__ uint32_t pack_bf16_lo_(float x, float y) {
    float hx = __bfloat162float(__float2bfloat16(x));
    float hy = __bfloat162float(__float2bfloat16(y));
    __nv_bfloat162 l = __halves2bfloat162(__float2bfloat16(x - hx), __float2bfloat16(y - hy));
    return *reinterpret_cast<uint32_t*>(&l);
}
__device__ __forceinline__ void cp16_(uint32_t dst, const void* src) {
    asm volatile("cp.async.ca.shared.global [%0], [%1], 16;" :: "r"(dst), "l"(src));
}

// ------------------------- prep: fp32 -> bf16 hi/lo ------------------------
__global__ __launch_bounds__(256) void cvt_a_kernel(
    const float* __restrict__ x, __nv_bfloat16* __restrict__ hi, __nv_bfloat16* __restrict__ lo)
{
    int i = (blockIdx.x * 256 + threadIdx.x) * 4;
    float4 v = *(const float4*)(x + i);
    uint2 oh, ol;
    oh.x = pack_bf16_hi_(v.x, v.y); oh.y = pack_bf16_hi_(v.z, v.w);
    ol.x = pack_bf16_lo_(v.x, v.y); ol.y = pack_bf16_lo_(v.z, v.w);
    *(uint2*)(hi + i) = oh;
    *(uint2*)(lo + i) = ol;
}

// W [K][N] -> Wt hi/lo [N][K]  (32x32 smem transpose)
__global__ __launch_bounds__(256) void cvt_wt_kernel(
    const float* __restrict__ W, __nv_bfloat16* __restrict__ hi, __nv_bfloat16* __restrict__ lo,
    int K, int N)
{
    __shared__ float tile[32][33];
    int n0 = blockIdx.x * 32, k0 = blockIdx.y * 32;
    int tx = threadIdx.x & 31, ty = threadIdx.x >> 5;   // 32 x 8
#pragma unroll
    for (int i = 0; i < 4; i++)
        tile[ty + 8 * i][tx] = W[(size_t)(k0 + ty + 8 * i) * N + n0 + tx];
    __syncthreads();
#pragma unroll
    for (int i = 0; i < 4; i++) {
        float v = tile[tx][ty + 8 * i];
        __nv_bfloat16 h = __float2bfloat16(v);
        size_t o = (size_t)(n0 + ty + 8 * i) * K + k0 + tx;
        hi[o] = h;
        lo[o] = __float2bfloat16(v - __bfloat162float(h));
    }
}

// ===================== warp-mma bf16 split-x3 GEMM (ldmatrix) ===============
#define MMA_BF16_(c, a0, a1, a2, a3, b0, b1) \
    asm volatile("mma.sync.aligned.m16n8k16.row.col.f32.bf16.bf16.f32 " \
        "{%0,%1,%2,%3}, {%4,%5,%6,%7}, {%8,%9}, {%0,%1,%2,%3};" \
        : "+f"((c)[0]), "+f"((c)[1]), "+f"((c)[2]), "+f"((c)[3]) \
        : "r"(a0), "r"(a1), "r"(a2), "r"(a3), "r"(b0), "r"(b1))

#define LDSM_X4_(r0, r1, r2, r3, addr) \
    asm volatile("ldmatrix.sync.aligned.m8n8.x4.shared.b16 {%0,%1,%2,%3}, [%4];" \
        : "=r"(r0), "=r"(r1), "=r"(r2), "=r"(r3) : "r"(addr))

#define MG_SMEM 65536

__global__ __launch_bounds__(256, 2) void mma_gemm2_kernel(
    const __nv_bfloat16* __restrict__ Ahi_g, const __nv_bfloat16* __restrict__ Alo_g,
    const __nv_bfloat16* __restrict__ Bhi_g, const __nv_bfloat16* __restrict__ Blo_g,
    const float* __restrict__ bias, float* __restrict__ C,
    int N, int K, int act)
{
    extern __shared__ __align__(16) uint32_t smem_u[];
    const uint32_t smem_b = smem_u32_(smem_u);
    const int tid = threadIdx.x;
    const int wid = tid >> 5, lane = tid & 31;
    const int g = lane >> 2, t = lane & 3;
    const int warp_m = (wid & 3) * 32;
    const int warp_n = (wid >> 2) * 64;
    const int row0 = blockIdx.y * 128, col0 = blockIdx.x * 128;

    const int qq = lane >> 3, rr = lane & 7;
    const int arow = warp_m + ((qq & 1) << 3) + rr;
    const int aqb  = (qq >> 1) & 1;
    const int brow = warp_n + ((qq >> 1) << 3) + rr;
    const int bqb  = qq & 1;

    float acc[2][8][4];
#pragma unroll
    for (int mt = 0; mt < 2; mt++)
#pragma unroll
        for (int nt = 0; nt < 8; nt++)
#pragma unroll
            for (int e = 0; e < 4; e++) acc[mt][nt][e] = 0.f;

    for (int k0 = 0; k0 < K; k0 += 64) {
        __syncthreads();
#pragma unroll
        for (int i = 0; i < 16; i++) {
            const int op = i >> 2;
            int rem = (i & 3) * 256 + tid;
            int row = rem >> 3, c = rem & 7;
            const __nv_bfloat16* gsrc =
                (op == 0) ? Ahi_g + (size_t)(row0 + row) * K + k0 + c * 8 :
                (op == 1) ? Alo_g + (size_t)(row0 + row) * K + k0 + c * 8 :
                (op == 2) ? Bhi_g + (size_t)(col0 + row) * K + k0 + c * 8 :
                            Blo_g + (size_t)(col0 + row) * K + k0 + c * 8;
            uint32_t dst = smem_b + (uint32_t)(((op << 12) + row * 32 + ((c ^ (row & 7)) << 2)) << 2);
            cp16_(dst, gsrc);
        }
        asm volatile("cp.async.commit_group;");
        asm volatile("cp.async.wait_group 0;");
        __syncthreads();

#pragma unroll
        for (int ks = 0; ks < 4; ks++) {
            uint32_t ah[2][4], al[2][4];
#pragma unroll
            for (int mt = 0; mt < 2; mt++) {
                int row = arow + mt * 16;
                int pc = (2 * ks + aqb) ^ (row & 7);
                uint32_t ad = smem_b + (uint32_t)((row * 32 + pc * 4) << 2);
                LDSM_X4_(ah[mt][0], ah[mt][1], ah[mt][2], ah[mt][3], ad);
                LDSM_X4_(al[mt][0], al[mt][1], al[mt][2], al[mt][3], ad + 16384);
            }
#pragma unroll
            for (int p = 0; p < 4; p++) {
                int n = brow + p * 16;
                int pc = (2 * ks + bqb) ^ (n & 7);
                uint32_t bd = smem_b + (uint32_t)(((8192 + n * 32 + pc * 4)) << 2);
                uint32_t bh0, bh1, bh2, bh3, bl0, bl1, bl2, bl3;
                LDSM_X4_(bh0, bh1, bh2, bh3, bd);
                LDSM_X4_(bl0, bl1, bl2, bl3, bd + 16384);
#pragma unroll
                for (int mt = 0; mt < 2; mt++) {
                    MMA_BF16_(acc[mt][2*p],   ah[mt][0], ah[mt][1], ah[mt][2], ah[mt][3], bh0, bh1);
                    MMA_BF16_(acc[mt][2*p],   ah[mt][0], ah[mt][1], ah[mt][2], ah[mt][3], bl0, bl1);
                    MMA_BF16_(acc[mt][2*p],   al[mt][0], al[mt][1], al[mt][2], al[mt][3], bh0, bh1);
                    MMA_BF16_(acc[mt][2*p+1], ah[mt][0], ah[mt][1], ah[mt][2], ah[mt][3], bh2, bh3);
                    MMA_BF16_(acc[mt][2*p+1], ah[mt][0], ah[mt][1], ah[mt][2], ah[mt][3], bl2, bl3);
                    MMA_BF16_(acc[mt][2*p+1], al[mt][0], al[mt][1], al[mt][2], al[mt][3], bh2, bh3);
                }
            }
        }
    }

#pragma unroll
    for (int mt = 0; mt < 2; mt++) {
        int r0g = row0 + warp_m + mt * 16 + g;
#pragma unroll
        for (int nt = 0; nt < 8; nt++) {
            int c = col0 + warp_n + nt * 8 + 2 * t;
            float2 v0, v1;
            v0.x = acc[mt][nt][0]; v0.y = acc[mt][nt][1];
            v1.x = acc[mt][nt][2]; v1.y = acc[mt][nt][3];
            if (act == 1) {
                float b0 = bias[c], b1 = bias[c + 1];
                v0.x = geluf_(v0.x + b0); v0.y = geluf_(v0.y + b1);
                v1.x = geluf_(v1.x + b0); v1.y = geluf_(v1.y + b1);
            }
            *(float2*)(C + (size_t)r0g * N + c) = v0;
            *(float2*)(C + (size_t)(r0g + 8) * N + c) = v1;
        }
    }
}

// ------------------------- short causal depthwise conv (K=4) + silu ---------
__global__ __launch_bounds__(256) void conv4_silu_kernel(
    const float* __restrict__ x, const float* __restrict__ f, float* __restrict__ y,
    int xstride, int xoff)
{
    int idx = blockIdx.x * 256 + threadIdx.x;      // (bl, c)
    int c  = idx & (H_ - 1);
    int bl = idx >> 10;
    int l  = bl & (L_ - 1);
    const float* xp = x + (size_t)bl * xstride + xoff + c;
    float4 fv = *(const float4*)(f + c * 4);
    float acc = fv.w * xp[0];
    if (l >= 1) acc += fv.z * xp[-xstride];
    if (l >= 2) acc += fv.y * xp[-2 * xstride];
    if (l >= 3) acc += fv.x * xp[-3 * xstride];
    y[idx] = acc * sigmoidf_(acc);
}

// ------------------------- beta = sigmoid(hs @ Wb) --------------------------
__global__ __launch_bounds__(128) void beta_kernel(
    const float* __restrict__ hs, const float* __restrict__ Wb, float* __restrict__ beta)
{
    int bl = blockIdx.x;
    int wrp = threadIdx.x >> 5, lane = threadIdx.x & 31;
    const float* hp = hs + (size_t)bl * H_;
    float acc = 0.f;
    for (int d = lane; d < H_; d += 32) acc += hp[d] * Wb[d * NH_ + wrp];
#pragma unroll
    for (int o = 16; o; o >>= 1) acc += __shfl_xor_sync(0xffffffffu, acc, o);
    if (lane == 0) beta[bl * NH_ + wrp] = sigmoidf_(acc);
}

// ------------------------- l2norm + beta-scale + [B,H,L,D] transpose --------
__global__ __launch_bounds__(256) void normtr_kernel(
    const float* __restrict__ qs, const float* __restrict__ ks, const float* __restrict__ vs,
    const float* __restrict__ beta,
    float* __restrict__ qn, float* __restrict__ kn, float* __restrict__ kb, float* __restrict__ vb)
{
    int bl = blockIdx.x, h = blockIdx.y, d = threadIdx.x;
    int b = bl >> 12;
    int l = bl & (L_ - 1);
    size_t src = (size_t)bl * H_ + h * DK_ + d;
    float qv = qs[src], kv = ks[src], vv = vs[src];
    float s1 = qv * qv, s2 = kv * kv;
#pragma unroll
    for (int o = 16; o; o >>= 1) {
        s1 += __shfl_xor_sync(0xffffffffu, s1, o);
        s2 += __shfl_xor_sync(0xffffffffu, s2, o);
    }
    __shared__ float r1[8], r2[8];
    __shared__ float inv1, inv2;
    int lane = d & 31, wid = d >> 5;
    if (lane == 0) { r1[wid] = s1; r2[wid] = s2; }
    __syncthreads();
    if (d == 0) {
        float t1 = 0.f, t2 = 0.f;
        for (int i = 0; i < 8; i++) { t1 += r1[i]; t2 += r2[i]; }
        inv1 = rsqrtf(t1);
        inv2 = rsqrtf(t2);
    }
    __syncthreads();
    float bt = beta[bl * NH_ + h];
    size_t dst = (((size_t)b * NH_ + h) * L_ + l) * DK_ + d;
    float knv = kv * inv2;
    qn[dst] = qv * inv1;
    kn[dst] = knv;
    kb[dst] = knv * bt;
    vb[dst] = vv * bt;
}

// ------------------------- per-chunk: UT transform, u, w, attn --------------
// smem rows padded to stride 257 (257 % 32 == 1) -> lane-indexed row reads
// (pj = row j, same d) hit 32 distinct banks instead of one.
#define CK_STRIDE 257
#define CK_SMEM ((96 * CK_STRIDE + 32 * 33) * 4)
__global__ __launch_bounds__(256) void chunk_kernel(
    const float* __restrict__ qn, const float* __restrict__ kn,
    const float* __restrict__ kb, const float* __restrict__ vb,
    float* __restrict__ U, float* __restrict__ Wm, float* __restrict__ ATT)
{
    extern __shared__ float sm[];
    float* sk  = sm;                       // 32 x 257
    float* skb = sm + 32 * CK_STRIDE;      // 32 x 257
    float* sx  = sm + 64 * CK_STRIDE;      // 32 x 257 (vb then qn)
    float* T   = sm + 96 * CK_STRIDE;      // 32 x 33
    int bh = blockIdx.x, n = blockIdx.y;
    int tid = threadIdx.x;
    size_t base = ((size_t)bh * L_ + n * C_) * DK_;

    for (int i = tid; i < 2048; i += 256) {
        int r = i >> 6, c4 = (i & 63) << 2;
        float4 a = ((const float4*)(kn + base))[i];
        float4 b = ((const float4*)(kb + base))[i];
        float4 v = ((const float4*)(vb + base))[i];
        float* pk = sk + r * CK_STRIDE + c4;
        float* pb = skb + r * CK_STRIDE + c4;
        float* pv = sx + r * CK_STRIDE + c4;
        pk[0] = a.x; pk[1] = a.y; pk[2] = a.z; pk[3] = a.w;
        pb[0] = b.x; pb[1] = b.y; pb[2] = b.z; pb[3] = b.w;
        pv[0] = v.x; pv[1] = v.y; pv[2] = v.z; pv[3] = v.w;
    }
    __syncthreads();

    // A = -(kb @ kn^T) * strict_lower
    for (int e = tid; e < 1024; e += 256) {
        int i = e >> 5, j = e & 31;
        float a = 0.f;
        if (j < i) {
            const float* pi = skb + i * CK_STRIDE;
            const float* pj = sk + j * CK_STRIDE;
            for (int d = 0; d < 256; d++) a -= pi[d] * pj[d];
        }
        T[i * 33 + j] = a;
    }
    __syncthreads();

    // forward substitution (warp 0)
    if (tid < 32) {
        int j = tid;
        for (int i = 1; i < 32; i++) {
            float rv = T[i * 33 + j];
            float acc = rv;
            for (int m = 1; m < i; m++)
                acc += __shfl_sync(0xffffffffu, rv, m) * T[m * 33 + j];
            __syncwarp();
            T[i * 33 + j] = acc;
            __syncwarp();
        }
        T[j * 33 + j] = 1.f;
    }
    __syncthreads();

    // u = T @ vb, w = T @ kb
    for (int idx = tid; idx < 8192; idx += 256) {
        int c = idx >> 8, d = idx & 255;
        float au = 0.f, aw = 0.f;
#pragma unroll
        for (int j = 0; j < 32; j++) {
            float t = T[c * 33 + j];
            au += t * sx[j * CK_STRIDE + d];
            aw += t * skb[j * CK_STRIDE + d];
        }
        U[base + idx]  = au;
        Wm[base + idx] = aw;
    }
    __syncthreads();

    // attn = (qn @ kn^T) * causal
    for (int i = tid; i < 2048; i += 256) {
        int r = i >> 6, c4 = (i & 63) << 2;
        float4 q = ((const float4*)(qn + base))[i];
        float* pv = sx + r * CK_STRIDE + c4;
        pv[0] = q.x; pv[1] = q.y; pv[2] = q.z; pv[3] = q.w;
    }
    __syncthreads();
    float* att = ATT + ((size_t)bh * NC_ + n) * 1024;
    for (int e = tid; e < 1024; e += 256) {
        int c = e >> 5, j = e & 31;
        float a = 0.f;
        if (j <= c) {
            const float* pq = sx + c * CK_STRIDE;
            const float* pk = sk + j * CK_STRIDE;
            for (int d = 0; d < 256; d++) a += pq[d] * pk[d];
        }
        att[e] = a;
    }
}

// ------------------------- sequential chunk scan (dv tiled by 16) -----------
// S [256][16] (verified broadcast layout); sq/sk/sw padded to stride 260 so
// per-g row reads hit distinct banks; sat padded to 36; w/q loads float4.
#define SC_STRIDE 260
#define SCAN_SMEM (31232 * 4)
__global__ __launch_bounds__(256) void scan_kernel(
    const float* __restrict__ qn, const float* __restrict__ kn,
    const float* __restrict__ U, const float* __restrict__ Wm,
    const float* __restrict__ ATT, float* __restrict__ OUT)
{
    extern __shared__ float sm[];
    float* S   = sm;             // [256][16]
    float* sq  = sm + 4096;      // [32][260]
    float* sk  = sm + 12416;     // [32][260]
    float* sw  = sm + 20736;     // [32][260]
    float* su  = sm + 29056;     // [32][16]
    float* sut = sm + 29568;     // [32][16]
    float* sat = sm + 30080;     // [32][36]
    const int bh = blockIdx.x, tile = blockIdx.y;
    const int tid = threadIdx.x;
    const int b = bh >> 2, h = bh & 3;
    const int g = tid >> 3, eg = tid & 7;
    const int eg2 = eg * 2;

    for (int i = tid; i < 4096; i += 256) S[i] = 0.f;

    for (int n = 0; n < NC_; n++) {
        __syncthreads();
        size_t base = ((size_t)bh * L_ + n * C_) * 256;
        for (int i = tid; i < 2048; i += 256) {
            int c = i >> 6, o = (i & 63) * 4;
            *(float4*)(sq + c * SC_STRIDE + o) = ((const float4*)(qn + base))[i];
            *(float4*)(sk + c * SC_STRIDE + o) = ((const float4*)(kn + base))[i];
            *(float4*)(sw + c * SC_STRIDE + o) = ((const float4*)(Wm + base))[i];
        }
        if (tid < 128) {
            int c = tid >> 2, e4 = tid & 3;
            ((float4*)su)[tid] = *(const float4*)(U + base + c * 256 + tile * 16 + e4 * 4);
        }
        {
            int c = tid >> 3, j4 = (tid & 7) * 4;
            *(float4*)(sat + c * 36 + j4) =
                ((const float4*)(ATT + ((size_t)bh * NC_ + n) * 1024))[tid];
        }
        __syncthreads();

        // u_t = u - w@S ; o_partial = q@S   (full dk = 256)
        float2 aw = make_float2(0.f, 0.f);
        float2 aq = make_float2(0.f, 0.f);
        const float* wr = sw + g * SC_STRIDE;
        const float* qr = sq + g * SC_STRIDE;
#pragma unroll 4
        for (int d = 0; d < 256; d += 4) {
            float4 w4 = *(const float4*)(wr + d);
            float4 q4 = *(const float4*)(qr + d);
            float2 s0 = *(float2*)(S + (d + 0) * 16 + eg2);
            float2 s1 = *(float2*)(S + (d + 1) * 16 + eg2);
            float2 s2 = *(float2*)(S + (d + 2) * 16 + eg2);
            float2 s3 = *(float2*)(S + (d + 3) * 16 + eg2);
            aw.x += w4.x * s0.x + w4.y * s1.x + w4.z * s2.x + w4.w * s3.x;
            aw.y += w4.x * s0.y + w4.y * s1.y + w4.z * s2.y + w4.w * s3.y;
            aq.x += q4.x * s0.x + q4.y * s1.x + q4.z * s2.x + q4.w * s3.x;
            aq.y += q4.x * s0.y + q4.y * s1.y + q4.z * s2.y + q4.w * s3.y;
        }
        float2 uv = *(float2*)(su + g * 16 + eg2);
        float2 ut = make_float2(uv.x - aw.x, uv.y - aw.y);
        *(float2*)(sut + g * 16 + eg2) = ut;
        __syncthreads();

        // o = q@S + attn @ u_t
        const float* ar = sat + g * 36;
#pragma unroll
        for (int j = 0; j < 32; j += 4) {
            float4 a4 = *(const float4*)(ar + j);
            float2 u0 = *(float2*)(sut + (j + 0) * 16 + eg2);
            float2 u1 = *(float2*)(sut + (j + 1) * 16 + eg2);
            float2 u2 = *(float2*)(sut + (j + 2) * 16 + eg2);
            float2 u3 = *(float2*)(sut + (j + 3) * 16 + eg2);
            aq.x += a4.x * u0.x + a4.y * u1.x + a4.z * u2.x + a4.w * u3.x;
            aq.y += a4.x * u0.y + a4.y * u1.y + a4.z * u2.y + a4.w * u3.y;
        }
        *(float2*)(OUT + (size_t)(b * L_ + n * C_ + g) * H_ + h * 256 + tile * 16 + eg2) = aq;

        // S += k^T @ u_t : thread owns d octet g*8.., e pair eg
        float2 accS[8];
#pragma unroll
        for (int i = 0; i < 8; i++) accS[i] = make_float2(0.f, 0.f);
        for (int c2 = 0; c2 < 32; c2++) {
            float2 u2 = *(float2*)(sut + c2 * 16 + eg2);
            const float* kr = sk + c2 * SC_STRIDE + g * 8;
            float4 k0 = *(const float4*)(kr);
            float4 k1 = *(const float4*)(kr + 4);
            accS[0].x += k0.x * u2.x; accS[0].y += k0.x * u2.y;
            accS[1].x += k0.y * u2.x; accS[1].y += k0.y * u2.y;
            accS[2].x += k0.z * u2.x; accS[2].y += k0.z * u2.y;
            accS[3].x += k0.w * u2.x; accS[3].y += k0.w * u2.y;
            accS[4].x += k1.x * u2.x; accS[4].y += k1.x * u2.y;
            accS[5].x += k1.y * u2.x; accS[5].y += k1.y * u2.y;
            accS[6].x += k1.z * u2.x; accS[6].y += k1.z * u2.y;
            accS[7].x += k1.w * u2.x; accS[7].y += k1.w * u2.y;
        }
#pragma unroll
        for (int i = 0; i < 8; i++) {
            float2 s2 = *(float2*)(S + (g * 8 + i) * 16 + eg2);
            s2.x += accS[i].x; s2.y += accS[i].y;
            *(float2*)(S + (g * 8 + i) * 16 + eg2) = s2;
        }
    }
}

// ------------------------- FIR K=7 (unrolled) -------------------------------
__global__ __launch_bounds__(256) void fir7_kernel(
    const float* __restrict__ x, const float* __restrict__ f, float* __restrict__ y)
{
    int idx = blockIdx.x * 256 + threadIdx.x;
    int c  = idx & (H_ - 1);
    int bl = idx >> 10;
    int l  = bl & (L_ - 1);
    const float* fp = f + (size_t)c * 7;
    float acc = 0.f;
#pragma unroll
    for (int t = 0; t < 7; t++) {
        int dl = t - 6;
        if (l + dl >= 0) acc += x[idx + dl * H_] * fp[t];
    }
    y[idx] = acc;
}

// ------------------------- FIR K=64: smem tile + register sliding window ----
#define FIR64_SMEM ((127 * 128 + 64 * 129) * 4)
__global__ __launch_bounds__(256) void fir64_smem_kernel(
    const float* __restrict__ x, const float* __restrict__ f, float* __restrict__ y)
{
    extern __shared__ float fsm[];
    float* sx = fsm;                 // 127 x 128
    float* sf = fsm + 127 * 128;     // 64 x 129
    const int ctile = blockIdx.x & 7;
    const int ltile = blockIdx.x >> 3;
    const int l0 = ltile * 64;
    const int lb = l0 & (L_ - 1);
    const int c0 = ctile * 128;
    const int tid = threadIdx.x;

    for (int i = tid; i < 64 * 128; i += 256) {
        int c = i >> 6, t = i & 63;
        sf[t * 129 + c] = f[(size_t)(c0 + c) * 64 + t];
    }
    for (int i = tid; i < 127 * 128; i += 256) {
        int j = i >> 7, c = i & 127;
        int lrel = lb + j - 63;
        float v = 0.f;
        if (lrel >= 0)
            v = x[(size_t)(l0 + j - 63) * H_ + c0 + c];
        sx[j * 128 + c] = v;
    }
    __syncthreads();

    const int c = tid & 127;
    const int lg = (tid >> 7) * 32;
    float acc[32], win[32];
#pragma unroll
    for (int i = 0; i < 32; i++) acc[i] = 0.f;
#pragma unroll
    for (int i = 0; i < 32; i++) win[i] = sx[(lg + i) * 128 + c];
#pragma unroll
    for (int t = 0; t < 64; t++) {
        float ft = sf[t * 129 + c];
#pragma unroll
        for (int i = 0; i < 32; i++) acc[i] += ft * win[i];
        if (t < 63) {
#pragma unroll
            for (int i = 0; i < 31; i++) win[i] = win[i + 1];
            win[31] = sx[(lg + t + 32) * 128 + c];
        }
    }
#pragma unroll
    for (int i = 0; i < 32; i++)
        y[(size_t)(l0 + lg + i) * H_ + c0 + c] = acc[i];
}

// ------------------------- fusion gate: h1 @ Wf2 + bf2 -> softmax4 ----------
__global__ __launch_bounds__(128) void gate_kernel(
    const float* __restrict__ h1, const float* __restrict__ Wf2,
    const float* __restrict__ bf2, float* __restrict__ fw)
{
    int bl = blockIdx.x, tid = threadIdx.x;
    float acc[16];
#pragma unroll
    for (int j = 0; j < 16; j++) acc[j] = 0.f;
    const float* hp = h1 + (size_t)bl * F1_;
    for (int d = tid; d < F1_; d += 128) {
        float hv = hp[d];
        const float4* w4 = (const float4*)(Wf2 + d * 16);
        float4 w0 = w4[0], w1 = w4[1], w2 = w4[2], w3 = w4[3];
        acc[0] += hv * w0.x; acc[1] += hv * w0.y; acc[2] += hv * w0.z; acc[3] += hv * w0.w;
        acc[4] += hv * w1.x; acc[5] += hv * w1.y; acc[6] += hv * w1.z; acc[7] += hv * w1.w;
        acc[8] += hv * w2.x; acc[9] += hv * w2.y; acc[10] += hv * w2.z; acc[11] += hv * w2.w;
        acc[12] += hv * w3.x; acc[13] += hv * w3.y; acc[14] += hv * w3.z; acc[15] += hv * w3.w;
    }
    __shared__ float red[16][129];
    __shared__ float logit[16];
#pragma unroll
    for (int j = 0; j < 16; j++) red[j][tid] = acc[j];
    __syncthreads();
    if (tid < 16) {
        float s = bf2[tid];
        for (int i = 0; i < 128; i++) s += red[tid][i];
        logit[tid] = s;
    }
    __syncthreads();
    if (tid < 4) {
        float l0 = logit[tid * 4], l1 = logit[tid * 4 + 1];
        float l2 = logit[tid * 4 + 2], l3 = logit[tid * 4 + 3];
        float m = fmaxf(fmaxf(l0, l1), fmaxf(l2, l3));
        float e0 = expf(l0 - m), e1 = expf(l1 - m), e2 = expf(l2 - m), e3 = expf(l3 - m);
        float inv = 1.f / (e0 + e1 + e2 + e3);
        float* o = fw + (size_t)bl * 16 + tid * 4;
        o[0] = e0 * inv; o[1] = e1 * inv; o[2] = e2 * inv; o[3] = e3 * inv;
    }
}

// ------------------------- branch mix + per-head rmsnorm -> bf16 hi/lo ------
__global__ __launch_bounds__(256) void mix_rms_kernel(
    const float* __restrict__ br_s, const float* __restrict__ br_l,
    const float* __restrict__ br_d, const float* __restrict__ br_v,
    const float* __restrict__ fw, const float* __restrict__ rmsw,
    __nv_bfloat16* __restrict__ Mhi, __nv_bfloat16* __restrict__ Mlo)
{
    int bl = blockIdx.x, h = blockIdx.y, d = threadIdx.x;
    size_t i = (size_t)bl * H_ + h * 256 + d;
    const float* f = fw + (size_t)bl * 16 + h * 4;
    float val = f[0] * br_s[i] + f[1] * br_l[i] + f[2] * br_d[i] + f[3] * br_v[i];
    float ss = val * val;
#pragma unroll
    for (int o = 16; o; o >>= 1) ss += __shfl_xor_sync(0xffffffffu, ss, o);
    __shared__ float red[8];
    __shared__ float scale;
    if ((d & 31) == 0) red[d >> 5] = ss;
    __syncthreads();
    if (d == 0) {
        float t = 0.f;
        for (int k = 0; k < 8; k++) t += red[k];
        scale = rsqrtf(t * (1.f / 256.f) + 1e-5f);
    }
    __syncthreads();
    float o = val * scale * rmsw[d];
    __nv_bfloat16 hb = __float2bfloat16(o);
    Mhi[i] = hb;
    Mlo[i] = __float2bfloat16(o - __bfloat162float(hb));
}

// ------------------------- launcher ----------------------------------------
extern "C" void kernel_launch(void* const* d_in, const int* in_sizes, int n_in,
                              void* d_out, int out_size)
{
    const float* hs   = (const float*)d_in[0];
    const float* Wq   = (const float*)d_in[1];
    const float* Wk   = (const float*)d_in[2];
    const float* Wv   = (const float*)d_in[3];
    const float* Wb   = (const float*)d_in[4];
    const float* cq   = (const float*)d_in[5];
    const float* ck   = (const float*)d_in[6];
    const float* cv   = (const float*)d_in[7];
    const float* fsw  = (const float*)d_in[8];
    const float* flw  = (const float*)d_in[9];
    const float* Wf1  = (const float*)d_in[10];
    const float* bf1  = (const float*)d_in[11];
    const float* Wf2  = (const float*)d_in[12];
    const float* bf2  = (const float*)d_in[13];
    const float* rmsw = (const float*)d_in[14];
    const float* Wo   = (const float*)d_in[15];
    float* out = (float*)d_out;

    float *qkvp, *qs, *ks, *vs, *qn, *kn, *kb, *vb;
    float *u, *w, *delta, *shrt, *lng, *h1, *att, *beta, *fw;
    __nv_bfloat16 *ahi, *alo, *mhi, *mlo, *wqh, *wql, *wf1h, *wf1l, *woh, *wol;
    cudaGetSymbolAddress((void**)&qkvp, g_qkvp);
    cudaGetSymbolAddress((void**)&qs, g_qs);
    cudaGetSymbolAddress((void**)&ks, g_ks);
    cudaGetSymbolAddress((void**)&vs, g_vs);
    cudaGetSymbolAddress((void**)&qn, g_qn);
    cudaGetSymbolAddress((void**)&kn, g_kn);
    cudaGetSymbolAddress((void**)&kb, g_kb);
    cudaGetSymbolAddress((void**)&vb, g_vb);
    cudaGetSymbolAddress((void**)&u, g_u);
    cudaGetSymbolAddress((void**)&w, g_w);
    cudaGetSymbolAddress((void**)&delta, g_delta);
    cudaGetSymbolAddress((void**)&shrt, g_shrt);
    cudaGetSymbolAddress((void**)&lng, g_long);
    cudaGetSymbolAddress((void**)&h1, g_h1);
    cudaGetSymbolAddress((void**)&att, g_att);
    cudaGetSymbolAddress((void**)&beta, g_beta);
    cudaGetSymbolAddress((void**)&fw, g_fw);
    cudaGetSymbolAddress((void**)&ahi, g_ahi);
    cudaGetSymbolAddress((void**)&alo, g_alo);
    cudaGetSymbolAddress((void**)&mhi, g_mhi);
    cudaGetSymbolAddress((void**)&mlo, g_mlo);
    cudaGetSymbolAddress((void**)&wqh, g_wqkv_hi);
    cudaGetSymbolAddress((void**)&wql, g_wqkv_lo);
    cudaGetSymbolAddress((void**)&wf1h, g_wf1_hi);
    cudaGetSymbolAddress((void**)&wf1l, g_wf1_lo);
    cudaGetSymbolAddress((void**)&woh, g_wo_hi);
    cudaGetSymbolAddress((void**)&wol, g_wo_lo);

    cudaFuncSetAttribute(mma_gemm2_kernel, cudaFuncAttributeMaxDynamicSharedMemorySize, MG_SMEM);
    cudaFuncSetAttribute(chunk_kernel, cudaFuncAttributeMaxDynamicSharedMemorySize, CK_SMEM);
    cudaFuncSetAttribute(scan_kernel,  cudaFuncAttributeMaxDynamicSharedMemorySize, SCAN_SMEM);
    cudaFuncSetAttribute(fir64_smem_kernel, cudaFuncAttributeMaxDynamicSharedMemorySize, FIR64_SMEM);

    // ---- prep: bf16 hi/lo conversions (A once, weights once, transposed) ---
    cvt_a_kernel<<<BL_ * H_ / 1024, 256>>>(hs, ahi, alo);
    cvt_wt_kernel<<<dim3(32, 32), 256>>>(Wq, wqh,             wql,             H_, H_);
    cvt_wt_kernel<<<dim3(32, 32), 256>>>(Wk, wqh + 1024 * H_, wql + 1024 * H_, H_, H_);
    cvt_wt_kernel<<<dim3(32, 32), 256>>>(Wv, wqh + 2048 * H_, wql + 2048 * H_, H_, H_);
    cvt_wt_kernel<<<dim3(64, 32), 256>>>(Wf1, wf1h, wf1l, H_, F1_);
    cvt_wt_kernel<<<dim3(32, 32), 256>>>(Wo, woh, wol, H_, H_);

    // ---- fused qkv projection + gate-MLP first layer -----------------------
    mma_gemm2_kernel<<<dim3(NQKV / 128, BL_ / 128), 256, MG_SMEM>>>(
        ahi, alo, wqh, wql, nullptr, qkvp, NQKV, H_, 0);
    mma_gemm2_kernel<<<dim3(F1_ / 128, BL_ / 128), 256, MG_SMEM>>>(
        ahi, alo, wf1h, wf1l, bf1, h1, F1_, H_, 1);

    // short conv + silu (reads packed qkv)
    conv4_silu_kernel<<<BL_ * H_ / 256, 256>>>(qkvp, cq, qs, NQKV, 0);
    conv4_silu_kernel<<<BL_ * H_ / 256, 256>>>(qkvp, ck, ks, NQKV, 1024);
    conv4_silu_kernel<<<BL_ * H_ / 256, 256>>>(qkvp, cv, vs, NQKV, 2048);

    // beta, l2norm + transpose
    beta_kernel<<<BL_, 128>>>(hs, Wb, beta);
    normtr_kernel<<<dim3(BL_, NH_), 256>>>(qs, ks, vs, beta, qn, kn, kb, vb);

    // delta rule
    chunk_kernel<<<dim3(BH_, NC_), 256, CK_SMEM>>>(qn, kn, kb, vb, u, w, att);
    scan_kernel<<<dim3(BH_, 16), 256, SCAN_SMEM>>>(qn, kn, u, w, att, delta);

    // FIR branches
    fir7_kernel<<<BL_ * H_ / 256, 256>>>(vs, fsw, shrt);
    fir64_smem_kernel<<<1024, 256, FIR64_SMEM>>>(vs, flw, lng);

    // gate, mix+rmsnorm (emits bf16 hi/lo), output projection
    gate_kernel<<<BL_, 128>>>(h1, Wf2, bf2, fw);
    mix_rms_kernel<<<dim3(BL_, NH_), 256>>>(shrt, lng, delta, vs, fw, rmsw, mhi, mlo);
    mma_gemm2_kernel<<<dim3(H_ / 128, BL_ / 128), 256, MG_SMEM>>>(
        mhi, mlo, woh, wol, nullptr, out, H_, H_, 0);
}

// round 13
// speedup vs baseline: 1.5385x; 1.1690x over previous
#include <cuda_runtime.h>
#include <cuda_bf16.h>
#include <math.h>
#include <stdint.h>

#define B_   2
#define L_   4096
#define H_   1024
#define NH_  4
#define DK_  256
#define DV_  256
#define C_   32
#define NC_  128
#define BL_  8192
#define BH_  8
#define F1_  2048
#define NQKV 3072

// ------------------------- scratch (static device memory; no allocs) -------
__device__ float g_qkvp[BL_*NQKV];
__device__ float g_qs[BL_*H_], g_ks[BL_*H_], g_vs[BL_*H_];
__device__ float g_qn[BL_*H_], g_kn[BL_*H_], g_kb[BL_*H_], g_vb[BL_*H_];
__device__ float g_u [BL_*H_];
__device__ float g_delta[BL_*H_], g_shrt[BL_*H_], g_long[BL_*H_];
__device__ float g_h1[BL_*F1_];
__device__ float g_att[BH_*NC_*C_*C_];
__device__ float g_beta[BL_*NH_];
__device__ float g_fw[BL_*16];
// bf16 hi/lo staging
__device__ __nv_bfloat16 g_ahi[BL_*H_],  g_alo[BL_*H_];
__device__ __nv_bfloat16 g_mhi[BL_*H_],  g_mlo[BL_*H_];
__device__ __nv_bfloat16 g_qnh[BL_*H_],  g_qnl[BL_*H_];
__device__ __nv_bfloat16 g_wh[BL_*H_],   g_wl[BL_*H_];
__device__ __nv_bfloat16 g_wqkv_hi[NQKV*H_], g_wqkv_lo[NQKV*H_];
__device__ __nv_bfloat16 g_wf1_hi[F1_*H_],   g_wf1_lo[F1_*H_];
__device__ __nv_bfloat16 g_wo_hi[H_*H_],     g_wo_lo[H_*H_];

__device__ __forceinline__ float sigmoidf_(float x) { return 1.f / (1.f + expf(-x)); }
__device__ __forceinline__ float geluf_(float x) {
    return 0.5f * x * (1.f + erff(x * 0.70710678118654752440f));
}
__device__ __forceinline__ uint32_t smem_u32_(const void* p) {
    uint32_t a;
    asm("{ .reg .u64 t; cvta.to.shared.u64 t, %1; cvt.u32.u64 %0, t; }" : "=r"(a) : "l"(p));
    return a;
}
__device__ __forceinline__ uint32_t pack_bf16_hi_(float x, float y) {
    __nv_bfloat162 h = __halves2bfloat162(__float2bfloat16(x), __float2bfloat16(y));
    return *reinterpret_cast<uint32_t*>(&h);
}
__device__ __forceinline__ uint32_t pack_bf16_lo_(float x, float y) {
    float hx = __bfloat162float(__float2bfloat16(x));
    float hy = __bfloat162float(__float2bfloat16(y));
    __nv_bfloat162 l = __halves2bfloat162(__float2bfloat16(x - hx), __float2bfloat16(y - hy));
    return *reinterpret_cast<uint32_t*>(&l);
}
__device__ __forceinline__ void cp16_(uint32_t dst, const void* src) {
    asm volatile("cp.async.ca.shared.global [%0], [%1], 16;" :: "r"(dst), "l"(src));
}

// ------------------------- prep: fp32 -> bf16 hi/lo ------------------------
__global__ __launch_bounds__(256) void cvt_a_kernel(
    const float* __restrict__ x, __nv_bfloat16* __restrict__ hi, __nv_bfloat16* __restrict__ lo)
{
    int i = (blockIdx.x * 256 + threadIdx.x) * 4;
    float4 v = *(const float4*)(x + i);
    uint2 oh, ol;
    oh.x = pack_bf16_hi_(v.x, v.y); oh.y = pack_bf16_hi_(v.z, v.w);
    ol.x = pack_bf16_lo_(v.x, v.y); ol.y = pack_bf16_lo_(v.z, v.w);
    *(uint2*)(hi + i) = oh;
    *(uint2*)(lo + i) = ol;
}

// W [K][N] -> Wt hi/lo [N][K]  (32x32 smem transpose)
__global__ __launch_bounds__(256) void cvt_wt_kernel(
    const float* __restrict__ W, __nv_bfloat16* __restrict__ hi, __nv_bfloat16* __restrict__ lo,
    int K, int N)
{
    __shared__ float tile[32][33];
    int n0 = blockIdx.x * 32, k0 = blockIdx.y * 32;
    int tx = threadIdx.x & 31, ty = threadIdx.x >> 5;
#pragma unroll
    for (int i = 0; i < 4; i++)
        tile[ty + 8 * i][tx] = W[(size_t)(k0 + ty + 8 * i) * N + n0 + tx];
    __syncthreads();
#pragma unroll
    for (int i = 0; i < 4; i++) {
        float v = tile[tx][ty + 8 * i];
        __nv_bfloat16 h = __float2bfloat16(v);
        size_t o = (size_t)(n0 + ty + 8 * i) * K + k0 + tx;
        hi[o] = h;
        lo[o] = __float2bfloat16(v - __bfloat162float(h));
    }
}

// ===================== warp-mma bf16 split-x3 GEMM (ldmatrix) ===============
#define MMA_BF16_(c, a0, a1, a2, a3, b0, b1) \
    asm volatile("mma.sync.aligned.m16n8k16.row.col.f32.bf16.bf16.f32 " \
        "{%0,%1,%2,%3}, {%4,%5,%6,%7}, {%8,%9}, {%0,%1,%2,%3};" \
        : "+f"((c)[0]), "+f"((c)[1]), "+f"((c)[2]), "+f"((c)[3]) \
        : "r"(a0), "r"(a1), "r"(a2), "r"(a3), "r"(b0), "r"(b1))

#define LDSM_X4_(r0, r1, r2, r3, addr) \
    asm volatile("ldmatrix.sync.aligned.m8n8.x4.shared.b16 {%0,%1,%2,%3}, [%4];" \
        : "=r"(r0), "=r"(r1), "=r"(r2), "=r"(r3) : "r"(addr))

#define MG_SMEM 65536

__global__ __launch_bounds__(256, 2) void mma_gemm2_kernel(
    const __nv_bfloat16* __restrict__ Ahi_g, const __nv_bfloat16* __restrict__ Alo_g,
    const __nv_bfloat16* __restrict__ Bhi_g, const __nv_bfloat16* __restrict__ Blo_g,
    const float* __restrict__ bias, float* __restrict__ C,
    int N, int K, int act)
{
    extern __shared__ __align__(16) uint32_t smem_u[];
    const uint32_t smem_b = smem_u32_(smem_u);
    const int tid = threadIdx.x;
    const int wid = tid >> 5, lane = tid & 31;
    const int g = lane >> 2, t = lane & 3;
    const int warp_m = (wid & 3) * 32;
    const int warp_n = (wid >> 2) * 64;
    const int row0 = blockIdx.y * 128, col0 = blockIdx.x * 128;

    const int qq = lane >> 3, rr = lane & 7;
    const int arow = warp_m + ((qq & 1) << 3) + rr;
    const int aqb  = (qq >> 1) & 1;
    const int brow = warp_n + ((qq >> 1) << 3) + rr;
    const int bqb  = qq & 1;

    float acc[2][8][4];
#pragma unroll
    for (int mt = 0; mt < 2; mt++)
#pragma unroll
        for (int nt = 0; nt < 8; nt++)
#pragma unroll
            for (int e = 0; e < 4; e++) acc[mt][nt][e] = 0.f;

    for (int k0 = 0; k0 < K; k0 += 64) {
        __syncthreads();
#pragma unroll
        for (int i = 0; i < 16; i++) {
            const int op = i >> 2;
            int rem = (i & 3) * 256 + tid;
            int row = rem >> 3, c = rem & 7;
            const __nv_bfloat16* gsrc =
                (op == 0) ? Ahi_g + (size_t)(row0 + row) * K + k0 + c * 8 :
                (op == 1) ? Alo_g + (size_t)(row0 + row) * K + k0 + c * 8 :
                (op == 2) ? Bhi_g + (size_t)(col0 + row) * K + k0 + c * 8 :
                            Blo_g + (size_t)(col0 + row) * K + k0 + c * 8;
            uint32_t dst = smem_b + (uint32_t)(((op << 12) + row * 32 + ((c ^ (row & 7)) << 2)) << 2);
            cp16_(dst, gsrc);
        }
        asm volatile("cp.async.commit_group;");
        asm volatile("cp.async.wait_group 0;");
        __syncthreads();

#pragma unroll
        for (int ks = 0; ks < 4; ks++) {
            uint32_t ah[2][4], al[2][4];
#pragma unroll
            for (int mt = 0; mt < 2; mt++) {
                int row = arow + mt * 16;
                int pc = (2 * ks + aqb) ^ (row & 7);
                uint32_t ad = smem_b + (uint32_t)((row * 32 + pc * 4) << 2);
                LDSM_X4_(ah[mt][0], ah[mt][1], ah[mt][2], ah[mt][3], ad);
                LDSM_X4_(al[mt][0], al[mt][1], al[mt][2], al[mt][3], ad + 16384);
            }
#pragma unroll
            for (int p = 0; p < 4; p++) {
                int n = brow + p * 16;
                int pc = (2 * ks + bqb) ^ (n & 7);
                uint32_t bd = smem_b + (uint32_t)(((8192 + n * 32 + pc * 4)) << 2);
                uint32_t bh0, bh1, bh2, bh3, bl0, bl1, bl2, bl3;
                LDSM_X4_(bh0, bh1, bh2, bh3, bd);
                LDSM_X4_(bl0, bl1, bl2, bl3, bd + 16384);
#pragma unroll
                for (int mt = 0; mt < 2; mt++) {
                    MMA_BF16_(acc[mt][2*p],   ah[mt][0], ah[mt][1], ah[mt][2], ah[mt][3], bh0, bh1);
                    MMA_BF16_(acc[mt][2*p],   ah[mt][0], ah[mt][1], ah[mt][2], ah[mt][3], bl0, bl1);
                    MMA_BF16_(acc[mt][2*p],   al[mt][0], al[mt][1], al[mt][2], al[mt][3], bh0, bh1);
                    MMA_BF16_(acc[mt][2*p+1], ah[mt][0], ah[mt][1], ah[mt][2], ah[mt][3], bh2, bh3);
                    MMA_BF16_(acc[mt][2*p+1], ah[mt][0], ah[mt][1], ah[mt][2], ah[mt][3], bl2, bl3);
                    MMA_BF16_(acc[mt][2*p+1], al[mt][0], al[mt][1], al[mt][2], al[mt][3], bh2, bh3);
                }
            }
        }
    }

#pragma unroll
    for (int mt = 0; mt < 2; mt++) {
        int r0g = row0 + warp_m + mt * 16 + g;
#pragma unroll
        for (int nt = 0; nt < 8; nt++) {
            int c = col0 + warp_n + nt * 8 + 2 * t;
            float2 v0, v1;
            v0.x = acc[mt][nt][0]; v0.y = acc[mt][nt][1];
            v1.x = acc[mt][nt][2]; v1.y = acc[mt][nt][3];
            if (act == 1) {
                float b0 = bias[c], b1 = bias[c + 1];
                v0.x = geluf_(v0.x + b0); v0.y = geluf_(v0.y + b1);
                v1.x = geluf_(v1.x + b0); v1.y = geluf_(v1.y + b1);
            }
            *(float2*)(C + (size_t)r0g * N + c) = v0;
            *(float2*)(C + (size_t)(r0g + 8) * N + c) = v1;
        }
    }
}

// ------------------------- short causal depthwise conv (K=4) + silu ---------
__global__ __launch_bounds__(256) void conv4_silu_kernel(
    const float* __restrict__ x, const float* __restrict__ f, float* __restrict__ y,
    int xstride, int xoff)
{
    int idx = blockIdx.x * 256 + threadIdx.x;
    int c  = idx & (H_ - 1);
    int bl = idx >> 10;
    int l  = bl & (L_ - 1);
    const float* xp = x + (size_t)bl * xstride + xoff + c;
    float4 fv = *(const float4*)(f + c * 4);
    float acc = fv.w * xp[0];
    if (l >= 1) acc += fv.z * xp[-xstride];
    if (l >= 2) acc += fv.y * xp[-2 * xstride];
    if (l >= 3) acc += fv.x * xp[-3 * xstride];
    y[idx] = acc * sigmoidf_(acc);
}

// ------------------------- beta = sigmoid(hs @ Wb) --------------------------
__global__ __launch_bounds__(128) void beta_kernel(
    const float* __restrict__ hs, const float* __restrict__ Wb, float* __restrict__ beta)
{
    int bl = blockIdx.x;
    int wrp = threadIdx.x >> 5, lane = threadIdx.x & 31;
    const float* hp = hs + (size_t)bl * H_;
    float acc = 0.f;
    for (int d = lane; d < H_; d += 32) acc += hp[d] * Wb[d * NH_ + wrp];
#pragma unroll
    for (int o = 16; o; o >>= 1) acc += __shfl_xor_sync(0xffffffffu, acc, o);
    if (lane == 0) beta[bl * NH_ + wrp] = sigmoidf_(acc);
}

// ------------------------- l2norm + beta-scale + transpose (+ qn bf16) ------
__global__ __launch_bounds__(256) void normtr_kernel(
    const float* __restrict__ qs, const float* __restrict__ ks, const float* __restrict__ vs,
    const float* __restrict__ beta,
    float* __restrict__ qn, float* __restrict__ kn, float* __restrict__ kb, float* __restrict__ vb,
    __nv_bfloat16* __restrict__ qnh, __nv_bfloat16* __restrict__ qnl)
{
    int bl = blockIdx.x, h = blockIdx.y, d = threadIdx.x;
    int b = bl >> 12;
    int l = bl & (L_ - 1);
    size_t src = (size_t)bl * H_ + h * DK_ + d;
    float qv = qs[src], kv = ks[src], vv = vs[src];
    float s1 = qv * qv, s2 = kv * kv;
#pragma unroll
    for (int o = 16; o; o >>= 1) {
        s1 += __shfl_xor_sync(0xffffffffu, s1, o);
        s2 += __shfl_xor_sync(0xffffffffu, s2, o);
    }
    __shared__ float r1[8], r2[8];
    __shared__ float inv1, inv2;
    int lane = d & 31, wid = d >> 5;
    if (lane == 0) { r1[wid] = s1; r2[wid] = s2; }
    __syncthreads();
    if (d == 0) {
        float t1 = 0.f, t2 = 0.f;
        for (int i = 0; i < 8; i++) { t1 += r1[i]; t2 += r2[i]; }
        inv1 = rsqrtf(t1);
        inv2 = rsqrtf(t2);
    }
    __syncthreads();
    float bt = beta[bl * NH_ + h];
    size_t dst = (((size_t)b * NH_ + h) * L_ + l) * DK_ + d;
    float knv = kv * inv2;
    float qnv = qv * inv1;
    qn[dst] = qnv;
    kn[dst] = knv;
    kb[dst] = knv * bt;
    vb[dst] = vv * bt;
    __nv_bfloat16 qh = __float2bfloat16(qnv);
    qnh[dst] = qh;
    qnl[dst] = __float2bfloat16(qnv - __bfloat162float(qh));
}

// ------------------------- per-chunk: UT transform, u, w, attn --------------
// w output emitted as bf16 hi/lo (consumed only by HMMA scan).
#define CK_STRIDE 257
#define CK_SMEM ((96 * CK_STRIDE + 32 * 33) * 4)
__global__ __launch_bounds__(256) void chunk_kernel(
    const float* __restrict__ qn, const float* __restrict__ kn,
    const float* __restrict__ kb, const float* __restrict__ vb,
    float* __restrict__ U, __nv_bfloat16* __restrict__ Wmh, __nv_bfloat16* __restrict__ Wml,
    float* __restrict__ ATT)
{
    extern __shared__ float sm[];
    float* sk  = sm;
    float* skb = sm + 32 * CK_STRIDE;
    float* sx  = sm + 64 * CK_STRIDE;
    float* T   = sm + 96 * CK_STRIDE;
    int bh = blockIdx.x, n = blockIdx.y;
    int tid = threadIdx.x;
    size_t base = ((size_t)bh * L_ + n * C_) * DK_;

    for (int i = tid; i < 2048; i += 256) {
        int r = i >> 6, c4 = (i & 63) << 2;
        float4 a = ((const float4*)(kn + base))[i];
        float4 b = ((const float4*)(kb + base))[i];
        float4 v = ((const float4*)(vb + base))[i];
        float* pk = sk + r * CK_STRIDE + c4;
        float* pb = skb + r * CK_STRIDE + c4;
        float* pv = sx + r * CK_STRIDE + c4;
        pk[0] = a.x; pk[1] = a.y; pk[2] = a.z; pk[3] = a.w;
        pb[0] = b.x; pb[1] = b.y; pb[2] = b.z; pb[3] = b.w;
        pv[0] = v.x; pv[1] = v.y; pv[2] = v.z; pv[3] = v.w;
    }
    __syncthreads();

    for (int e = tid; e < 1024; e += 256) {
        int i = e >> 5, j = e & 31;
        float a = 0.f;
        if (j < i) {
            const float* pi = skb + i * CK_STRIDE;
            const float* pj = sk + j * CK_STRIDE;
            for (int d = 0; d < 256; d++) a -= pi[d] * pj[d];
        }
        T[i * 33 + j] = a;
    }
    __syncthreads();

    if (tid < 32) {
        int j = tid;
        for (int i = 1; i < 32; i++) {
            float rv = T[i * 33 + j];
            float acc = rv;
            for (int m = 1; m < i; m++)
                acc += __shfl_sync(0xffffffffu, rv, m) * T[m * 33 + j];
            __syncwarp();
            T[i * 33 + j] = acc;
            __syncwarp();
        }
        T[j * 33 + j] = 1.f;
    }
    __syncthreads();

    for (int idx = tid; idx < 8192; idx += 256) {
        int c = idx >> 8, d = idx & 255;
        float au = 0.f, aw = 0.f;
#pragma unroll
        for (int j = 0; j < 32; j++) {
            float t = T[c * 33 + j];
            au += t * sx[j * CK_STRIDE + d];
            aw += t * skb[j * CK_STRIDE + d];
        }
        U[base + idx] = au;
        __nv_bfloat16 hh = __float2bfloat16(aw);
        Wmh[base + idx] = hh;
        Wml[base + idx] = __float2bfloat16(aw - __bfloat162float(hh));
    }
    __syncthreads();

    for (int i = tid; i < 2048; i += 256) {
        int r = i >> 6, c4 = (i & 63) << 2;
        float4 q = ((const float4*)(qn + base))[i];
        float* pv = sx + r * CK_STRIDE + c4;
        pv[0] = q.x; pv[1] = q.y; pv[2] = q.z; pv[3] = q.w;
    }
    __syncthreads();
    float* att = ATT + ((size_t)bh * NC_ + n) * 1024;
    for (int e = tid; e < 1024; e += 256) {
        int c = e >> 5, j = e & 31;
        float a = 0.f;
        if (j <= c) {
            const float* pq = sx + c * CK_STRIDE;
            const float* pk = sk + j * CK_STRIDE;
            for (int d = 0; d < 256; d++) a += pq[d] * pk[d];
        }
        att[e] = a;
    }
}

// ------------------------- sequential chunk scan: HMMA wS/qS ----------------
// S fp32 [256][16] (verified). Per step: S -> Sb16 hi/lo transposed [e][d]
// (132-word rows); w/q arrive pre-split bf16, cp.async'd into R11-style
// swizzled A tiles (128-word rows). 8 warps = {w,q} x 2 m-tiles x 2 n-tiles,
// 16 ksteps x 3 split-MMA each. kS + attn stay FFMA.
// smem (floats): S 0 | sk 4096 | A 12416 (wh,wl,qh,ql x4096w) | Sbh 28800
// | Sbl 30912 | su 33024 | sut 33536 | sat 34048 | swS 35200 | sqS 35776
#define SCAN_SMEM (36352 * 4)
__global__ __launch_bounds__(256) void scan_kernel(
    const float* __restrict__ kn,
    const __nv_bfloat16* __restrict__ qh_g, const __nv_bfloat16* __restrict__ ql_g,
    const __nv_bfloat16* __restrict__ wh_g, const __nv_bfloat16* __restrict__ wl_g,
    const float* __restrict__ U, const float* __restrict__ ATT, float* __restrict__ OUT)
{
    extern __shared__ float sm[];
    float* S   = sm;             // [256][16]
    float* sk  = sm + 4096;      // [32][260]
    uint32_t* sbh = (uint32_t*)(sm + 28800);
    uint32_t* sbl = (uint32_t*)(sm + 30912);
    float* su  = sm + 33024;     // [32][16]
    float* sut = sm + 33536;     // [32][16]
    float* sat = sm + 34048;     // [32][36]
    float* swS = sm + 35200;     // [32][18]
    float* sqS = sm + 35776;     // [32][18]
    const uint32_t smem_b = smem_u32_(sm);
    const int bh = blockIdx.x, tile = blockIdx.y;
    const int tid = threadIdx.x;
    const int wid = tid >> 5, lane = tid & 31;
    const int b = bh >> 2, h = bh & 3;
    const int g = tid >> 3, eg = tid & 7, eg2 = eg * 2;
    // HMMA roles
    const int pr = wid & 1, mt = (wid >> 1) & 1, nt = wid >> 2;
    const int qq = lane >> 3, rr = lane & 7;
    const int arow = mt * 16 + ((qq & 1) << 3) + rr;
    const int aqb  = qq >> 1;
    const int brow = ((qq >> 1) << 3) + rr;
    const int bqb  = qq & 1;
    const int gg = lane >> 2, tt = lane & 3;
    const uint32_t abaseW = 12416u + (pr ? 8192u : 0u);
    // S conversion role
    const int ce = tid & 15, cd0 = (tid >> 4) * 16;

    for (int i = tid; i < 4096; i += 256) S[i] = 0.f;

    for (int n = 0; n < NC_; n++) {
        __syncthreads();
        size_t base = ((size_t)bh * L_ + n * C_) * 256;
        for (int i = tid; i < 2048; i += 256) {
            int c = i >> 6, o = (i & 63) * 4;
            *(float4*)(sk + c * 260 + o) = ((const float4*)(kn + base))[i];
        }
        // A tiles: arr 0=wh 1=wl 2=qh 3=ql; arr = i>>2 (static per unroll)
#pragma unroll
        for (int i = 0; i < 16; i++) {
            const int arr = i >> 2, r = i & 3;
            int row = r * 8 + wid;
            int ch  = lane;
            const __nv_bfloat16* gp =
                (arr == 0) ? wh_g + base + row * 256 + ch * 8 :
                (arr == 1) ? wl_g + base + row * 256 + ch * 8 :
                (arr == 2) ? qh_g + base + row * 256 + ch * 8 :
                             ql_g + base + row * 256 + ch * 8;
            uint32_t w = 12416u + (uint32_t)(arr * 4096 + row * 128
                         + (((ch & 24) | ((ch & 7) ^ (row & 7))) << 2));
            cp16_(smem_b + w * 4, gp);
        }
        asm volatile("cp.async.commit_group;");
        if (tid < 128) {
            int c = tid >> 2, e4 = tid & 3;
            ((float4*)su)[tid] = *(const float4*)(U + base + c * 256 + tile * 16 + e4 * 4);
        }
        {
            int c = tid >> 3, j4 = (tid & 7) * 4;
            *(float4*)(sat + c * 36 + j4) =
                ((const float4*)(ATT + ((size_t)bh * NC_ + n) * 1024))[tid];
        }
        // S[d][e] -> Sb16 hi/lo [e][d] (2 bf16 per word)
#pragma unroll
        for (int i2 = 0; i2 < 8; i2++) {
            int d = cd0 + i2 * 2;
            float x = S[d * 16 + ce], y = S[(d + 1) * 16 + ce];
            sbh[ce * 132 + (d >> 1)] = pack_bf16_hi_(x, y);
            sbl[ce * 132 + (d >> 1)] = pack_bf16_lo_(x, y);
        }
        asm volatile("cp.async.wait_group 0;");
        __syncthreads();

        // HMMA: this warp's 16(c) x 8(e) tile of wS or qS over k=256
        float acc[4] = {0.f, 0.f, 0.f, 0.f};
#pragma unroll
        for (int ks = 0; ks < 16; ks++) {
            int ch = 2 * ks + aqb;
            uint32_t aw_ = abaseW + (uint32_t)(arow * 128
                          + (((ch & 24) | ((ch & 7) ^ (arow & 7))) << 2));
            uint32_t ah0, ah1, ah2, ah3, al0, al1, al2, al3;
            LDSM_X4_(ah0, ah1, ah2, ah3, smem_b + aw_ * 4);
            LDSM_X4_(al0, al1, al2, al3, smem_b + (aw_ + 4096u) * 4);
            uint32_t bw_ = 28800u + (uint32_t)(brow * 132 + (2 * ks + bqb) * 4);
            uint32_t bh0, bh1, bh2, bh3, bl0, bl1, bl2, bl3;
            LDSM_X4_(bh0, bh1, bh2, bh3, smem_b + bw_ * 4);
            LDSM_X4_(bl0, bl1, bl2, bl3, smem_b + (bw_ + 2112u) * 4);
            uint32_t B0h = nt ? bh2 : bh0, B1h = nt ? bh3 : bh1;
            uint32_t B0l = nt ? bl2 : bl0, B1l = nt ? bl3 : bl1;
            MMA_BF16_(acc, ah0, ah1, ah2, ah3, B0h, B1h);
            MMA_BF16_(acc, ah0, ah1, ah2, ah3, B0l, B1l);
            MMA_BF16_(acc, al0, al1, al2, al3, B0h, B1h);
        }
        {
            float* dst = pr ? sqS : swS;
            int c0 = mt * 16 + gg, e0 = nt * 8 + 2 * tt;
            *(float2*)(dst + c0 * 18 + e0) = make_float2(acc[0], acc[1]);
            *(float2*)(dst + (c0 + 8) * 18 + e0) = make_float2(acc[2], acc[3]);
        }
        __syncthreads();

        // ut = u - wS
        float2 uv = *(float2*)(su + g * 16 + eg2);
        float2 wv = *(float2*)(swS + g * 18 + eg2);
        float2 ut = make_float2(uv.x - wv.x, uv.y - wv.y);
        *(float2*)(sut + g * 16 + eg2) = ut;
        float2 aq = *(float2*)(sqS + g * 18 + eg2);
        __syncthreads();

        // o = qS + attn @ u_t
        const float* ar = sat + g * 36;
#pragma unroll
        for (int j = 0; j < 32; j += 4) {
            float4 a4 = *(const float4*)(ar + j);
            float2 u0 = *(float2*)(sut + (j + 0) * 16 + eg2);
            float2 u1 = *(float2*)(sut + (j + 1) * 16 + eg2);
            float2 u2 = *(float2*)(sut + (j + 2) * 16 + eg2);
            float2 u3 = *(float2*)(sut + (j + 3) * 16 + eg2);
            aq.x += a4.x * u0.x + a4.y * u1.x + a4.z * u2.x + a4.w * u3.x;
            aq.y += a4.x * u0.y + a4.y * u1.y + a4.z * u2.y + a4.w * u3.y;
        }
        *(float2*)(OUT + (size_t)(b * L_ + n * C_ + g) * H_ + h * 256 + tile * 16 + eg2) = aq;

        // S += k^T @ u_t
        float2 accS[8];
#pragma unroll
        for (int i = 0; i < 8; i++) accS[i] = make_float2(0.f, 0.f);
        for (int c2 = 0; c2 < 32; c2++) {
            float2 u2 = *(float2*)(sut + c2 * 16 + eg2);
            const float* kr = sk + c2 * 260 + g * 8;
            float4 k0 = *(const float4*)(kr);
            float4 k1 = *(const float4*)(kr + 4);
            accS[0].x += k0.x * u2.x; accS[0].y += k0.x * u2.y;
            accS[1].x += k0.y * u2.x; accS[1].y += k0.y * u2.y;
            accS[2].x += k0.z * u2.x; accS[2].y += k0.z * u2.y;
            accS[3].x += k0.w * u2.x; accS[3].y += k0.w * u2.y;
            accS[4].x += k1.x * u2.x; accS[4].y += k1.x * u2.y;
            accS[5].x += k1.y * u2.x; accS[5].y += k1.y * u2.y;
            accS[6].x += k1.z * u2.x; accS[6].y += k1.z * u2.y;
            accS[7].x += k1.w * u2.x; accS[7].y += k1.w * u2.y;
        }
#pragma unroll
        for (int i = 0; i < 8; i++) {
            float2 s2 = *(float2*)(S + (g * 8 + i) * 16 + eg2);
            s2.x += accS[i].x; s2.y += accS[i].y;
            *(float2*)(S + (g * 8 + i) * 16 + eg2) = s2;
        }
    }
}

// ------------------------- FIR K=7 (unrolled) -------------------------------
__global__ __launch_bounds__(256) void fir7_kernel(
    const float* __restrict__ x, const float* __restrict__ f, float* __restrict__ y)
{
    int idx = blockIdx.x * 256 + threadIdx.x;
    int c  = idx & (H_ - 1);
    int bl = idx >> 10;
    int l  = bl & (L_ - 1);
    const float* fp = f + (size_t)c * 7;
    float acc = 0.f;
#pragma unroll
    for (int t = 0; t < 7; t++) {
        int dl = t - 6;
        if (l + dl >= 0) acc += x[idx + dl * H_] * fp[t];
    }
    y[idx] = acc;
}

// ------------------------- FIR K=64: smem tile + register sliding window ----
#define FIR64_SMEM ((127 * 128 + 64 * 129) * 4)
__global__ __launch_bounds__(256) void fir64_smem_kernel(
    const float* __restrict__ x, const float* __restrict__ f, float* __restrict__ y)
{
    extern __shared__ float fsm[];
    float* sx = fsm;
    float* sf = fsm + 127 * 128;
    const int ctile = blockIdx.x & 7;
    const int ltile = blockIdx.x >> 3;
    const int l0 = ltile * 64;
    const int lb = l0 & (L_ - 1);
    const int c0 = ctile * 128;
    const int tid = threadIdx.x;

    for (int i = tid; i < 64 * 128; i += 256) {
        int c = i >> 6, t = i & 63;
        sf[t * 129 + c] = f[(size_t)(c0 + c) * 64 + t];
    }
    for (int i = tid; i < 127 * 128; i += 256) {
        int j = i >> 7, c = i & 127;
        int lrel = lb + j - 63;
        float v = 0.f;
        if (lrel >= 0)
            v = x[(size_t)(l0 + j - 63) * H_ + c0 + c];
        sx[j * 128 + c] = v;
    }
    __syncthreads();

    const int c = tid & 127;
    const int lg = (tid >> 7) * 32;
    float acc[32], win[32];
#pragma unroll
    for (int i = 0; i < 32; i++) acc[i] = 0.f;
#pragma unroll
    for (int i = 0; i < 32; i++) win[i] = sx[(lg + i) * 128 + c];
#pragma unroll
    for (int t = 0; t < 64; t++) {
        float ft = sf[t * 129 + c];
#pragma unroll
        for (int i = 0; i < 32; i++) acc[i] += ft * win[i];
        if (t < 63) {
#pragma unroll
            for (int i = 0; i < 31; i++) win[i] = win[i + 1];
            win[31] = sx[(lg + t + 32) * 128 + c];
        }
    }
#pragma unroll
    for (int i = 0; i < 32; i++)
        y[(size_t)(l0 + lg + i) * H_ + c0 + c] = acc[i];
}

// ------------------------- fusion gate: h1 @ Wf2 + bf2 -> softmax4 ----------
__global__ __launch_bounds__(128) void gate_kernel(
    const float* __restrict__ h1, const float* __restrict__ Wf2,
    const float* __restrict__ bf2, float* __restrict__ fw)
{
    int bl = blockIdx.x, tid = threadIdx.x;
    float acc[16];
#pragma unroll
    for (int j = 0; j < 16; j++) acc[j] = 0.f;
    const float* hp = h1 + (size_t)bl * F1_;
    for (int d = tid; d < F1_; d += 128) {
        float hv = hp[d];
        const float4* w4 = (const float4*)(Wf2 + d * 16);
        float4 w0 = w4[0], w1 = w4[1], w2 = w4[2], w3 = w4[3];
        acc[0] += hv * w0.x; acc[1] += hv * w0.y; acc[2] += hv * w0.z; acc[3] += hv * w0.w;
        acc[4] += hv * w1.x; acc[5] += hv * w1.y; acc[6] += hv * w1.z; acc[7] += hv * w1.w;
        acc[8] += hv * w2.x; acc[9] += hv * w2.y; acc[10] += hv * w2.z; acc[11] += hv * w2.w;
        acc[12] += hv * w3.x; acc[13] += hv * w3.y; acc[14] += hv * w3.z; acc[15] += hv * w3.w;
    }
    __shared__ float red[16][129];
    __shared__ float logit[16];
#pragma unroll
    for (int j = 0; j < 16; j++) red[j][tid] = acc[j];
    __syncthreads();
    if (tid < 16) {
        float s = bf2[tid];
        for (int i = 0; i < 128; i++) s += red[tid][i];
        logit[tid] = s;
    }
    __syncthreads();
    if (tid < 4) {
        float l0 = logit[tid * 4], l1 = logit[tid * 4 + 1];
        float l2 = logit[tid * 4 + 2], l3 = logit[tid * 4 + 3];
        float m = fmaxf(fmaxf(l0, l1), fmaxf(l2, l3));
        float e0 = expf(l0 - m), e1 = expf(l1 - m), e2 = expf(l2 - m), e3 = expf(l3 - m);
        float inv = 1.f / (e0 + e1 + e2 + e3);
        float* o = fw + (size_t)bl * 16 + tid * 4;
        o[0] = e0 * inv; o[1] = e1 * inv; o[2] = e2 * inv; o[3] = e3 * inv;
    }
}

// ------------------------- branch mix + per-head rmsnorm -> bf16 hi/lo ------
__global__ __launch_bounds__(256) void mix_rms_kernel(
    const float* __restrict__ br_s, const float* __restrict__ br_l,
    const float* __restrict__ br_d, const float* __restrict__ br_v,
    const float* __restrict__ fw, const float* __restrict__ rmsw,
    __nv_bfloat16* __restrict__ Mhi, __nv_bfloat16* __restrict__ Mlo)
{
    int bl = blockIdx.x, h = blockIdx.y, d = threadIdx.x;
    size_t i = (size_t)bl * H_ + h * 256 + d;
    const float* f = fw + (size_t)bl * 16 + h * 4;
    float val = f[0] * br_s[i] + f[1] * br_l[i] + f[2] * br_d[i] + f[3] * br_v[i];
    float ss = val * val;
#pragma unroll
    for (int o = 16; o; o >>= 1) ss += __shfl_xor_sync(0xffffffffu, ss, o);
    __shared__ float red[8];
    __shared__ float scale;
    if ((d & 31) == 0) red[d >> 5] = ss;
    __syncthreads();
    if (d == 0) {
        float t = 0.f;
        for (int k = 0; k < 8; k++) t += red[k];
        scale = rsqrtf(t * (1.f / 256.f) + 1e-5f);
    }
    __syncthreads();
    float o = val * scale * rmsw[d];
    __nv_bfloat16 hb = __float2bfloat16(o);
    Mhi[i] = hb;
    Mlo[i] = __float2bfloat16(o - __bfloat162float(hb));
}

// ------------------------- launcher ----------------------------------------
extern "C" void kernel_launch(void* const* d_in, const int* in_sizes, int n_in,
                              void* d_out, int out_size)
{
    const float* hs   = (const float*)d_in[0];
    const float* Wq   = (const float*)d_in[1];
    const float* Wk   = (const float*)d_in[2];
    const float* Wv   = (const float*)d_in[3];
    const float* Wb   = (const float*)d_in[4];
    const float* cq   = (const float*)d_in[5];
    const float* ck   = (const float*)d_in[6];
    const float* cv   = (const float*)d_in[7];
    const float* fsw  = (const float*)d_in[8];
    const float* flw  = (const float*)d_in[9];
    const float* Wf1  = (const float*)d_in[10];
    const float* bf1  = (const float*)d_in[11];
    const float* Wf2  = (const float*)d_in[12];
    const float* bf2  = (const float*)d_in[13];
    const float* rmsw = (const float*)d_in[14];
    const float* Wo   = (const float*)d_in[15];
    float* out = (float*)d_out;

    float *qkvp, *qs, *ks, *vs, *qn, *kn, *kb, *vb;
    float *u, *delta, *shrt, *lng, *h1, *att, *beta, *fw;
    __nv_bfloat16 *ahi, *alo, *mhi, *mlo, *wqh, *wql, *wf1h, *wf1l, *woh, *wol;
    __nv_bfloat16 *qnh, *qnl, *wmh, *wml;
    cudaGetSymbolAddress((void**)&qkvp, g_qkvp);
    cudaGetSymbolAddress((void**)&qs, g_qs);
    cudaGetSymbolAddress((void**)&ks, g_ks);
    cudaGetSymbolAddress((void**)&vs, g_vs);
    cudaGetSymbolAddress((void**)&qn, g_qn);
    cudaGetSymbolAddress((void**)&kn, g_kn);
    cudaGetSymbolAddress((void**)&kb, g_kb);
    cudaGetSymbolAddress((void**)&vb, g_vb);
    cudaGetSymbolAddress((void**)&u, g_u);
    cudaGetSymbolAddress((void**)&delta, g_delta);
    cudaGetSymbolAddress((void**)&shrt, g_shrt);
    cudaGetSymbolAddress((void**)&lng, g_long);
    cudaGetSymbolAddress((void**)&h1, g_h1);
    cudaGetSymbolAddress((void**)&att, g_att);
    cudaGetSymbolAddress((void**)&beta, g_beta);
    cudaGetSymbolAddress((void**)&fw, g_fw);
    cudaGetSymbolAddress((void**)&ahi, g_ahi);
    cudaGetSymbolAddress((void**)&alo, g_alo);
    cudaGetSymbolAddress((void**)&mhi, g_mhi);
    cudaGetSymbolAddress((void**)&mlo, g_mlo);
    cudaGetSymbolAddress((void**)&qnh, g_qnh);
    cudaGetSymbolAddress((void**)&qnl, g_qnl);
    cudaGetSymbolAddress((void**)&wmh, g_wh);
    cudaGetSymbolAddress((void**)&wml, g_wl);
    cudaGetSymbolAddress((void**)&wqh, g_wqkv_hi);
    cudaGetSymbolAddress((void**)&wql, g_wqkv_lo);
    cudaGetSymbolAddress((void**)&wf1h, g_wf1_hi);
    cudaGetSymbolAddress((void**)&wf1l, g_wf1_lo);
    cudaGetSymbolAddress((void**)&woh, g_wo_hi);
    cudaGetSymbolAddress((void**)&wol, g_wo_lo);

    cudaFuncSetAttribute(mma_gemm2_kernel, cudaFuncAttributeMaxDynamicSharedMemorySize, MG_SMEM);
    cudaFuncSetAttribute(chunk_kernel, cudaFuncAttributeMaxDynamicSharedMemorySize, CK_SMEM);
    cudaFuncSetAttribute(scan_kernel,  cudaFuncAttributeMaxDynamicSharedMemorySize, SCAN_SMEM);
    cudaFuncSetAttribute(fir64_smem_kernel, cudaFuncAttributeMaxDynamicSharedMemorySize, FIR64_SMEM);

    // ---- prep: bf16 hi/lo conversions ----
    cvt_a_kernel<<<BL_ * H_ / 1024, 256>>>(hs, ahi, alo);
    cvt_wt_kernel<<<dim3(32, 32), 256>>>(Wq, wqh,             wql,             H_, H_);
    cvt_wt_kernel<<<dim3(32, 32), 256>>>(Wk, wqh + 1024 * H_, wql + 1024 * H_, H_, H_);
    cvt_wt_kernel<<<dim3(32, 32), 256>>>(Wv, wqh + 2048 * H_, wql + 2048 * H_, H_, H_);
    cvt_wt_kernel<<<dim3(64, 32), 256>>>(Wf1, wf1h, wf1l, H_, F1_);
    cvt_wt_kernel<<<dim3(32, 32), 256>>>(Wo, woh, wol, H_, H_);

    // ---- fused qkv projection + gate-MLP first layer ----
    mma_gemm2_kernel<<<dim3(NQKV / 128, BL_ / 128), 256, MG_SMEM>>>(
        ahi, alo, wqh, wql, nullptr, qkvp, NQKV, H_, 0);
    mma_gemm2_kernel<<<dim3(F1_ / 128, BL_ / 128), 256, MG_SMEM>>>(
        ahi, alo, wf1h, wf1l, bf1, h1, F1_, H_, 1);

    // short conv + silu
    conv4_silu_kernel<<<BL_ * H_ / 256, 256>>>(qkvp, cq, qs, NQKV, 0);
    conv4_silu_kernel<<<BL_ * H_ / 256, 256>>>(qkvp, ck, ks, NQKV, 1024);
    conv4_silu_kernel<<<BL_ * H_ / 256, 256>>>(qkvp, cv, vs, NQKV, 2048);

    // beta, l2norm + transpose (+ qn bf16 hi/lo)
    beta_kernel<<<BL_, 128>>>(hs, Wb, beta);
    normtr_kernel<<<dim3(BL_, NH_), 256>>>(qs, ks, vs, beta, qn, kn, kb, vb, qnh, qnl);

    // delta rule
    chunk_kernel<<<dim3(BH_, NC_), 256, CK_SMEM>>>(qn, kn, kb, vb, u, wmh, wml, att);
    scan_kernel<<<dim3(BH_, 16), 256, SCAN_SMEM>>>(kn, qnh, qnl, wmh, wml, u, att, delta);

    // FIR branches
    fir7_kernel<<<BL_ * H_ / 256, 256>>>(vs, fsw, shrt);
    fir64_smem_kernel<<<1024, 256, FIR64_SMEM>>>(vs, flw, lng);

    // gate, mix+rmsnorm, output projection
    gate_kernel<<<BL_, 128>>>(h1, Wf2, bf2, fw);
    mix_rms_kernel<<<dim3(BL_, NH_), 256>>>(shrt, lng, delta, vs, fw, rmsw, mhi, mlo);
    mma_gemm2_kernel<<<dim3(H_ / 128, BL_ / 128), 256, MG_SMEM>>>(
        mhi, mlo, woh, wol, nullptr, out, H_, H_, 0);
}

// round 14
// speedup vs baseline: 1.5684x; 1.0194x over previous
#include <cuda_runtime.h>
#include <cuda_bf16.h>
#include <math.h>
#include <stdint.h>

#define B_   2
#define L_   4096
#define H_   1024
#define NH_  4
#define DK_  256
#define DV_  256
#define C_   32
#define NC_  128
#define BL_  8192
#define BH_  8
#define F1_  2048
#define NQKV 3072

// ------------------------- scratch (static device memory; no allocs) -------
__device__ float g_qkvp[BL_*NQKV];
__device__ float g_qs[BL_*H_], g_ks[BL_*H_], g_vs[BL_*H_];
__device__ float g_kn[BL_*H_], g_kb[BL_*H_], g_vb[BL_*H_];
__device__ float g_u [BL_*H_];
__device__ float g_delta[BL_*H_], g_shrt[BL_*H_], g_long[BL_*H_];
__device__ float g_h1[BL_*F1_];
__device__ float g_att[BH_*NC_*C_*C_];
__device__ float g_beta[BL_*NH_];
__device__ float g_fw[BL_*16];
// bf16 hi/lo staging
__device__ __nv_bfloat16 g_ahi[BL_*H_],  g_alo[BL_*H_];
__device__ __nv_bfloat16 g_mhi[BL_*H_],  g_mlo[BL_*H_];
__device__ __nv_bfloat16 g_qnh[BL_*H_],  g_qnl[BL_*H_];
__device__ __nv_bfloat16 g_knh[BL_*H_],  g_knl[BL_*H_];
__device__ __nv_bfloat16 g_kbh[BL_*H_],  g_kbl[BL_*H_];
__device__ __nv_bfloat16 g_wh[BL_*H_],   g_wl[BL_*H_];
__device__ __nv_bfloat16 g_wqkv_hi[NQKV*H_], g_wqkv_lo[NQKV*H_];
__device__ __nv_bfloat16 g_wf1_hi[F1_*H_],   g_wf1_lo[F1_*H_];
__device__ __nv_bfloat16 g_wo_hi[H_*H_],     g_wo_lo[H_*H_];

__device__ __forceinline__ float sigmoidf_(float x) { return 1.f / (1.f + expf(-x)); }
__device__ __forceinline__ float geluf_(float x) {
    return 0.5f * x * (1.f + erff(x * 0.70710678118654752440f));
}
__device__ __forceinline__ uint32_t smem_u32_(const void* p) {
    uint32_t a;
    asm("{ .reg .u64 t; cvta.to.shared.u64 t, %1; cvt.u32.u64 %0, t; }" : "=r"(a) : "l"(p));
    return a;
}
__device__ __forceinline__ uint32_t pack_bf16_hi_(float x, float y) {
    __nv_bfloat162 h = __halves2bfloat162(__float2bfloat16(x), __float2bfloat16(y));
    return *reinterpret_cast<uint32_t*>(&h);
}
__device__ __forceinline__ uint32_t pack_bf16_lo_(float x, float y) {
    float hx = __bfloat162float(__float2bfloat16(x));
    float hy = __bfloat162float(__float2bfloat16(y));
    __nv_bfloat162 l = __halves2bfloat162(__float2bfloat16(x - hx), __float2bfloat16(y - hy));
    return *reinterpret_cast<uint32_t*>(&l);
}
__device__ __forceinline__ void cp16_(uint32_t dst, const void* src) {
    asm volatile("cp.async.ca.shared.global [%0], [%1], 16;" :: "r"(dst), "l"(src));
}

// ------------------------- prep: fp32 -> bf16 hi/lo ------------------------
__global__ __launch_bounds__(256) void cvt_a_kernel(
    const float* __restrict__ x, __nv_bfloat16* __restrict__ hi, __nv_bfloat16* __restrict__ lo)
{
    int i = (blockIdx.x * 256 + threadIdx.x) * 4;
    float4 v = *(const float4*)(x + i);
    uint2 oh, ol;
    oh.x = pack_bf16_hi_(v.x, v.y); oh.y = pack_bf16_hi_(v.z, v.w);
    ol.x = pack_bf16_lo_(v.x, v.y); ol.y = pack_bf16_lo_(v.z, v.w);
    *(uint2*)(hi + i) = oh;
    *(uint2*)(lo + i) = ol;
}

// W [K][N] -> Wt hi/lo [N][K]  (32x32 smem transpose)
__global__ __launch_bounds__(256) void cvt_wt_kernel(
    const float* __restrict__ W, __nv_bfloat16* __restrict__ hi, __nv_bfloat16* __restrict__ lo,
    int K, int N)
{
    __shared__ float tile[32][33];
    int n0 = blockIdx.x * 32, k0 = blockIdx.y * 32;
    int tx = threadIdx.x & 31, ty = threadIdx.x >> 5;
#pragma unroll
    for (int i = 0; i < 4; i++)
        tile[ty + 8 * i][tx] = W[(size_t)(k0 + ty + 8 * i) * N + n0 + tx];
    __syncthreads();
#pragma unroll
    for (int i = 0; i < 4; i++) {
        float v = tile[tx][ty + 8 * i];
        __nv_bfloat16 h = __float2bfloat16(v);
        size_t o = (size_t)(n0 + ty + 8 * i) * K + k0 + tx;
        hi[o] = h;
        lo[o] = __float2bfloat16(v - __bfloat162float(h));
    }
}

// ===================== warp-mma bf16 split-x3 GEMM (ldmatrix) ===============
#define MMA_BF16_(c, a0, a1, a2, a3, b0, b1) \
    asm volatile("mma.sync.aligned.m16n8k16.row.col.f32.bf16.bf16.f32 " \
        "{%0,%1,%2,%3}, {%4,%5,%6,%7}, {%8,%9}, {%0,%1,%2,%3};" \
        : "+f"((c)[0]), "+f"((c)[1]), "+f"((c)[2]), "+f"((c)[3]) \
        : "r"(a0), "r"(a1), "r"(a2), "r"(a3), "r"(b0), "r"(b1))

#define LDSM_X4_(r0, r1, r2, r3, addr) \
    asm volatile("ldmatrix.sync.aligned.m8n8.x4.shared.b16 {%0,%1,%2,%3}, [%4];" \
        : "=r"(r0), "=r"(r1), "=r"(r2), "=r"(r3) : "r"(addr))

#define MG_SMEM 65536

__global__ __launch_bounds__(256, 2) void mma_gemm2_kernel(
    const __nv_bfloat16* __restrict__ Ahi_g, const __nv_bfloat16* __restrict__ Alo_g,
    const __nv_bfloat16* __restrict__ Bhi_g, const __nv_bfloat16* __restrict__ Blo_g,
    const float* __restrict__ bias, float* __restrict__ C,
    int N, int K, int act)
{
    extern __shared__ __align__(16) uint32_t smem_u[];
    const uint32_t smem_b = smem_u32_(smem_u);
    const int tid = threadIdx.x;
    const int wid = tid >> 5, lane = tid & 31;
    const int g = lane >> 2, t = lane & 3;
    const int warp_m = (wid & 3) * 32;
    const int warp_n = (wid >> 2) * 64;
    const int row0 = blockIdx.y * 128, col0 = blockIdx.x * 128;

    const int qq = lane >> 3, rr = lane & 7;
    const int arow = warp_m + ((qq & 1) << 3) + rr;
    const int aqb  = (qq >> 1) & 1;
    const int brow = warp_n + ((qq >> 1) << 3) + rr;
    const int bqb  = qq & 1;

    float acc[2][8][4];
#pragma unroll
    for (int mt = 0; mt < 2; mt++)
#pragma unroll
        for (int nt = 0; nt < 8; nt++)
#pragma unroll
            for (int e = 0; e < 4; e++) acc[mt][nt][e] = 0.f;

    for (int k0 = 0; k0 < K; k0 += 64) {
        __syncthreads();
#pragma unroll
        for (int i = 0; i < 16; i++) {
            const int op = i >> 2;
            int rem = (i & 3) * 256 + tid;
            int row = rem >> 3, c = rem & 7;
            const __nv_bfloat16* gsrc =
                (op == 0) ? Ahi_g + (size_t)(row0 + row) * K + k0 + c * 8 :
                (op == 1) ? Alo_g + (size_t)(row0 + row) * K + k0 + c * 8 :
                (op == 2) ? Bhi_g + (size_t)(col0 + row) * K + k0 + c * 8 :
                            Blo_g + (size_t)(col0 + row) * K + k0 + c * 8;
            uint32_t dst = smem_b + (uint32_t)(((op << 12) + row * 32 + ((c ^ (row & 7)) << 2)) << 2);
            cp16_(dst, gsrc);
        }
        asm volatile("cp.async.commit_group;");
        asm volatile("cp.async.wait_group 0;");
        __syncthreads();

#pragma unroll
        for (int ks = 0; ks < 4; ks++) {
            uint32_t ah[2][4], al[2][4];
#pragma unroll
            for (int mt = 0; mt < 2; mt++) {
                int row = arow + mt * 16;
                int pc = (2 * ks + aqb) ^ (row & 7);
                uint32_t ad = smem_b + (uint32_t)((row * 32 + pc * 4) << 2);
                LDSM_X4_(ah[mt][0], ah[mt][1], ah[mt][2], ah[mt][3], ad);
                LDSM_X4_(al[mt][0], al[mt][1], al[mt][2], al[mt][3], ad + 16384);
            }
#pragma unroll
            for (int p = 0; p < 4; p++) {
                int n = brow + p * 16;
                int pc = (2 * ks + bqb) ^ (n & 7);
                uint32_t bd = smem_b + (uint32_t)(((8192 + n * 32 + pc * 4)) << 2);
                uint32_t bh0, bh1, bh2, bh3, bl0, bl1, bl2, bl3;
                LDSM_X4_(bh0, bh1, bh2, bh3, bd);
                LDSM_X4_(bl0, bl1, bl2, bl3, bd + 16384);
#pragma unroll
                for (int mt = 0; mt < 2; mt++) {
                    MMA_BF16_(acc[mt][2*p],   ah[mt][0], ah[mt][1], ah[mt][2], ah[mt][3], bh0, bh1);
                    MMA_BF16_(acc[mt][2*p],   ah[mt][0], ah[mt][1], ah[mt][2], ah[mt][3], bl0, bl1);
                    MMA_BF16_(acc[mt][2*p],   al[mt][0], al[mt][1], al[mt][2], al[mt][3], bh0, bh1);
                    MMA_BF16_(acc[mt][2*p+1], ah[mt][0], ah[mt][1], ah[mt][2], ah[mt][3], bh2, bh3);
                    MMA_BF16_(acc[mt][2*p+1], ah[mt][0], ah[mt][1], ah[mt][2], ah[mt][3], bl2, bl3);
                    MMA_BF16_(acc[mt][2*p+1], al[mt][0], al[mt][1], al[mt][2], al[mt][3], bh2, bh3);
                }
            }
        }
    }

#pragma unroll
    for (int mt = 0; mt < 2; mt++) {
        int r0g = row0 + warp_m + mt * 16 + g;
#pragma unroll
        for (int nt = 0; nt < 8; nt++) {
            int c = col0 + warp_n + nt * 8 + 2 * t;
            float2 v0, v1;
            v0.x = acc[mt][nt][0]; v0.y = acc[mt][nt][1];
            v1.x = acc[mt][nt][2]; v1.y = acc[mt][nt][3];
            if (act == 1) {
                float b0 = bias[c], b1 = bias[c + 1];
                v0.x = geluf_(v0.x + b0); v0.y = geluf_(v0.y + b1);
                v1.x = geluf_(v1.x + b0); v1.y = geluf_(v1.y + b1);
            }
            *(float2*)(C + (size_t)r0g * N + c) = v0;
            *(float2*)(C + (size_t)(r0g + 8) * N + c) = v1;
        }
    }
}

// ------------------------- short causal depthwise conv (K=4) + silu ---------
__global__ __launch_bounds__(256) void conv4_silu_kernel(
    const float* __restrict__ x, const float* __restrict__ f, float* __restrict__ y,
    int xstride, int xoff)
{
    int idx = blockIdx.x * 256 + threadIdx.x;
    int c  = idx & (H_ - 1);
    int bl = idx >> 10;
    int l  = bl & (L_ - 1);
    const float* xp = x + (size_t)bl * xstride + xoff + c;
    float4 fv = *(const float4*)(f + c * 4);
    float acc = fv.w * xp[0];
    if (l >= 1) acc += fv.z * xp[-xstride];
    if (l >= 2) acc += fv.y * xp[-2 * xstride];
    if (l >= 3) acc += fv.x * xp[-3 * xstride];
    y[idx] = acc * sigmoidf_(acc);
}

// ------------------------- beta = sigmoid(hs @ Wb) --------------------------
__global__ __launch_bounds__(128) void beta_kernel(
    const float* __restrict__ hs, const float* __restrict__ Wb, float* __restrict__ beta)
{
    int bl = blockIdx.x;
    int wrp = threadIdx.x >> 5, lane = threadIdx.x & 31;
    const float* hp = hs + (size_t)bl * H_;
    float acc = 0.f;
    for (int d = lane; d < H_; d += 32) acc += hp[d] * Wb[d * NH_ + wrp];
#pragma unroll
    for (int o = 16; o; o >>= 1) acc += __shfl_xor_sync(0xffffffffu, acc, o);
    if (lane == 0) beta[bl * NH_ + wrp] = sigmoidf_(acc);
}

// ------------------------- l2norm + beta + transpose -> fp32 + bf16 hi/lo ---
__global__ __launch_bounds__(256) void normtr_kernel(
    const float* __restrict__ qs, const float* __restrict__ ks, const float* __restrict__ vs,
    const float* __restrict__ beta,
    float* __restrict__ kn, float* __restrict__ kb, float* __restrict__ vb,
    __nv_bfloat16* __restrict__ qnh, __nv_bfloat16* __restrict__ qnl,
    __nv_bfloat16* __restrict__ knh, __nv_bfloat16* __restrict__ knl,
    __nv_bfloat16* __restrict__ kbh, __nv_bfloat16* __restrict__ kbl)
{
    int bl = blockIdx.x, h = blockIdx.y, d = threadIdx.x;
    int b = bl >> 12;
    int l = bl & (L_ - 1);
    size_t src = (size_t)bl * H_ + h * DK_ + d;
    float qv = qs[src], kv = ks[src], vv = vs[src];
    float s1 = qv * qv, s2 = kv * kv;
#pragma unroll
    for (int o = 16; o; o >>= 1) {
        s1 += __shfl_xor_sync(0xffffffffu, s1, o);
        s2 += __shfl_xor_sync(0xffffffffu, s2, o);
    }
    __shared__ float r1[8], r2[8];
    __shared__ float inv1, inv2;
    int lane = d & 31, wid = d >> 5;
    if (lane == 0) { r1[wid] = s1; r2[wid] = s2; }
    __syncthreads();
    if (d == 0) {
        float t1 = 0.f, t2 = 0.f;
        for (int i = 0; i < 8; i++) { t1 += r1[i]; t2 += r2[i]; }
        inv1 = rsqrtf(t1);
        inv2 = rsqrtf(t2);
    }
    __syncthreads();
    float bt = beta[bl * NH_ + h];
    size_t dst = (((size_t)b * NH_ + h) * L_ + l) * DK_ + d;
    float knv = kv * inv2;
    float qnv = qv * inv1;
    float kbv = knv * bt;
    kn[dst] = knv;
    kb[dst] = kbv;
    vb[dst] = vv * bt;
    __nv_bfloat16 t0;
    t0 = __float2bfloat16(qnv); qnh[dst] = t0;
    qnl[dst] = __float2bfloat16(qnv - __bfloat162float(t0));
    t0 = __float2bfloat16(knv); knh[dst] = t0;
    knl[dst] = __float2bfloat16(knv - __bfloat162float(t0));
    t0 = __float2bfloat16(kbv); kbh[dst] = t0;
    kbl[dst] = __float2bfloat16(kbv - __bfloat162float(t0));
}

// ------------------------- per-chunk: HMMA A/attn + UT transform, u, w ------
// smem floats: skb[32x257] 0 | sx(vb)[32x257] 8224 | T[32x33] 16448 |
// bf16 word-arrays: knh 17504 | knl 21600 | X0(kbh->qnh) 25696 | X1 29792
#define CK_STRIDE 257
#define CK_SMEM (33888 * 4)
__global__ __launch_bounds__(256) void chunk_kernel(
    const float* __restrict__ kb, const float* __restrict__ vb,
    const __nv_bfloat16* __restrict__ knh_g, const __nv_bfloat16* __restrict__ knl_g,
    const __nv_bfloat16* __restrict__ kbh_g, const __nv_bfloat16* __restrict__ kbl_g,
    const __nv_bfloat16* __restrict__ qnh_g, const __nv_bfloat16* __restrict__ qnl_g,
    float* __restrict__ U, __nv_bfloat16* __restrict__ Wmh, __nv_bfloat16* __restrict__ Wml,
    float* __restrict__ ATT)
{
    extern __shared__ float sm[];
    float* skb = sm;
    float* sx  = sm + 8224;
    float* T   = sm + 16448;
    const uint32_t smem_b = smem_u32_(sm);
    const int bh = blockIdx.x, n = blockIdx.y;
    const int tid = threadIdx.x;
    const int wid = tid >> 5, lane = tid & 31;
    size_t base = ((size_t)bh * L_ + n * C_) * DK_;

    // fp32 fills (kb, vb) at stride 257
    for (int i = tid; i < 2048; i += 256) {
        int r = i >> 6, c4 = (i & 63) << 2;
        float4 b = ((const float4*)(kb + base))[i];
        float4 v = ((const float4*)(vb + base))[i];
        float* pb = skb + r * CK_STRIDE + c4;
        float* pv = sx + r * CK_STRIDE + c4;
        pb[0] = b.x; pb[1] = b.y; pb[2] = b.z; pb[3] = b.w;
        pv[0] = v.x; pv[1] = v.y; pv[2] = v.z; pv[3] = v.w;
    }
    // bf16 tiles via cp.async: knh, knl, kbh, kbl
#pragma unroll
    for (int i = 0; i < 16; i++) {
        const int arr = i >> 2;
        int idx = (i & 3) * 256 + tid;
        int row = idx >> 5, ch = idx & 31;
        const __nv_bfloat16* gp =
            (arr == 0) ? knh_g + base + row * 256 + ch * 8 :
            (arr == 1) ? knl_g + base + row * 256 + ch * 8 :
            (arr == 2) ? kbh_g + base + row * 256 + ch * 8 :
                         kbl_g + base + row * 256 + ch * 8;
        const uint32_t ab = (arr == 0) ? 17504u : (arr == 1) ? 21600u
                          : (arr == 2) ? 25696u : 29792u;
        uint32_t w = ab + (uint32_t)(row * 128 + (((ch & 24) | ((ch & 7) ^ (row & 7))) << 2));
        cp16_(smem_b + w * 4, gp);
    }
    asm volatile("cp.async.commit_group;");
    asm volatile("cp.async.wait_group 0;");
    __syncthreads();

    // ---- HMMA A = kb @ kn^T (each warp: one m16n8 tile, full K=256) --------
    const int m0 = (wid & 1) << 4, n0 = (wid >> 1) << 3;
    const int qq = lane >> 3, rr = lane & 7;
    const int gg = lane >> 2, tt = lane & 3;
    const int arow = m0 + ((qq & 1) << 3) + rr;
    const int aqb = qq >> 1;
    const int brw = n0 + rr;
    {
        float acc[4] = {0.f, 0.f, 0.f, 0.f};
#pragma unroll
        for (int p = 0; p < 8; p++) {
            int bch = 4 * p + qq;
            uint32_t bw = 17504u + (uint32_t)(brw * 128 + (((bch & 24) | ((bch & 7) ^ (brw & 7))) << 2));
            uint32_t b0, b1, b2, b3, c0, c1, c2, c3;
            LDSM_X4_(b0, b1, b2, b3, smem_b + bw * 4);
            LDSM_X4_(c0, c1, c2, c3, smem_b + (bw + 4096u) * 4);
#pragma unroll
            for (int s = 0; s < 2; s++) {
                int ach = 2 * (2 * p + s) + aqb;
                uint32_t aw = 25696u + (uint32_t)(arow * 128 + (((ach & 24) | ((ach & 7) ^ (arow & 7))) << 2));
                uint32_t ah0, ah1, ah2, ah3, al0, al1, al2, al3;
                LDSM_X4_(ah0, ah1, ah2, ah3, smem_b + aw * 4);
                LDSM_X4_(al0, al1, al2, al3, smem_b + (aw + 4096u) * 4);
                uint32_t Bh0 = s ? b2 : b0, Bh1 = s ? b3 : b1;
                uint32_t Bl0 = s ? c2 : c0, Bl1 = s ? c3 : c1;
                MMA_BF16_(acc, ah0, ah1, ah2, ah3, Bh0, Bh1);
                MMA_BF16_(acc, ah0, ah1, ah2, ah3, Bl0, Bl1);
                MMA_BF16_(acc, al0, al1, al2, al3, Bh0, Bh1);
            }
        }
        int i0 = m0 + gg, j0 = n0 + 2 * tt;
        T[i0 * 33 + j0]           = (j0 < i0)         ? -acc[0] : 0.f;
        T[i0 * 33 + j0 + 1]       = (j0 + 1 < i0)     ? -acc[1] : 0.f;
        T[(i0 + 8) * 33 + j0]     = (j0 < i0 + 8)     ? -acc[2] : 0.f;
        T[(i0 + 8) * 33 + j0 + 1] = (j0 + 1 < i0 + 8) ? -acc[3] : 0.f;
    }
    __syncthreads();

    // prefetch qn bf16 into X region (kb tiles dead after A)
#pragma unroll
    for (int i = 0; i < 8; i++) {
        const int arr = i >> 2;
        int idx = (i & 3) * 256 + tid;
        int row = idx >> 5, ch = idx & 31;
        const __nv_bfloat16* gp = (arr ? qnl_g : qnh_g) + base + row * 256 + ch * 8;
        uint32_t w = (arr ? 29792u : 25696u)
                   + (uint32_t)(row * 128 + (((ch & 24) | ((ch & 7) ^ (row & 7))) << 2));
        cp16_(smem_b + w * 4, gp);
    }
    asm volatile("cp.async.commit_group;");

    // forward substitution (warp 0)
    if (tid < 32) {
        int j = tid;
        for (int i = 1; i < 32; i++) {
            float rv = T[i * 33 + j];
            float acc = rv;
            for (int m = 1; m < i; m++)
                acc += __shfl_sync(0xffffffffu, rv, m) * T[m * 33 + j];
            __syncwarp();
            T[i * 33 + j] = acc;
            __syncwarp();
        }
        T[j * 33 + j] = 1.f;
    }
    __syncthreads();

    // u = T @ vb, w = T @ kb
    for (int idx = tid; idx < 8192; idx += 256) {
        int c = idx >> 8, d = idx & 255;
        float au = 0.f, aw = 0.f;
#pragma unroll
        for (int j = 0; j < 32; j++) {
            float t = T[c * 33 + j];
            au += t * sx[j * CK_STRIDE + d];
            aw += t * skb[j * CK_STRIDE + d];
        }
        U[base + idx] = au;
        __nv_bfloat16 hh = __float2bfloat16(aw);
        Wmh[base + idx] = hh;
        Wml[base + idx] = __float2bfloat16(aw - __bfloat162float(hh));
    }

    asm volatile("cp.async.wait_group 0;");
    __syncthreads();

    // ---- HMMA attn = qn @ kn^T (causal) ------------------------------------
    {
        float acc[4] = {0.f, 0.f, 0.f, 0.f};
#pragma unroll
        for (int p = 0; p < 8; p++) {
            int bch = 4 * p + qq;
            uint32_t bw = 17504u + (uint32_t)(brw * 128 + (((bch & 24) | ((bch & 7) ^ (brw & 7))) << 2));
            uint32_t b0, b1, b2, b3, c0, c1, c2, c3;
            LDSM_X4_(b0, b1, b2, b3, smem_b + bw * 4);
            LDSM_X4_(c0, c1, c2, c3, smem_b + (bw + 4096u) * 4);
#pragma unroll
            for (int s = 0; s < 2; s++) {
                int ach = 2 * (2 * p + s) + aqb;
                uint32_t aw = 25696u + (uint32_t)(arow * 128 + (((ach & 24) | ((ach & 7) ^ (arow & 7))) << 2));
                uint32_t ah0, ah1, ah2, ah3, al0, al1, al2, al3;
                LDSM_X4_(ah0, ah1, ah2, ah3, smem_b + aw * 4);
                LDSM_X4_(al0, al1, al2, al3, smem_b + (aw + 4096u) * 4);
                uint32_t Bh0 = s ? b2 : b0, Bh1 = s ? b3 : b1;
                uint32_t Bl0 = s ? c2 : c0, Bl1 = s ? c3 : c1;
                MMA_BF16_(acc, ah0, ah1, ah2, ah3, Bh0, Bh1);
                MMA_BF16_(acc, ah0, ah1, ah2, ah3, Bl0, Bl1);
                MMA_BF16_(acc, al0, al1, al2, al3, Bh0, Bh1);
            }
        }
        float* att = ATT + ((size_t)bh * NC_ + n) * 1024;
        int i0 = m0 + gg, j0 = n0 + 2 * tt;
        att[i0 * 32 + j0]           = (j0 <= i0)         ? acc[0] : 0.f;
        att[i0 * 32 + j0 + 1]       = (j0 + 1 <= i0)     ? acc[1] : 0.f;
        att[(i0 + 8) * 32 + j0]     = (j0 <= i0 + 8)     ? acc[2] : 0.f;
        att[(i0 + 8) * 32 + j0 + 1] = (j0 + 1 <= i0 + 8) ? acc[3] : 0.f;
    }
}

// ------------------------- sequential chunk scan: HMMA wS/qS ----------------
#define SCAN_SMEM (36352 * 4)
__global__ __launch_bounds__(256) void scan_kernel(
    const float* __restrict__ kn,
    const __nv_bfloat16* __restrict__ qh_g, const __nv_bfloat16* __restrict__ ql_g,
    const __nv_bfloat16* __restrict__ wh_g, const __nv_bfloat16* __restrict__ wl_g,
    const float* __restrict__ U, const float* __restrict__ ATT, float* __restrict__ OUT)
{
    extern __shared__ float sm[];
    float* S   = sm;             // [256][16]
    float* sk  = sm + 4096;      // [32][260]
    uint32_t* sbh = (uint32_t*)(sm + 28800);
    uint32_t* sbl = (uint32_t*)(sm + 30912);
    float* su  = sm + 33024;     // [32][16]
    float* sut = sm + 33536;     // [32][16]
    float* sat = sm + 34048;     // [32][36]
    float* swS = sm + 35200;     // [32][18]
    float* sqS = sm + 35776;     // [32][18]
    const uint32_t smem_b = smem_u32_(sm);
    const int bh = blockIdx.x, tile = blockIdx.y;
    const int tid = threadIdx.x;
    const int wid = tid >> 5, lane = tid & 31;
    const int b = bh >> 2, h = bh & 3;
    const int g = tid >> 3, eg = tid & 7, eg2 = eg * 2;
    const int pr = wid & 1, mt = (wid >> 1) & 1, nt = wid >> 2;
    const int qq = lane >> 3, rr = lane & 7;
    const int arow = mt * 16 + ((qq & 1) << 3) + rr;
    const int aqb  = qq >> 1;
    const int brow = ((qq >> 1) << 3) + rr;
    const int bqb  = qq & 1;
    const int gg = lane >> 2, tt = lane & 3;
    const uint32_t abaseW = 12416u + (pr ? 8192u : 0u);
    const int ce = tid & 15, cd0 = (tid >> 4) * 16;

    for (int i = tid; i < 4096; i += 256) S[i] = 0.f;

    for (int n = 0; n < NC_; n++) {
        __syncthreads();
        size_t base = ((size_t)bh * L_ + n * C_) * 256;
        for (int i = tid; i < 2048; i += 256) {
            int c = i >> 6, o = (i & 63) * 4;
            *(float4*)(sk + c * 260 + o) = ((const float4*)(kn + base))[i];
        }
#pragma unroll
        for (int i = 0; i < 16; i++) {
            const int arr = i >> 2, r = i & 3;
            int row = r * 8 + wid;
            int ch  = lane;
            const __nv_bfloat16* gp =
                (arr == 0) ? wh_g + base + row * 256 + ch * 8 :
                (arr == 1) ? wl_g + base + row * 256 + ch * 8 :
                (arr == 2) ? qh_g + base + row * 256 + ch * 8 :
                             ql_g + base + row * 256 + ch * 8;
            uint32_t w = 12416u + (uint32_t)(arr * 4096 + row * 128
                         + (((ch & 24) | ((ch & 7) ^ (row & 7))) << 2));
            cp16_(smem_b + w * 4, gp);
        }
        asm volatile("cp.async.commit_group;");
        if (tid < 128) {
            int c = tid >> 2, e4 = tid & 3;
            ((float4*)su)[tid] = *(const float4*)(U + base + c * 256 + tile * 16 + e4 * 4);
        }
        {
            int c = tid >> 3, j4 = (tid & 7) * 4;
            *(float4*)(sat + c * 36 + j4) =
                ((const float4*)(ATT + ((size_t)bh * NC_ + n) * 1024))[tid];
        }
#pragma unroll
        for (int i2 = 0; i2 < 8; i2++) {
            int d = cd0 + i2 * 2;
            float x = S[d * 16 + ce], y = S[(d + 1) * 16 + ce];
            sbh[ce * 132 + (d >> 1)] = pack_bf16_hi_(x, y);
            sbl[ce * 132 + (d >> 1)] = pack_bf16_lo_(x, y);
        }
        asm volatile("cp.async.wait_group 0;");
        __syncthreads();

        float acc[4] = {0.f, 0.f, 0.f, 0.f};
#pragma unroll
        for (int ks = 0; ks < 16; ks++) {
            int ch = 2 * ks + aqb;
            uint32_t aw_ = abaseW + (uint32_t)(arow * 128
                          + (((ch & 24) | ((ch & 7) ^ (arow & 7))) << 2));
            uint32_t ah0, ah1, ah2, ah3, al0, al1, al2, al3;
            LDSM_X4_(ah0, ah1, ah2, ah3, smem_b + aw_ * 4);
            LDSM_X4_(al0, al1, al2, al3, smem_b + (aw_ + 4096u) * 4);
            uint32_t bw_ = 28800u + (uint32_t)(brow * 132 + (2 * ks + bqb) * 4);
            uint32_t bh0, bh1, bh2, bh3, bl0, bl1, bl2, bl3;
            LDSM_X4_(bh0, bh1, bh2, bh3, smem_b + bw_ * 4);
            LDSM_X4_(bl0, bl1, bl2, bl3, smem_b + (bw_ + 2112u) * 4);
            uint32_t B0h = nt ? bh2 : bh0, B1h = nt ? bh3 : bh1;
            uint32_t B0l = nt ? bl2 : bl0, B1l = nt ? bl3 : bl1;
            MMA_BF16_(acc, ah0, ah1, ah2, ah3, B0h, B1h);
            MMA_BF16_(acc, ah0, ah1, ah2, ah3, B0l, B1l);
            MMA_BF16_(acc, al0, al1, al2, al3, B0h, B1h);
        }
        {
            float* dst = pr ? sqS : swS;
            int c0 = mt * 16 + gg, e0 = nt * 8 + 2 * tt;
            *(float2*)(dst + c0 * 18 + e0) = make_float2(acc[0], acc[1]);
            *(float2*)(dst + (c0 + 8) * 18 + e0) = make_float2(acc[2], acc[3]);
        }
        __syncthreads();

        float2 uv = *(float2*)(su + g * 16 + eg2);
        float2 wv = *(float2*)(swS + g * 18 + eg2);
        float2 ut = make_float2(uv.x - wv.x, uv.y - wv.y);
        *(float2*)(sut + g * 16 + eg2) = ut;
        float2 aq = *(float2*)(sqS + g * 18 + eg2);
        __syncthreads();

        const float* ar = sat + g * 36;
#pragma unroll
        for (int j = 0; j < 32; j += 4) {
            float4 a4 = *(const float4*)(ar + j);
            float2 u0 = *(float2*)(sut + (j + 0) * 16 + eg2);
            float2 u1 = *(float2*)(sut + (j + 1) * 16 + eg2);
            float2 u2 = *(float2*)(sut + (j + 2) * 16 + eg2);
            float2 u3 = *(float2*)(sut + (j + 3) * 16 + eg2);
            aq.x += a4.x * u0.x + a4.y * u1.x + a4.z * u2.x + a4.w * u3.x;
            aq.y += a4.x * u0.y + a4.y * u1.y + a4.z * u2.y + a4.w * u3.y;
        }
        *(float2*)(OUT + (size_t)(b * L_ + n * C_ + g) * H_ + h * 256 + tile * 16 + eg2) = aq;

        float2 accS[8];
#pragma unroll
        for (int i = 0; i < 8; i++) accS[i] = make_float2(0.f, 0.f);
        for (int c2 = 0; c2 < 32; c2++) {
            float2 u2 = *(float2*)(sut + c2 * 16 + eg2);
            const float* kr = sk + c2 * 260 + g * 8;
            float4 k0 = *(const float4*)(kr);
            float4 k1 = *(const float4*)(kr + 4);
            accS[0].x += k0.x * u2.x; accS[0].y += k0.x * u2.y;
            accS[1].x += k0.y * u2.x; accS[1].y += k0.y * u2.y;
            accS[2].x += k0.z * u2.x; accS[2].y += k0.z * u2.y;
            accS[3].x += k0.w * u2.x; accS[3].y += k0.w * u2.y;
            accS[4].x += k1.x * u2.x; accS[4].y += k1.x * u2.y;
            accS[5].x += k1.y * u2.x; accS[5].y += k1.y * u2.y;
            accS[6].x += k1.z * u2.x; accS[6].y += k1.z * u2.y;
            accS[7].x += k1.w * u2.x; accS[7].y += k1.w * u2.y;
        }
#pragma unroll
        for (int i = 0; i < 8; i++) {
            float2 s2 = *(float2*)(S + (g * 8 + i) * 16 + eg2);
            s2.x += accS[i].x; s2.y += accS[i].y;
            *(float2*)(S + (g * 8 + i) * 16 + eg2) = s2;
        }
    }
}

// ------------------------- FIR K=7 (unrolled) -------------------------------
__global__ __launch_bounds__(256) void fir7_kernel(
    const float* __restrict__ x, const float* __restrict__ f, float* __restrict__ y)
{
    int idx = blockIdx.x * 256 + threadIdx.x;
    int c  = idx & (H_ - 1);
    int bl = idx >> 10;
    int l  = bl & (L_ - 1);
    const float* fp = f + (size_t)c * 7;
    float acc = 0.f;
#pragma unroll
    for (int t = 0; t < 7; t++) {
        int dl = t - 6;
        if (l + dl >= 0) acc += x[idx + dl * H_] * fp[t];
    }
    y[idx] = acc;
}

// ------------------------- FIR K=64: smem tile + register sliding window ----
#define FIR64_SMEM ((127 * 128 + 64 * 129) * 4)
__global__ __launch_bounds__(256) void fir64_smem_kernel(
    const float* __restrict__ x, const float* __restrict__ f, float* __restrict__ y)
{
    extern __shared__ float fsm[];
    float* sx = fsm;
    float* sf = fsm + 127 * 128;
    const int ctile = blockIdx.x & 7;
    const int ltile = blockIdx.x >> 3;
    const int l0 = ltile * 64;
    const int lb = l0 & (L_ - 1);
    const int c0 = ctile * 128;
    const int tid = threadIdx.x;

    for (int i = tid; i < 64 * 128; i += 256) {
        int c = i >> 6, t = i & 63;
        sf[t * 129 + c] = f[(size_t)(c0 + c) * 64 + t];
    }
    for (int i = tid; i < 127 * 128; i += 256) {
        int j = i >> 7, c = i & 127;
        int lrel = lb + j - 63;
        float v = 0.f;
        if (lrel >= 0)
            v = x[(size_t)(l0 + j - 63) * H_ + c0 + c];
        sx[j * 128 + c] = v;
    }
    __syncthreads();

    const int c = tid & 127;
    const int lg = (tid >> 7) * 32;
    float acc[32], win[32];
#pragma unroll
    for (int i = 0; i < 32; i++) acc[i] = 0.f;
#pragma unroll
    for (int i = 0; i < 32; i++) win[i] = sx[(lg + i) * 128 + c];
#pragma unroll
    for (int t = 0; t < 64; t++) {
        float ft = sf[t * 129 + c];
#pragma unroll
        for (int i = 0; i < 32; i++) acc[i] += ft * win[i];
        if (t < 63) {
#pragma unroll
            for (int i = 0; i < 31; i++) win[i] = win[i + 1];
            win[31] = sx[(lg + t + 32) * 128 + c];
        }
    }
#pragma unroll
    for (int i = 0; i < 32; i++)
        y[(size_t)(l0 + lg + i) * H_ + c0 + c] = acc[i];
}

// ------------------------- fusion gate: h1 @ Wf2 + bf2 -> softmax4 ----------
__global__ __launch_bounds__(128) void gate_kernel(
    const float* __restrict__ h1, const float* __restrict__ Wf2,
    const float* __restrict__ bf2, float* __restrict__ fw)
{
    int bl = blockIdx.x, tid = threadIdx.x;
    float acc[16];
#pragma unroll
    for (int j = 0; j < 16; j++) acc[j] = 0.f;
    const float* hp = h1 + (size_t)bl * F1_;
    for (int d = tid; d < F1_; d += 128) {
        float hv = hp[d];
        const float4* w4 = (const float4*)(Wf2 + d * 16);
        float4 w0 = w4[0], w1 = w4[1], w2 = w4[2], w3 = w4[3];
        acc[0] += hv * w0.x; acc[1] += hv * w0.y; acc[2] += hv * w0.z; acc[3] += hv * w0.w;
        acc[4] += hv * w1.x; acc[5] += hv * w1.y; acc[6] += hv * w1.z; acc[7] += hv * w1.w;
        acc[8] += hv * w2.x; acc[9] += hv * w2.y; acc[10] += hv * w2.z; acc[11] += hv * w2.w;
        acc[12] += hv * w3.x; acc[13] += hv * w3.y; acc[14] += hv * w3.z; acc[15] += hv * w3.w;
    }
    __shared__ float red[16][129];
    __shared__ float logit[16];
#pragma unroll
    for (int j = 0; j < 16; j++) red[j][tid] = acc[j];
    __syncthreads();
    if (tid < 16) {
        float s = bf2[tid];
        for (int i = 0; i < 128; i++) s += red[tid][i];
        logit[tid] = s;
    }
    __syncthreads();
    if (tid < 4) {
        float l0 = logit[tid * 4], l1 = logit[tid * 4 + 1];
        float l2 = logit[tid * 4 + 2], l3 = logit[tid * 4 + 3];
        float m = fmaxf(fmaxf(l0, l1), fmaxf(l2, l3));
        float e0 = expf(l0 - m), e1 = expf(l1 - m), e2 = expf(l2 - m), e3 = expf(l3 - m);
        float inv = 1.f / (e0 + e1 + e2 + e3);
        float* o = fw + (size_t)bl * 16 + tid * 4;
        o[0] = e0 * inv; o[1] = e1 * inv; o[2] = e2 * inv; o[3] = e3 * inv;
    }
}

// ------------------------- branch mix + per-head rmsnorm -> bf16 hi/lo ------
__global__ __launch_bounds__(256) void mix_rms_kernel(
    const float* __restrict__ br_s, const float* __restrict__ br_l,
    const float* __restrict__ br_d, const float* __restrict__ br_v,
    const float* __restrict__ fw, const float* __restrict__ rmsw,
    __nv_bfloat16* __restrict__ Mhi, __nv_bfloat16* __restrict__ Mlo)
{
    int bl = blockIdx.x, h = blockIdx.y, d = threadIdx.x;
    size_t i = (size_t)bl * H_ + h * 256 + d;
    const float* f = fw + (size_t)bl * 16 + h * 4;
    float val = f[0] * br_s[i] + f[1] * br_l[i] + f[2] * br_d[i] + f[3] * br_v[i];
    float ss = val * val;
#pragma unroll
    for (int o = 16; o; o >>= 1) ss += __shfl_xor_sync(0xffffffffu, ss, o);
    __shared__ float red[8];
    __shared__ float scale;
    if ((d & 31) == 0) red[d >> 5] = ss;
    __syncthreads();
    if (d == 0) {
        float t = 0.f;
        for (int k = 0; k < 8; k++) t += red[k];
        scale = rsqrtf(t * (1.f / 256.f) + 1e-5f);
    }
    __syncthreads();
    float o = val * scale * rmsw[d];
    __nv_bfloat16 hb = __float2bfloat16(o);
    Mhi[i] = hb;
    Mlo[i] = __float2bfloat16(o - __bfloat162float(hb));
}

// ------------------------- launcher ----------------------------------------
extern "C" void kernel_launch(void* const* d_in, const int* in_sizes, int n_in,
                              void* d_out, int out_size)
{
    const float* hs   = (const float*)d_in[0];
    const float* Wq   = (const float*)d_in[1];
    const float* Wk   = (const float*)d_in[2];
    const float* Wv   = (const float*)d_in[3];
    const float* Wb   = (const float*)d_in[4];
    const float* cq   = (const float*)d_in[5];
    const float* ck   = (const float*)d_in[6];
    const float* cv   = (const float*)d_in[7];
    const float* fsw  = (const float*)d_in[8];
    const float* flw  = (const float*)d_in[9];
    const float* Wf1  = (const float*)d_in[10];
    const float* bf1  = (const float*)d_in[11];
    const float* Wf2  = (const float*)d_in[12];
    const float* bf2  = (const float*)d_in[13];
    const float* rmsw = (const float*)d_in[14];
    const float* Wo   = (const float*)d_in[15];
    float* out = (float*)d_out;

    float *qkvp, *qs, *ks, *vs, *kn, *kb, *vb;
    float *u, *delta, *shrt, *lng, *h1, *att, *beta, *fw;
    __nv_bfloat16 *ahi, *alo, *mhi, *mlo, *wqh, *wql, *wf1h, *wf1l, *woh, *wol;
    __nv_bfloat16 *qnh, *qnl, *knh, *knl, *kbh, *kbl, *wmh, *wml;
    cudaGetSymbolAddress((void**)&qkvp, g_qkvp);
    cudaGetSymbolAddress((void**)&qs, g_qs);
    cudaGetSymbolAddress((void**)&ks, g_ks);
    cudaGetSymbolAddress((void**)&vs, g_vs);
    cudaGetSymbolAddress((void**)&kn, g_kn);
    cudaGetSymbolAddress((void**)&kb, g_kb);
    cudaGetSymbolAddress((void**)&vb, g_vb);
    cudaGetSymbolAddress((void**)&u, g_u);
    cudaGetSymbolAddress((void**)&delta, g_delta);
    cudaGetSymbolAddress((void**)&shrt, g_shrt);
    cudaGetSymbolAddress((void**)&lng, g_long);
    cudaGetSymbolAddress((void**)&h1, g_h1);
    cudaGetSymbolAddress((void**)&att, g_att);
    cudaGetSymbolAddress((void**)&beta, g_beta);
    cudaGetSymbolAddress((void**)&fw, g_fw);
    cudaGetSymbolAddress((void**)&ahi, g_ahi);
    cudaGetSymbolAddress((void**)&alo, g_alo);
    cudaGetSymbolAddress((void**)&mhi, g_mhi);
    cudaGetSymbolAddress((void**)&mlo, g_mlo);
    cudaGetSymbolAddress((void**)&qnh, g_qnh);
    cudaGetSymbolAddress((void**)&qnl, g_qnl);
    cudaGetSymbolAddress((void**)&knh, g_knh);
    cudaGetSymbolAddress((void**)&knl, g_knl);
    cudaGetSymbolAddress((void**)&kbh, g_kbh);
    cudaGetSymbolAddress((void**)&kbl, g_kbl);
    cudaGetSymbolAddress((void**)&wmh, g_wh);
    cudaGetSymbolAddress((void**)&wml, g_wl);
    cudaGetSymbolAddress((void**)&wqh, g_wqkv_hi);
    cudaGetSymbolAddress((void**)&wql, g_wqkv_lo);
    cudaGetSymbolAddress((void**)&wf1h, g_wf1_hi);
    cudaGetSymbolAddress((void**)&wf1l, g_wf1_lo);
    cudaGetSymbolAddress((void**)&woh, g_wo_hi);
    cudaGetSymbolAddress((void**)&wol, g_wo_lo);

    cudaFuncSetAttribute(mma_gemm2_kernel, cudaFuncAttributeMaxDynamicSharedMemorySize, MG_SMEM);
    cudaFuncSetAttribute(chunk_kernel, cudaFuncAttributeMaxDynamicSharedMemorySize, CK_SMEM);
    cudaFuncSetAttribute(scan_kernel,  cudaFuncAttributeMaxDynamicSharedMemorySize, SCAN_SMEM);
    cudaFuncSetAttribute(fir64_smem_kernel, cudaFuncAttributeMaxDynamicSharedMemorySize, FIR64_SMEM);

    // ---- prep: bf16 hi/lo conversions ----
    cvt_a_kernel<<<BL_ * H_ / 1024, 256>>>(hs, ahi, alo);
    cvt_wt_kernel<<<dim3(32, 32), 256>>>(Wq, wqh,             wql,             H_, H_);
    cvt_wt_kernel<<<dim3(32, 32), 256>>>(Wk, wqh + 1024 * H_, wql + 1024 * H_, H_, H_);
    cvt_wt_kernel<<<dim3(32, 32), 256>>>(Wv, wqh + 2048 * H_, wql + 2048 * H_, H_, H_);
    cvt_wt_kernel<<<dim3(64, 32), 256>>>(Wf1, wf1h, wf1l, H_, F1_);
    cvt_wt_kernel<<<dim3(32, 32), 256>>>(Wo, woh, wol, H_, H_);

    // ---- fused qkv projection + gate-MLP first layer ----
    mma_gemm2_kernel<<<dim3(NQKV / 128, BL_ / 128), 256, MG_SMEM>>>(
        ahi, alo, wqh, wql, nullptr, qkvp, NQKV, H_, 0);
    mma_gemm2_kernel<<<dim3(F1_ / 128, BL_ / 128), 256, MG_SMEM>>>(
        ahi, alo, wf1h, wf1l, bf1, h1, F1_, H_, 1);

    // short conv + silu
    conv4_silu_kernel<<<BL_ * H_ / 256, 256>>>(qkvp, cq, qs, NQKV, 0);
    conv4_silu_kernel<<<BL_ * H_ / 256, 256>>>(qkvp, ck, ks, NQKV, 1024);
    conv4_silu_kernel<<<BL_ * H_ / 256, 256>>>(qkvp, cv, vs, NQKV, 2048);

    // beta, l2norm + transpose (fp32 + bf16 hi/lo)
    beta_kernel<<<BL_, 128>>>(hs, Wb, beta);
    normtr_kernel<<<dim3(BL_, NH_), 256>>>(qs, ks, vs, beta, kn, kb, vb,
                                           qnh, qnl, knh, knl, kbh, kbl);

    // delta rule
    chunk_kernel<<<dim3(BH_, NC_), 256, CK_SMEM>>>(
        kb, vb, knh, knl, kbh, kbl, qnh, qnl, u, wmh, wml, att);
    scan_kernel<<<dim3(BH_, 16), 256, SCAN_SMEM>>>(kn, qnh, qnl, wmh, wml, u, att, delta);

    // FIR branches
    fir7_kernel<<<BL_ * H_ / 256, 256>>>(vs, fsw, shrt);
    fir64_smem_kernel<<<1024, 256, FIR64_SMEM>>>(vs, flw, lng);

    // gate, mix+rmsnorm, output projection
    gate_kernel<<<BL_, 128>>>(h1, Wf2, bf2, fw);
    mix_rms_kernel<<<dim3(BL_, NH_), 256>>>(shrt, lng, delta, vs, fw, rmsw, mhi, mlo);
    mma_gemm2_kernel<<<dim3(H_ / 128, BL_ / 128), 256, MG_SMEM>>>(
        mhi, mlo, woh, wol, nullptr, out, H_, H_, 0);
}

// round 15
// speedup vs baseline: 1.6106x; 1.0269x over previous
#include <cuda_runtime.h>
#include <cuda_bf16.h>
#include <math.h>
#include <stdint.h>

#define B_   2
#define L_   4096
#define H_   1024
#define NH_  4
#define DK_  256
#define DV_  256
#define C_   32
#define NC_  128
#define BL_  8192
#define BH_  8
#define F1_  2048
#define NQKV 3072

// ------------------------- scratch (static device memory; no allocs) -------
__device__ float g_qkvp[BL_*NQKV];
__device__ float g_qs[BL_*H_], g_ks[BL_*H_], g_vs[BL_*H_];
__device__ float g_kn[BL_*H_], g_kb[BL_*H_], g_vb[BL_*H_];
__device__ float g_u [BL_*H_];
__device__ float g_delta[BL_*H_], g_shrt[BL_*H_], g_long[BL_*H_];
__device__ float g_lgp[16*BL_*16];
__device__ float g_att[BH_*NC_*C_*C_];
__device__ float g_beta[BL_*NH_];
__device__ float g_fw[BL_*16];
// bf16 hi/lo staging
__device__ __nv_bfloat16 g_ahi[BL_*H_],  g_alo[BL_*H_];
__device__ __nv_bfloat16 g_mhi[BL_*H_],  g_mlo[BL_*H_];
__device__ __nv_bfloat16 g_qnh[BL_*H_],  g_qnl[BL_*H_];
__device__ __nv_bfloat16 g_knh[BL_*H_],  g_knl[BL_*H_];
__device__ __nv_bfloat16 g_kbh[BL_*H_],  g_kbl[BL_*H_];
__device__ __nv_bfloat16 g_wh[BL_*H_],   g_wl[BL_*H_];
__device__ __nv_bfloat16 g_wqkv_hi[NQKV*H_], g_wqkv_lo[NQKV*H_];
__device__ __nv_bfloat16 g_wf1_hi[F1_*H_],   g_wf1_lo[F1_*H_];
__device__ __nv_bfloat16 g_wo_hi[H_*H_],     g_wo_lo[H_*H_];

__device__ __forceinline__ float sigmoidf_(float x) { return 1.f / (1.f + expf(-x)); }
__device__ __forceinline__ float geluf_(float x) {
    return 0.5f * x * (1.f + erff(x * 0.70710678118654752440f));
}
__device__ __forceinline__ uint32_t smem_u32_(const void* p) {
    uint32_t a;
    asm("{ .reg .u64 t; cvta.to.shared.u64 t, %1; cvt.u32.u64 %0, t; }" : "=r"(a) : "l"(p));
    return a;
}
__device__ __forceinline__ uint32_t pack_bf16_hi_(float x, float y) {
    __nv_bfloat162 h = __halves2bfloat162(__float2bfloat16(x), __float2bfloat16(y));
    return *reinterpret_cast<uint32_t*>(&h);
}
__device__ __forceinline__ uint32_t pack_bf16_lo_(float x, float y) {
    float hx = __bfloat162float(__float2bfloat16(x));
    float hy = __bfloat162float(__float2bfloat16(y));
    __nv_bfloat162 l = __halves2bfloat162(__float2bfloat16(x - hx), __float2bfloat16(y - hy));
    return *reinterpret_cast<uint32_t*>(&l);
}
__device__ __forceinline__ void cp16_(uint32_t dst, const void* src) {
    asm volatile("cp.async.ca.shared.global [%0], [%1], 16;" :: "r"(dst), "l"(src));
}

// ------------------------- prep: fp32 -> bf16 hi/lo ------------------------
__global__ __launch_bounds__(256) void cvt_a_kernel(
    const float* __restrict__ x, __nv_bfloat16* __restrict__ hi, __nv_bfloat16* __restrict__ lo)
{
    int i = (blockIdx.x * 256 + threadIdx.x) * 4;
    float4 v = *(const float4*)(x + i);
    uint2 oh, ol;
    oh.x = pack_bf16_hi_(v.x, v.y); oh.y = pack_bf16_hi_(v.z, v.w);
    ol.x = pack_bf16_lo_(v.x, v.y); ol.y = pack_bf16_lo_(v.z, v.w);
    *(uint2*)(hi + i) = oh;
    *(uint2*)(lo + i) = ol;
}

// W [K][N] -> Wt hi/lo [N][K]  (32x32 smem transpose)
__global__ __launch_bounds__(256) void cvt_wt_kernel(
    const float* __restrict__ W, __nv_bfloat16* __restrict__ hi, __nv_bfloat16* __restrict__ lo,
    int K, int N)
{
    __shared__ float tile[32][33];
    int n0 = blockIdx.x * 32, k0 = blockIdx.y * 32;
    int tx = threadIdx.x & 31, ty = threadIdx.x >> 5;
#pragma unroll
    for (int i = 0; i < 4; i++)
        tile[ty + 8 * i][tx] = W[(size_t)(k0 + ty + 8 * i) * N + n0 + tx];
    __syncthreads();
#pragma unroll
    for (int i = 0; i < 4; i++) {
        float v = tile[tx][ty + 8 * i];
        __nv_bfloat16 h = __float2bfloat16(v);
        size_t o = (size_t)(n0 + ty + 8 * i) * K + k0 + tx;
        hi[o] = h;
        lo[o] = __float2bfloat16(v - __bfloat162float(h));
    }
}

// ===================== warp-mma bf16 split-x3 GEMM (ldmatrix) ===============
// act==0: plain store. act==1: gelu(+bias) store. act==2: gate fusion —
// gelu(+bias) tile -> partial logits vs Wf2 slice -> Lgp[tile][row][16],
// no C store (h1 never materialized).
#define MMA_BF16_(c, a0, a1, a2, a3, b0, b1) \
    asm volatile("mma.sync.aligned.m16n8k16.row.col.f32.bf16.bf16.f32 " \
        "{%0,%1,%2,%3}, {%4,%5,%6,%7}, {%8,%9}, {%0,%1,%2,%3};" \
        : "+f"((c)[0]), "+f"((c)[1]), "+f"((c)[2]), "+f"((c)[3]) \
        : "r"(a0), "r"(a1), "r"(a2), "r"(a3), "r"(b0), "r"(b1))

#define LDSM_X4_(r0, r1, r2, r3, addr) \
    asm volatile("ldmatrix.sync.aligned.m8n8.x4.shared.b16 {%0,%1,%2,%3}, [%4];" \
        : "=r"(r0), "=r"(r1), "=r"(r2), "=r"(r3) : "r"(addr))

#define MG_SMEM 65536

__global__ __launch_bounds__(256, 2) void mma_gemm2_kernel(
    const __nv_bfloat16* __restrict__ Ahi_g, const __nv_bfloat16* __restrict__ Alo_g,
    const __nv_bfloat16* __restrict__ Bhi_g, const __nv_bfloat16* __restrict__ Blo_g,
    const float* __restrict__ bias, float* __restrict__ C,
    const float* __restrict__ Wf2g, float* __restrict__ Lgp,
    int N, int K, int act)
{
    extern __shared__ __align__(16) uint32_t smem_u[];
    const uint32_t smem_b = smem_u32_(smem_u);
    const int tid = threadIdx.x;
    const int wid = tid >> 5, lane = tid & 31;
    const int g = lane >> 2, t = lane & 3;
    const int warp_m = (wid & 3) * 32;
    const int warp_n = (wid >> 2) * 64;
    const int row0 = blockIdx.y * 128, col0 = blockIdx.x * 128;

    const int qq = lane >> 3, rr = lane & 7;
    const int arow = warp_m + ((qq & 1) << 3) + rr;
    const int aqb  = (qq >> 1) & 1;
    const int brow = warp_n + ((qq >> 1) << 3) + rr;
    const int bqb  = qq & 1;

    float acc[2][8][4];
#pragma unroll
    for (int mt = 0; mt < 2; mt++)
#pragma unroll
        for (int nt = 0; nt < 8; nt++)
#pragma unroll
            for (int e = 0; e < 4; e++) acc[mt][nt][e] = 0.f;

    for (int k0 = 0; k0 < K; k0 += 64) {
        __syncthreads();
#pragma unroll
        for (int i = 0; i < 16; i++) {
            const int op = i >> 2;
            int rem = (i & 3) * 256 + tid;
            int row = rem >> 3, c = rem & 7;
            const __nv_bfloat16* gsrc =
                (op == 0) ? Ahi_g + (size_t)(row0 + row) * K + k0 + c * 8 :
                (op == 1) ? Alo_g + (size_t)(row0 + row) * K + k0 + c * 8 :
                (op == 2) ? Bhi_g + (size_t)(col0 + row) * K + k0 + c * 8 :
                            Blo_g + (size_t)(col0 + row) * K + k0 + c * 8;
            uint32_t dst = smem_b + (uint32_t)(((op << 12) + row * 32 + ((c ^ (row & 7)) << 2)) << 2);
            cp16_(dst, gsrc);
        }
        asm volatile("cp.async.commit_group;");
        asm volatile("cp.async.wait_group 0;");
        __syncthreads();

#pragma unroll
        for (int ks = 0; ks < 4; ks++) {
            uint32_t ah[2][4], al[2][4];
#pragma unroll
            for (int mt = 0; mt < 2; mt++) {
                int row = arow + mt * 16;
                int pc = (2 * ks + aqb) ^ (row & 7);
                uint32_t ad = smem_b + (uint32_t)((row * 32 + pc * 4) << 2);
                LDSM_X4_(ah[mt][0], ah[mt][1], ah[mt][2], ah[mt][3], ad);
                LDSM_X4_(al[mt][0], al[mt][1], al[mt][2], al[mt][3], ad + 16384);
            }
#pragma unroll
            for (int p = 0; p < 4; p++) {
                int n = brow + p * 16;
                int pc = (2 * ks + bqb) ^ (n & 7);
                uint32_t bd = smem_b + (uint32_t)(((8192 + n * 32 + pc * 4)) << 2);
                uint32_t bh0, bh1, bh2, bh3, bl0, bl1, bl2, bl3;
                LDSM_X4_(bh0, bh1, bh2, bh3, bd);
                LDSM_X4_(bl0, bl1, bl2, bl3, bd + 16384);
#pragma unroll
                for (int mt = 0; mt < 2; mt++) {
                    MMA_BF16_(acc[mt][2*p],   ah[mt][0], ah[mt][1], ah[mt][2], ah[mt][3], bh0, bh1);
                    MMA_BF16_(acc[mt][2*p],   ah[mt][0], ah[mt][1], ah[mt][2], ah[mt][3], bl0, bl1);
                    MMA_BF16_(acc[mt][2*p],   al[mt][0], al[mt][1], al[mt][2], al[mt][3], bh0, bh1);
                    MMA_BF16_(acc[mt][2*p+1], ah[mt][0], ah[mt][1], ah[mt][2], ah[mt][3], bh2, bh3);
                    MMA_BF16_(acc[mt][2*p+1], ah[mt][0], ah[mt][1], ah[mt][2], ah[mt][3], bl2, bl3);
                    MMA_BF16_(acc[mt][2*p+1], al[mt][0], al[mt][1], al[mt][2], al[mt][3], bh2, bh3);
                }
            }
        }
    }

    if (act == 2) {
        // ---- fused gate: logits partials for this 128-col tile -------------
        float* sw   = (float*)smem_u;            // [128][20]
        float* slog = (float*)smem_u + 2560;     // [2][128][16]
        __syncthreads();
        for (int i = tid; i < 2048; i += 256) {
            int cl = i >> 4, j = i & 15;
            sw[cl * 20 + j] = Wf2g[(size_t)(col0 + cl) * 16 + j];
        }
        __syncthreads();
        const float* biasp = bias + col0;
#pragma unroll
        for (int mt = 0; mt < 2; mt++)
#pragma unroll
        for (int rw = 0; rw < 2; rw++) {
            float pl[16];
#pragma unroll
            for (int j = 0; j < 16; j++) pl[j] = 0.f;
#pragma unroll
            for (int nt = 0; nt < 8; nt++) {
                int cl = warp_n + nt * 8 + 2 * t;
                float v0 = geluf_(acc[mt][nt][rw * 2 + 0] + biasp[cl]);
                float v1 = geluf_(acc[mt][nt][rw * 2 + 1] + biasp[cl + 1]);
                const float* w0 = sw + cl * 20;
                const float* w1 = w0 + 20;
#pragma unroll
                for (int j4 = 0; j4 < 16; j4 += 4) {
                    float4 a4 = *(const float4*)(w0 + j4);
                    float4 b4 = *(const float4*)(w1 + j4);
                    pl[j4 + 0] += v0 * a4.x + v1 * b4.x;
                    pl[j4 + 1] += v0 * a4.y + v1 * b4.y;
                    pl[j4 + 2] += v0 * a4.z + v1 * b4.z;
                    pl[j4 + 3] += v0 * a4.w + v1 * b4.w;
                }
            }
#pragma unroll
            for (int o = 1; o <= 2; o <<= 1)
#pragma unroll
                for (int j = 0; j < 16; j++)
                    pl[j] += __shfl_xor_sync(0xffffffffu, pl[j], o);
            if (t == 0) {
                int r = warp_m + mt * 16 + g + rw * 8;
                float* dst = slog + (((wid >> 2) << 7) + r) * 16;
                *(float4*)(dst + 0)  = make_float4(pl[0], pl[1], pl[2], pl[3]);
                *(float4*)(dst + 4)  = make_float4(pl[4], pl[5], pl[6], pl[7]);
                *(float4*)(dst + 8)  = make_float4(pl[8], pl[9], pl[10], pl[11]);
                *(float4*)(dst + 12) = make_float4(pl[12], pl[13], pl[14], pl[15]);
            }
        }
        __syncthreads();
        for (int i = tid; i < 2048; i += 256) {
            int r = i >> 4, j = i & 15;
            float v = slog[r * 16 + j] + slog[(128 + r) * 16 + j];
            Lgp[(size_t)blockIdx.x * (BL_ * 16) + (size_t)(row0 + r) * 16 + j] = v;
        }
        return;
    }

#pragma unroll
    for (int mt = 0; mt < 2; mt++) {
        int r0g = row0 + warp_m + mt * 16 + g;
#pragma unroll
        for (int nt = 0; nt < 8; nt++) {
            int c = col0 + warp_n + nt * 8 + 2 * t;
            float2 v0, v1;
            v0.x = acc[mt][nt][0]; v0.y = acc[mt][nt][1];
            v1.x = acc[mt][nt][2]; v1.y = acc[mt][nt][3];
            if (act == 1) {
                float b0 = bias[c], b1 = bias[c + 1];
                v0.x = geluf_(v0.x + b0); v0.y = geluf_(v0.y + b1);
                v1.x = geluf_(v1.x + b0); v1.y = geluf_(v1.y + b1);
            }
            *(float2*)(C + (size_t)r0g * N + c) = v0;
            *(float2*)(C + (size_t)(r0g + 8) * N + c) = v1;
        }
    }
}

// ------------------------- softmax over 4 gate branches ---------------------
__global__ __launch_bounds__(256) void softmax4_kernel(
    const float* __restrict__ Lgp, const float* __restrict__ bf2, float* __restrict__ fw)
{
    int idx = blockIdx.x * 256 + threadIdx.x;   // bl*4 + h, 32768 total
    int bl = idx >> 2, h = idx & 3;
    float l0 = bf2[h * 4 + 0], l1 = bf2[h * 4 + 1];
    float l2 = bf2[h * 4 + 2], l3 = bf2[h * 4 + 3];
#pragma unroll
    for (int tl = 0; tl < 16; tl++) {
        float4 v = *(const float4*)(Lgp + (size_t)tl * (BL_ * 16) + bl * 16 + h * 4);
        l0 += v.x; l1 += v.y; l2 += v.z; l3 += v.w;
    }
    float m = fmaxf(fmaxf(l0, l1), fmaxf(l2, l3));
    float e0 = expf(l0 - m), e1 = expf(l1 - m), e2 = expf(l2 - m), e3 = expf(l3 - m);
    float inv = 1.f / (e0 + e1 + e2 + e3);
    *(float4*)(fw + bl * 16 + h * 4) = make_float4(e0 * inv, e1 * inv, e2 * inv, e3 * inv);
}

// ------------------------- fused q/k/v short conv (K=4) + silu --------------
__global__ __launch_bounds__(256) void conv4_all_kernel(
    const float* __restrict__ x,
    const float* __restrict__ fq, const float* __restrict__ fk, const float* __restrict__ fv,
    float* __restrict__ qs, float* __restrict__ ks, float* __restrict__ vs)
{
    int idx = blockIdx.x * 256 + threadIdx.x;      // over BL_*3072
    int bl = idx / NQKV;
    int c3 = idx - bl * NQKV;
    int s  = c3 >> 10;
    int c  = c3 & (H_ - 1);
    int l  = bl & (L_ - 1);
    const float* f = (s == 0) ? fq : (s == 1) ? fk : fv;
    float* y = (s == 0) ? qs : (s == 1) ? ks : vs;
    const float* xp = x + (size_t)bl * NQKV + c3;
    float4 fv4 = *(const float4*)(f + c * 4);
    float acc = fv4.w * xp[0];
    if (l >= 1) acc += fv4.z * xp[-NQKV];
    if (l >= 2) acc += fv4.y * xp[-2 * NQKV];
    if (l >= 3) acc += fv4.x * xp[-3 * NQKV];
    y[(size_t)bl * H_ + c] = acc * sigmoidf_(acc);
}

// ------------------------- beta = sigmoid(hs @ Wb) --------------------------
__global__ __launch_bounds__(128) void beta_kernel(
    const float* __restrict__ hs, const float* __restrict__ Wb, float* __restrict__ beta)
{
    int bl = blockIdx.x;
    int wrp = threadIdx.x >> 5, lane = threadIdx.x & 31;
    const float* hp = hs + (size_t)bl * H_;
    float acc = 0.f;
    for (int d = lane; d < H_; d += 32) acc += hp[d] * Wb[d * NH_ + wrp];
#pragma unroll
    for (int o = 16; o; o >>= 1) acc += __shfl_xor_sync(0xffffffffu, acc, o);
    if (lane == 0) beta[bl * NH_ + wrp] = sigmoidf_(acc);
}

// ------------------------- l2norm + beta + transpose -> fp32 + bf16 hi/lo ---
__global__ __launch_bounds__(256) void normtr_kernel(
    const float* __restrict__ qs, const float* __restrict__ ks, const float* __restrict__ vs,
    const float* __restrict__ beta,
    float* __restrict__ kn, float* __restrict__ kb, float* __restrict__ vb,
    __nv_bfloat16* __restrict__ qnh, __nv_bfloat16* __restrict__ qnl,
    __nv_bfloat16* __restrict__ knh, __nv_bfloat16* __restrict__ knl,
    __nv_bfloat16* __restrict__ kbh, __nv_bfloat16* __restrict__ kbl)
{
    int bl = blockIdx.x, h = blockIdx.y, d = threadIdx.x;
    int b = bl >> 12;
    int l = bl & (L_ - 1);
    size_t src = (size_t)bl * H_ + h * DK_ + d;
    float qv = qs[src], kv = ks[src], vv = vs[src];
    float s1 = qv * qv, s2 = kv * kv;
#pragma unroll
    for (int o = 16; o; o >>= 1) {
        s1 += __shfl_xor_sync(0xffffffffu, s1, o);
        s2 += __shfl_xor_sync(0xffffffffu, s2, o);
    }
    __shared__ float r1[8], r2[8];
    __shared__ float inv1, inv2;
    int lane = d & 31, wid = d >> 5;
    if (lane == 0) { r1[wid] = s1; r2[wid] = s2; }
    __syncthreads();
    if (d == 0) {
        float t1 = 0.f, t2 = 0.f;
        for (int i = 0; i < 8; i++) { t1 += r1[i]; t2 += r2[i]; }
        inv1 = rsqrtf(t1);
        inv2 = rsqrtf(t2);
    }
    __syncthreads();
    float bt = beta[bl * NH_ + h];
    size_t dst = (((size_t)b * NH_ + h) * L_ + l) * DK_ + d;
    float knv = kv * inv2;
    float qnv = qv * inv1;
    float kbv = knv * bt;
    kn[dst] = knv;
    kb[dst] = kbv;
    vb[dst] = vv * bt;
    __nv_bfloat16 t0;
    t0 = __float2bfloat16(qnv); qnh[dst] = t0;
    qnl[dst] = __float2bfloat16(qnv - __bfloat162float(t0));
    t0 = __float2bfloat16(knv); knh[dst] = t0;
    knl[dst] = __float2bfloat16(knv - __bfloat162float(t0));
    t0 = __float2bfloat16(kbv); kbh[dst] = t0;
    kbl[dst] = __float2bfloat16(kbv - __bfloat162float(t0));
}

// ------------------------- per-chunk: HMMA A/attn + UT transform, u, w ------
#define CK_STRIDE 257
#define CK_SMEM (33888 * 4)
__global__ __launch_bounds__(256) void chunk_kernel(
    const float* __restrict__ kb, const float* __restrict__ vb,
    const __nv_bfloat16* __restrict__ knh_g, const __nv_bfloat16* __restrict__ knl_g,
    const __nv_bfloat16* __restrict__ kbh_g, const __nv_bfloat16* __restrict__ kbl_g,
    const __nv_bfloat16* __restrict__ qnh_g, const __nv_bfloat16* __restrict__ qnl_g,
    float* __restrict__ U, __nv_bfloat16* __restrict__ Wmh, __nv_bfloat16* __restrict__ Wml,
    float* __restrict__ ATT)
{
    extern __shared__ float sm[];
    float* skb = sm;
    float* sx  = sm + 8224;
    float* T   = sm + 16448;
    const uint32_t smem_b = smem_u32_(sm);
    const int bh = blockIdx.x, n = blockIdx.y;
    const int tid = threadIdx.x;
    const int wid = tid >> 5, lane = tid & 31;
    size_t base = ((size_t)bh * L_ + n * C_) * DK_;

    for (int i = tid; i < 2048; i += 256) {
        int r = i >> 6, c4 = (i & 63) << 2;
        float4 b = ((const float4*)(kb + base))[i];
        float4 v = ((const float4*)(vb + base))[i];
        float* pb = skb + r * CK_STRIDE + c4;
        float* pv = sx + r * CK_STRIDE + c4;
        pb[0] = b.x; pb[1] = b.y; pb[2] = b.z; pb[3] = b.w;
        pv[0] = v.x; pv[1] = v.y; pv[2] = v.z; pv[3] = v.w;
    }
#pragma unroll
    for (int i = 0; i < 16; i++) {
        const int arr = i >> 2;
        int idx = (i & 3) * 256 + tid;
        int row = idx >> 5, ch = idx & 31;
        const __nv_bfloat16* gp =
            (arr == 0) ? knh_g + base + row * 256 + ch * 8 :
            (arr == 1) ? knl_g + base + row * 256 + ch * 8 :
            (arr == 2) ? kbh_g + base + row * 256 + ch * 8 :
                         kbl_g + base + row * 256 + ch * 8;
        const uint32_t ab = (arr == 0) ? 17504u : (arr == 1) ? 21600u
                          : (arr == 2) ? 25696u : 29792u;
        uint32_t w = ab + (uint32_t)(row * 128 + (((ch & 24) | ((ch & 7) ^ (row & 7))) << 2));
        cp16_(smem_b + w * 4, gp);
    }
    asm volatile("cp.async.commit_group;");
    asm volatile("cp.async.wait_group 0;");
    __syncthreads();

    const int m0 = (wid & 1) << 4, n0 = (wid >> 1) << 3;
    const int qq = lane >> 3, rr = lane & 7;
    const int gg = lane >> 2, tt = lane & 3;
    const int arow = m0 + ((qq & 1) << 3) + rr;
    const int aqb = qq >> 1;
    const int brw = n0 + rr;
    {
        float acc[4] = {0.f, 0.f, 0.f, 0.f};
#pragma unroll
        for (int p = 0; p < 8; p++) {
            int bch = 4 * p + qq;
            uint32_t bw = 17504u + (uint32_t)(brw * 128 + (((bch & 24) | ((bch & 7) ^ (brw & 7))) << 2));
            uint32_t b0, b1, b2, b3, c0, c1, c2, c3;
            LDSM_X4_(b0, b1, b2, b3, smem_b + bw * 4);
            LDSM_X4_(c0, c1, c2, c3, smem_b + (bw + 4096u) * 4);
#pragma unroll
            for (int s = 0; s < 2; s++) {
                int ach = 2 * (2 * p + s) + aqb;
                uint32_t aw = 25696u + (uint32_t)(arow * 128 + (((ach & 24) | ((ach & 7) ^ (arow & 7))) << 2));
                uint32_t ah0, ah1, ah2, ah3, al0, al1, al2, al3;
                LDSM_X4_(ah0, ah1, ah2, ah3, smem_b + aw * 4);
                LDSM_X4_(al0, al1, al2, al3, smem_b + (aw + 4096u) * 4);
                uint32_t Bh0 = s ? b2 : b0, Bh1 = s ? b3 : b1;
                uint32_t Bl0 = s ? c2 : c0, Bl1 = s ? c3 : c1;
                MMA_BF16_(acc, ah0, ah1, ah2, ah3, Bh0, Bh1);
                MMA_BF16_(acc, ah0, ah1, ah2, ah3, Bl0, Bl1);
                MMA_BF16_(acc, al0, al1, al2, al3, Bh0, Bh1);
            }
        }
        int i0 = m0 + gg, j0 = n0 + 2 * tt;
        T[i0 * 33 + j0]           = (j0 < i0)         ? -acc[0] : 0.f;
        T[i0 * 33 + j0 + 1]       = (j0 + 1 < i0)     ? -acc[1] : 0.f;
        T[(i0 + 8) * 33 + j0]     = (j0 < i0 + 8)     ? -acc[2] : 0.f;
        T[(i0 + 8) * 33 + j0 + 1] = (j0 + 1 < i0 + 8) ? -acc[3] : 0.f;
    }
    __syncthreads();

#pragma unroll
    for (int i = 0; i < 8; i++) {
        const int arr = i >> 2;
        int idx = (i & 3) * 256 + tid;
        int row = idx >> 5, ch = idx & 31;
        const __nv_bfloat16* gp = (arr ? qnl_g : qnh_g) + base + row * 256 + ch * 8;
        uint32_t w = (arr ? 29792u : 25696u)
                   + (uint32_t)(row * 128 + (((ch & 24) | ((ch & 7) ^ (row & 7))) << 2));
        cp16_(smem_b + w * 4, gp);
    }
    asm volatile("cp.async.commit_group;");

    if (tid < 32) {
        int j = tid;
        for (int i = 1; i < 32; i++) {
            float rv = T[i * 33 + j];
            float acc = rv;
            for (int m = 1; m < i; m++)
                acc += __shfl_sync(0xffffffffu, rv, m) * T[m * 33 + j];
            __syncwarp();
            T[i * 33 + j] = acc;
            __syncwarp();
        }
        T[j * 33 + j] = 1.f;
    }
    __syncthreads();

    for (int idx = tid; idx < 8192; idx += 256) {
        int c = idx >> 8, d = idx & 255;
        float au = 0.f, aw = 0.f;
#pragma unroll
        for (int j = 0; j < 32; j++) {
            float t = T[c * 33 + j];
            au += t * sx[j * CK_STRIDE + d];
            aw += t * skb[j * CK_STRIDE + d];
        }
        U[base + idx] = au;
        __nv_bfloat16 hh = __float2bfloat16(aw);
        Wmh[base + idx] = hh;
        Wml[base + idx] = __float2bfloat16(aw - __bfloat162float(hh));
    }

    asm volatile("cp.async.wait_group 0;");
    __syncthreads();

    {
        float acc[4] = {0.f, 0.f, 0.f, 0.f};
#pragma unroll
        for (int p = 0; p < 8; p++) {
            int bch = 4 * p + qq;
            uint32_t bw = 17504u + (uint32_t)(brw * 128 + (((bch & 24) | ((bch & 7) ^ (brw & 7))) << 2));
            uint32_t b0, b1, b2, b3, c0, c1, c2, c3;
            LDSM_X4_(b0, b1, b2, b3, smem_b + bw * 4);
            LDSM_X4_(c0, c1, c2, c3, smem_b + (bw + 4096u) * 4);
#pragma unroll
            for (int s = 0; s < 2; s++) {
                int ach = 2 * (2 * p + s) + aqb;
                uint32_t aw = 25696u + (uint32_t)(arow * 128 + (((ach & 24) | ((ach & 7) ^ (arow & 7))) << 2));
                uint32_t ah0, ah1, ah2, ah3, al0, al1, al2, al3;
                LDSM_X4_(ah0, ah1, ah2, ah3, smem_b + aw * 4);
                LDSM_X4_(al0, al1, al2, al3, smem_b + (aw + 4096u) * 4);
                uint32_t Bh0 = s ? b2 : b0, Bh1 = s ? b3 : b1;
                uint32_t Bl0 = s ? c2 : c0, Bl1 = s ? c3 : c1;
                MMA_BF16_(acc, ah0, ah1, ah2, ah3, Bh0, Bh1);
                MMA_BF16_(acc, ah0, ah1, ah2, ah3, Bl0, Bl1);
                MMA_BF16_(acc, al0, al1, al2, al3, Bh0, Bh1);
            }
        }
        float* att = ATT + ((size_t)bh * NC_ + n) * 1024;
        int i0 = m0 + gg, j0 = n0 + 2 * tt;
        att[i0 * 32 + j0]           = (j0 <= i0)         ? acc[0] : 0.f;
        att[i0 * 32 + j0 + 1]       = (j0 + 1 <= i0)     ? acc[1] : 0.f;
        att[(i0 + 8) * 32 + j0]     = (j0 <= i0 + 8)     ? acc[2] : 0.f;
        att[(i0 + 8) * 32 + j0 + 1] = (j0 + 1 <= i0 + 8) ? acc[3] : 0.f;
    }
}

// ------------------------- sequential chunk scan: HMMA wS/qS ----------------
#define SCAN_SMEM (36352 * 4)
__global__ __launch_bounds__(256) void scan_kernel(
    const float* __restrict__ kn,
    const __nv_bfloat16* __restrict__ qh_g, const __nv_bfloat16* __restrict__ ql_g,
    const __nv_bfloat16* __restrict__ wh_g, const __nv_bfloat16* __restrict__ wl_g,
    const float* __restrict__ U, const float* __restrict__ ATT, float* __restrict__ OUT)
{
    extern __shared__ float sm[];
    float* S   = sm;             // [256][16]
    float* sk  = sm + 4096;      // [32][260]
    uint32_t* sbh = (uint32_t*)(sm + 28800);
    uint32_t* sbl = (uint32_t*)(sm + 30912);
    float* su  = sm + 33024;
    float* sut = sm + 33536;
    float* sat = sm + 34048;
    float* swS = sm + 35200;
    float* sqS = sm + 35776;
    const uint32_t smem_b = smem_u32_(sm);
    const int bh = blockIdx.x, tile = blockIdx.y;
    const int tid = threadIdx.x;
    const int wid = tid >> 5, lane = tid & 31;
    const int b = bh >> 2, h = bh & 3;
    const int g = tid >> 3, eg = tid & 7, eg2 = eg * 2;
    const int pr = wid & 1, mt = (wid >> 1) & 1, nt = wid >> 2;
    const int qq = lane >> 3, rr = lane & 7;
    const int arow = mt * 16 + ((qq & 1) << 3) + rr;
    const int aqb  = qq >> 1;
    const int brow = ((qq >> 1) << 3) + rr;
    const int bqb  = qq & 1;
    const int gg = lane >> 2, tt = lane & 3;
    const uint32_t abaseW = 12416u + (pr ? 8192u : 0u);
    const int ce = tid & 15, cd0 = (tid >> 4) * 16;

    for (int i = tid; i < 4096; i += 256) S[i] = 0.f;

    for (int n = 0; n < NC_; n++) {
        __syncthreads();
        size_t base = ((size_t)bh * L_ + n * C_) * 256;
        for (int i = tid; i < 2048; i += 256) {
            int c = i >> 6, o = (i & 63) * 4;
            *(float4*)(sk + c * 260 + o) = ((const float4*)(kn + base))[i];
        }
#pragma unroll
        for (int i = 0; i < 16; i++) {
            const int arr = i >> 2, r = i & 3;
            int row = r * 8 + wid;
            int ch  = lane;
            const __nv_bfloat16* gp =
                (arr == 0) ? wh_g + base + row * 256 + ch * 8 :
                (arr == 1) ? wl_g + base + row * 256 + ch * 8 :
                (arr == 2) ? qh_g + base + row * 256 + ch * 8 :
                             ql_g + base + row * 256 + ch * 8;
            uint32_t w = 12416u + (uint32_t)(arr * 4096 + row * 128
                         + (((ch & 24) | ((ch & 7) ^ (row & 7))) << 2));
            cp16_(smem_b + w * 4, gp);
        }
        asm volatile("cp.async.commit_group;");
        if (tid < 128) {
            int c = tid >> 2, e4 = tid & 3;
            ((float4*)su)[tid] = *(const float4*)(U + base + c * 256 + tile * 16 + e4 * 4);
        }
        {
            int c = tid >> 3, j4 = (tid & 7) * 4;
            *(float4*)(sat + c * 36 + j4) =
                ((const float4*)(ATT + ((size_t)bh * NC_ + n) * 1024))[tid];
        }
#pragma unroll
        for (int i2 = 0; i2 < 8; i2++) {
            int d = cd0 + i2 * 2;
            float x = S[d * 16 + ce], y = S[(d + 1) * 16 + ce];
            sbh[ce * 132 + (d >> 1)] = pack_bf16_hi_(x, y);
            sbl[ce * 132 + (d >> 1)] = pack_bf16_lo_(x, y);
        }
        asm volatile("cp.async.wait_group 0;");
        __syncthreads();

        float acc[4] = {0.f, 0.f, 0.f, 0.f};
#pragma unroll
        for (int ks = 0; ks < 16; ks++) {
            int ch = 2 * ks + aqb;
            uint32_t aw_ = abaseW + (uint32_t)(arow * 128
                          + (((ch & 24) | ((ch & 7) ^ (arow & 7))) << 2));
            uint32_t ah0, ah1, ah2, ah3, al0, al1, al2, al3;
            LDSM_X4_(ah0, ah1, ah2, ah3, smem_b + aw_ * 4);
            LDSM_X4_(al0, al1, al2, al3, smem_b + (aw_ + 4096u) * 4);
            uint32_t bw_ = 28800u + (uint32_t)(brow * 132 + (2 * ks + bqb) * 4);
            uint32_t bh0, bh1, bh2, bh3, bl0, bl1, bl2, bl3;
            LDSM_X4_(bh0, bh1, bh2, bh3, smem_b + bw_ * 4);
            LDSM_X4_(bl0, bl1, bl2, bl3, smem_b + (bw_ + 2112u) * 4);
            uint32_t B0h = nt ? bh2 : bh0, B1h = nt ? bh3 : bh1;
            uint32_t B0l = nt ? bl2 : bl0, B1l = nt ? bl3 : bl1;
            MMA_BF16_(acc, ah0, ah1, ah2, ah3, B0h, B1h);
            MMA_BF16_(acc, ah0, ah1, ah2, ah3, B0l, B1l);
            MMA_BF16_(acc, al0, al1, al2, al3, B0h, B1h);
        }
        {
            float* dst = pr ? sqS : swS;
            int c0 = mt * 16 + gg, e0 = nt * 8 + 2 * tt;
            *(float2*)(dst + c0 * 18 + e0) = make_float2(acc[0], acc[1]);
            *(float2*)(dst + (c0 + 8) * 18 + e0) = make_float2(acc[2], acc[3]);
        }
        __syncthreads();

        float2 uv = *(float2*)(su + g * 16 + eg2);
        float2 wv = *(float2*)(swS + g * 18 + eg2);
        float2 ut = make_float2(uv.x - wv.x, uv.y - wv.y);
        *(float2*)(sut + g * 16 + eg2) = ut;
        float2 aq = *(float2*)(sqS + g * 18 + eg2);
        __syncthreads();

        const float* ar = sat + g * 36;
#pragma unroll
        for (int j = 0; j < 32; j += 4) {
            float4 a4 = *(const float4*)(ar + j);
            float2 u0 = *(float2*)(sut + (j + 0) * 16 + eg2);
            float2 u1 = *(float2*)(sut + (j + 1) * 16 + eg2);
            float2 u2 = *(float2*)(sut + (j + 2) * 16 + eg2);
            float2 u3 = *(float2*)(sut + (j + 3) * 16 + eg2);
            aq.x += a4.x * u0.x + a4.y * u1.x + a4.z * u2.x + a4.w * u3.x;
            aq.y += a4.x * u0.y + a4.y * u1.y + a4.z * u2.y + a4.w * u3.y;
        }
        *(float2*)(OUT + (size_t)(b * L_ + n * C_ + g) * H_ + h * 256 + tile * 16 + eg2) = aq;

        float2 accS[8];
#pragma unroll
        for (int i = 0; i < 8; i++) accS[i] = make_float2(0.f, 0.f);
        for (int c2 = 0; c2 < 32; c2++) {
            float2 u2 = *(float2*)(sut + c2 * 16 + eg2);
            const float* kr = sk + c2 * 260 + g * 8;
            float4 k0 = *(const float4*)(kr);
            float4 k1 = *(const float4*)(kr + 4);
            accS[0].x += k0.x * u2.x; accS[0].y += k0.x * u2.y;
            accS[1].x += k0.y * u2.x; accS[1].y += k0.y * u2.y;
            accS[2].x += k0.z * u2.x; accS[2].y += k0.z * u2.y;
            accS[3].x += k0.w * u2.x; accS[3].y += k0.w * u2.y;
            accS[4].x += k1.x * u2.x; accS[4].y += k1.x * u2.y;
            accS[5].x += k1.y * u2.x; accS[5].y += k1.y * u2.y;
            accS[6].x += k1.z * u2.x; accS[6].y += k1.z * u2.y;
            accS[7].x += k1.w * u2.x; accS[7].y += k1.w * u2.y;
        }
#pragma unroll
        for (int i = 0; i < 8; i++) {
            float2 s2 = *(float2*)(S + (g * 8 + i) * 16 + eg2);
            s2.x += accS[i].x; s2.y += accS[i].y;
            *(float2*)(S + (g * 8 + i) * 16 + eg2) = s2;
        }
    }
}

// ------------------------- FIR K=7 (unrolled) -------------------------------
__global__ __launch_bounds__(256) void fir7_kernel(
    const float* __restrict__ x, const float* __restrict__ f, float* __restrict__ y)
{
    int idx = blockIdx.x * 256 + threadIdx.x;
    int c  = idx & (H_ - 1);
    int bl = idx >> 10;
    int l  = bl & (L_ - 1);
    const float* fp = f + (size_t)c * 7;
    float acc = 0.f;
#pragma unroll
    for (int t = 0; t < 7; t++) {
        int dl = t - 6;
        if (l + dl >= 0) acc += x[idx + dl * H_] * fp[t];
    }
    y[idx] = acc;
}

// ------------------------- FIR K=64: smem tile + register sliding window ----
#define FIR64_SMEM ((127 * 128 + 64 * 129) * 4)
__global__ __launch_bounds__(256) void fir64_smem_kernel(
    const float* __restrict__ x, const float* __restrict__ f, float* __restrict__ y)
{
    extern __shared__ float fsm[];
    float* sx = fsm;
    float* sf = fsm + 127 * 128;
    const int ctile = blockIdx.x & 7;
    const int ltile = blockIdx.x >> 3;
    const int l0 = ltile * 64;
    const int lb = l0 & (L_ - 1);
    const int c0 = ctile * 128;
    const int tid = threadIdx.x;

    for (int i = tid; i < 64 * 128; i += 256) {
        int c = i >> 6, t = i & 63;
        sf[t * 129 + c] = f[(size_t)(c0 + c) * 64 + t];
    }
    for (int i = tid; i < 127 * 128; i += 256) {
        int j = i >> 7, c = i & 127;
        int lrel = lb + j - 63;
        float v = 0.f;
        if (lrel >= 0)
            v = x[(size_t)(l0 + j - 63) * H_ + c0 + c];
        sx[j * 128 + c] = v;
    }
    __syncthreads();

    const int c = tid & 127;
    const int lg = (tid >> 7) * 32;
    float acc[32], win[32];
#pragma unroll
    for (int i = 0; i < 32; i++) acc[i] = 0.f;
#pragma unroll
    for (int i = 0; i < 32; i++) win[i] = sx[(lg + i) * 128 + c];
#pragma unroll
    for (int t = 0; t < 64; t++) {
        float ft = sf[t * 129 + c];
#pragma unroll
        for (int i = 0; i < 32; i++) acc[i] += ft * win[i];
        if (t < 63) {
#pragma unroll
            for (int i = 0; i < 31; i++) win[i] = win[i + 1];
            win[31] = sx[(lg + t + 32) * 128 + c];
        }
    }
#pragma unroll
    for (int i = 0; i < 32; i++)
        y[(size_t)(l0 + lg + i) * H_ + c0 + c] = acc[i];
}

// ------------------------- branch mix + per-head rmsnorm -> bf16 hi/lo ------
__global__ __launch_bounds__(256) void mix_rms_kernel(
    const float* __restrict__ br_s, const float* __restrict__ br_l,
    const float* __restrict__ br_d, const float* __restrict__ br_v,
    const float* __restrict__ fw, const float* __restrict__ rmsw,
    __nv_bfloat16* __restrict__ Mhi, __nv_bfloat16* __restrict__ Mlo)
{
    int bl = blockIdx.x, h = blockIdx.y, d = threadIdx.x;
    size_t i = (size_t)bl * H_ + h * 256 + d;
    const float* f = fw + (size_t)bl * 16 + h * 4;
    float val = f[0] * br_s[i] + f[1] * br_l[i] + f[2] * br_d[i] + f[3] * br_v[i];
    float ss = val * val;
#pragma unroll
    for (int o = 16; o; o >>= 1) ss += __shfl_xor_sync(0xffffffffu, ss, o);
    __shared__ float red[8];
    __shared__ float scale;
    if ((d & 31) == 0) red[d >> 5] = ss;
    __syncthreads();
    if (d == 0) {
        float t = 0.f;
        for (int k = 0; k < 8; k++) t += red[k];
        scale = rsqrtf(t * (1.f / 256.f) + 1e-5f);
    }
    __syncthreads();
    float o = val * scale * rmsw[d];
    __nv_bfloat16 hb = __float2bfloat16(o);
    Mhi[i] = hb;
    Mlo[i] = __float2bfloat16(o - __bfloat162float(hb));
}

// ------------------------- launcher ----------------------------------------
extern "C" void kernel_launch(void* const* d_in, const int* in_sizes, int n_in,
                              void* d_out, int out_size)
{
    const float* hs   = (const float*)d_in[0];
    const float* Wq   = (const float*)d_in[1];
    const float* Wk   = (const float*)d_in[2];
    const float* Wv   = (const float*)d_in[3];
    const float* Wb   = (const float*)d_in[4];
    const float* cq   = (const float*)d_in[5];
    const float* ck   = (const float*)d_in[6];
    const float* cv   = (const float*)d_in[7];
    const float* fsw  = (const float*)d_in[8];
    const float* flw  = (const float*)d_in[9];
    const float* Wf1  = (const float*)d_in[10];
    const float* bf1  = (const float*)d_in[11];
    const float* Wf2  = (const float*)d_in[12];
    const float* bf2  = (const float*)d_in[13];
    const float* rmsw = (const float*)d_in[14];
    const float* Wo   = (const float*)d_in[15];
    float* out = (float*)d_out;

    float *qkvp, *qs, *ks, *vs, *kn, *kb, *vb;
    float *u, *delta, *shrt, *lng, *lgp, *att, *beta, *fw;
    __nv_bfloat16 *ahi, *alo, *mhi, *mlo, *wqh, *wql, *wf1h, *wf1l, *woh, *wol;
    __nv_bfloat16 *qnh, *qnl, *knh, *knl, *kbh, *kbl, *wmh, *wml;
    cudaGetSymbolAddress((void**)&qkvp, g_qkvp);
    cudaGetSymbolAddress((void**)&qs, g_qs);
    cudaGetSymbolAddress((void**)&ks, g_ks);
    cudaGetSymbolAddress((void**)&vs, g_vs);
    cudaGetSymbolAddress((void**)&kn, g_kn);
    cudaGetSymbolAddress((void**)&kb, g_kb);
    cudaGetSymbolAddress((void**)&vb, g_vb);
    cudaGetSymbolAddress((void**)&u, g_u);
    cudaGetSymbolAddress((void**)&delta, g_delta);
    cudaGetSymbolAddress((void**)&shrt, g_shrt);
    cudaGetSymbolAddress((void**)&lng, g_long);
    cudaGetSymbolAddress((void**)&lgp, g_lgp);
    cudaGetSymbolAddress((void**)&att, g_att);
    cudaGetSymbolAddress((void**)&beta, g_beta);
    cudaGetSymbolAddress((void**)&fw, g_fw);
    cudaGetSymbolAddress((void**)&ahi, g_ahi);
    cudaGetSymbolAddress((void**)&alo, g_alo);
    cudaGetSymbolAddress((void**)&mhi, g_mhi);
    cudaGetSymbolAddress((void**)&mlo, g_mlo);
    cudaGetSymbolAddress((void**)&qnh, g_qnh);
    cudaGetSymbolAddress((void**)&qnl, g_qnl);
    cudaGetSymbolAddress((void**)&knh, g_knh);
    cudaGetSymbolAddress((void**)&knl, g_knl);
    cudaGetSymbolAddress((void**)&kbh, g_kbh);
    cudaGetSymbolAddress((void**)&kbl, g_kbl);
    cudaGetSymbolAddress((void**)&wmh, g_wh);
    cudaGetSymbolAddress((void**)&wml, g_wl);
    cudaGetSymbolAddress((void**)&wqh, g_wqkv_hi);
    cudaGetSymbolAddress((void**)&wql, g_wqkv_lo);
    cudaGetSymbolAddress((void**)&wf1h, g_wf1_hi);
    cudaGetSymbolAddress((void**)&wf1l, g_wf1_lo);
    cudaGetSymbolAddress((void**)&woh, g_wo_hi);
    cudaGetSymbolAddress((void**)&wol, g_wo_lo);

    cudaFuncSetAttribute(mma_gemm2_kernel, cudaFuncAttributeMaxDynamicSharedMemorySize, MG_SMEM);
    cudaFuncSetAttribute(chunk_kernel, cudaFuncAttributeMaxDynamicSharedMemorySize, CK_SMEM);
    cudaFuncSetAttribute(scan_kernel,  cudaFuncAttributeMaxDynamicSharedMemorySize, SCAN_SMEM);
    cudaFuncSetAttribute(fir64_smem_kernel, cudaFuncAttributeMaxDynamicSharedMemorySize, FIR64_SMEM);

    // ---- prep: bf16 hi/lo conversions ----
    cvt_a_kernel<<<BL_ * H_ / 1024, 256>>>(hs, ahi, alo);
    cvt_wt_kernel<<<dim3(32, 32), 256>>>(Wq, wqh,             wql,             H_, H_);
    cvt_wt_kernel<<<dim3(32, 32), 256>>>(Wk, wqh + 1024 * H_, wql + 1024 * H_, H_, H_);
    cvt_wt_kernel<<<dim3(32, 32), 256>>>(Wv, wqh + 2048 * H_, wql + 2048 * H_, H_, H_);
    cvt_wt_kernel<<<dim3(64, 32), 256>>>(Wf1, wf1h, wf1l, H_, F1_);
    cvt_wt_kernel<<<dim3(32, 32), 256>>>(Wo, woh, wol, H_, H_);

    // ---- fused qkv projection; f1 GEMM + fused gate logits -----------------
    mma_gemm2_kernel<<<dim3(NQKV / 128, BL_ / 128), 256, MG_SMEM>>>(
        ahi, alo, wqh, wql, nullptr, qkvp, nullptr, nullptr, NQKV, H_, 0);
    mma_gemm2_kernel<<<dim3(F1_ / 128, BL_ / 128), 256, MG_SMEM>>>(
        ahi, alo, wf1h, wf1l, bf1, nullptr, Wf2, lgp, F1_, H_, 2);
    softmax4_kernel<<<BL_ * 4 / 256, 256>>>(lgp, bf2, fw);

    // fused short conv + silu (q,k,v in one launch)
    conv4_all_kernel<<<BL_ * NQKV / 256, 256>>>(qkvp, cq, ck, cv, qs, ks, vs);

    // beta, l2norm + transpose (fp32 + bf16 hi/lo)
    beta_kernel<<<BL_, 128>>>(hs, Wb, beta);
    normtr_kernel<<<dim3(BL_, NH_), 256>>>(qs, ks, vs, beta, kn, kb, vb,
                                           qnh, qnl, knh, knl, kbh, kbl);

    // delta rule
    chunk_kernel<<<dim3(BH_, NC_), 256, CK_SMEM>>>(
        kb, vb, knh, knl, kbh, kbl, qnh, qnl, u, wmh, wml, att);
    scan_kernel<<<dim3(BH_, 16), 256, SCAN_SMEM>>>(kn, qnh, qnl, wmh, wml, u, att, delta);

    // FIR branches
    fir7_kernel<<<BL_ * H_ / 256, 256>>>(vs, fsw, shrt);
    fir64_smem_kernel<<<1024, 256, FIR64_SMEM>>>(vs, flw, lng);

    // mix+rmsnorm, output projection
    mix_rms_kernel<<<dim3(BL_, NH_), 256>>>(shrt, lng, delta, vs, fw, rmsw, mhi, mlo);
    mma_gemm2_kernel<<<dim3(H_ / 128, BL_ / 128), 256, MG_SMEM>>>(
        mhi, mlo, woh, wol, nullptr, out, nullptr, nullptr, H_, H_, 0);
}

// round 16
// speedup vs baseline: 1.7879x; 1.1100x over previous
#include <cuda_runtime.h>
#include <cuda_bf16.h>
#include <math.h>
#include <stdint.h>

#define B_   2
#define L_   4096
#define H_   1024
#define NH_  4
#define DK_  256
#define DV_  256
#define C_   32
#define NC_  128
#define BL_  8192
#define BH_  8
#define F1_  2048
#define NQKV 3072

// ------------------------- scratch (static device memory; no allocs) -------
__device__ float g_qkvp[BL_*NQKV];
__device__ float g_qs[BL_*H_], g_ks[BL_*H_], g_vs[BL_*H_];
__device__ float g_kb[BL_*H_], g_vb[BL_*H_];
__device__ float g_u [BL_*H_];
__device__ float g_delta[BL_*H_], g_long[BL_*H_];
__device__ float g_lgp[16*BL_*16];
__device__ float g_att[BH_*NC_*C_*C_];
__device__ float g_beta[BL_*NH_];
__device__ float g_fw[BL_*16];
// bf16 hi/lo staging
__device__ __nv_bfloat16 g_ahi[BL_*H_],  g_alo[BL_*H_];
__device__ __nv_bfloat16 g_mhi[BL_*H_],  g_mlo[BL_*H_];
__device__ __nv_bfloat16 g_qnh[BL_*H_],  g_qnl[BL_*H_];
__device__ __nv_bfloat16 g_knh[BL_*H_],  g_knl[BL_*H_];
__device__ __nv_bfloat16 g_kbh[BL_*H_],  g_kbl[BL_*H_];
__device__ __nv_bfloat16 g_wh[BL_*H_],   g_wl[BL_*H_];
__device__ __nv_bfloat16 g_wqkv_hi[NQKV*H_], g_wqkv_lo[NQKV*H_];
__device__ __nv_bfloat16 g_wf1_hi[F1_*H_],   g_wf1_lo[F1_*H_];
__device__ __nv_bfloat16 g_wo_hi[H_*H_],     g_wo_lo[H_*H_];

__device__ __forceinline__ float sigmoidf_(float x) { return 1.f / (1.f + expf(-x)); }
__device__ __forceinline__ float geluf_(float x) {
    return 0.5f * x * (1.f + erff(x * 0.70710678118654752440f));
}
__device__ __forceinline__ uint32_t smem_u32_(const void* p) {
    uint32_t a;
    asm("{ .reg .u64 t; cvta.to.shared.u64 t, %1; cvt.u32.u64 %0, t; }" : "=r"(a) : "l"(p));
    return a;
}
__device__ __forceinline__ uint32_t pack_bf16_hi_(float x, float y) {
    __nv_bfloat162 h = __halves2bfloat162(__float2bfloat16(x), __float2bfloat16(y));
    return *reinterpret_cast<uint32_t*>(&h);
}
__device__ __forceinline__ uint32_t pack_bf16_lo_(float x, float y) {
    float hx = __bfloat162float(__float2bfloat16(x));
    float hy = __bfloat162float(__float2bfloat16(y));
    __nv_bfloat162 l = __halves2bfloat162(__float2bfloat16(x - hx), __float2bfloat16(y - hy));
    return *reinterpret_cast<uint32_t*>(&l);
}
__device__ __forceinline__ void cp16_(uint32_t dst, const void* src) {
    asm volatile("cp.async.ca.shared.global [%0], [%1], 16;" :: "r"(dst), "l"(src));
}

// ------------------------- prep: fp32 -> bf16 hi/lo ------------------------
__global__ __launch_bounds__(256) void cvt_a_kernel(
    const float* __restrict__ x, __nv_bfloat16* __restrict__ hi, __nv_bfloat16* __restrict__ lo)
{
    int i = (blockIdx.x * 256 + threadIdx.x) * 4;
    float4 v = *(const float4*)(x + i);
    uint2 oh, ol;
    oh.x = pack_bf16_hi_(v.x, v.y); oh.y = pack_bf16_hi_(v.z, v.w);
    ol.x = pack_bf16_lo_(v.x, v.y); ol.y = pack_bf16_lo_(v.z, v.w);
    *(uint2*)(hi + i) = oh;
    *(uint2*)(lo + i) = ol;
}

// W [K][N] -> Wt hi/lo [N][K]  (32x32 smem transpose)
__global__ __launch_bounds__(256) void cvt_wt_kernel(
    const float* __restrict__ W, __nv_bfloat16* __restrict__ hi, __nv_bfloat16* __restrict__ lo,
    int K, int N)
{
    __shared__ float tile[32][33];
    int n0 = blockIdx.x * 32, k0 = blockIdx.y * 32;
    int tx = threadIdx.x & 31, ty = threadIdx.x >> 5;
#pragma unroll
    for (int i = 0; i < 4; i++)
        tile[ty + 8 * i][tx] = W[(size_t)(k0 + ty + 8 * i) * N + n0 + tx];
    __syncthreads();
#pragma unroll
    for (int i = 0; i < 4; i++) {
        float v = tile[tx][ty + 8 * i];
        __nv_bfloat16 h = __float2bfloat16(v);
        size_t o = (size_t)(n0 + ty + 8 * i) * K + k0 + tx;
        hi[o] = h;
        lo[o] = __float2bfloat16(v - __bfloat162float(h));
    }
}

// ===================== warp-mma bf16 split-x3 GEMM (ldmatrix) ===============
#define MMA_BF16_(c, a0, a1, a2, a3, b0, b1) \
    asm volatile("mma.sync.aligned.m16n8k16.row.col.f32.bf16.bf16.f32 " \
        "{%0,%1,%2,%3}, {%4,%5,%6,%7}, {%8,%9}, {%0,%1,%2,%3};" \
        : "+f"((c)[0]), "+f"((c)[1]), "+f"((c)[2]), "+f"((c)[3]) \
        : "r"(a0), "r"(a1), "r"(a2), "r"(a3), "r"(b0), "r"(b1))

#define LDSM_X4_(r0, r1, r2, r3, addr) \
    asm volatile("ldmatrix.sync.aligned.m8n8.x4.shared.b16 {%0,%1,%2,%3}, [%4];" \
        : "=r"(r0), "=r"(r1), "=r"(r2), "=r"(r3) : "r"(addr))

#define LDSM_X4T_(r0, r1, r2, r3, addr) \
    asm volatile("ldmatrix.sync.aligned.m8n8.x4.trans.shared.b16 {%0,%1,%2,%3}, [%4];" \
        : "=r"(r0), "=r"(r1), "=r"(r2), "=r"(r3) : "r"(addr))

#define MG_SMEM 65536

__global__ __launch_bounds__(256, 2) void mma_gemm2_kernel(
    const __nv_bfloat16* __restrict__ Ahi_g, const __nv_bfloat16* __restrict__ Alo_g,
    const __nv_bfloat16* __restrict__ Bhi_g, const __nv_bfloat16* __restrict__ Blo_g,
    const float* __restrict__ bias, float* __restrict__ C,
    const float* __restrict__ Wf2g, float* __restrict__ Lgp,
    int N, int K, int act)
{
    extern __shared__ __align__(16) uint32_t smem_u[];
    const uint32_t smem_b = smem_u32_(smem_u);
    const int tid = threadIdx.x;
    const int wid = tid >> 5, lane = tid & 31;
    const int g = lane >> 2, t = lane & 3;
    const int warp_m = (wid & 3) * 32;
    const int warp_n = (wid >> 2) * 64;
    const int row0 = blockIdx.y * 128, col0 = blockIdx.x * 128;

    const int qq = lane >> 3, rr = lane & 7;
    const int arow = warp_m + ((qq & 1) << 3) + rr;
    const int aqb  = (qq >> 1) & 1;
    const int brow = warp_n + ((qq >> 1) << 3) + rr;
    const int bqb  = qq & 1;

    float acc[2][8][4];
#pragma unroll
    for (int mt = 0; mt < 2; mt++)
#pragma unroll
        for (int nt = 0; nt < 8; nt++)
#pragma unroll
            for (int e = 0; e < 4; e++) acc[mt][nt][e] = 0.f;

    for (int k0 = 0; k0 < K; k0 += 64) {
        __syncthreads();
#pragma unroll
        for (int i = 0; i < 16; i++) {
            const int op = i >> 2;
            int rem = (i & 3) * 256 + tid;
            int row = rem >> 3, c = rem & 7;
            const __nv_bfloat16* gsrc =
                (op == 0) ? Ahi_g + (size_t)(row0 + row) * K + k0 + c * 8 :
                (op == 1) ? Alo_g + (size_t)(row0 + row) * K + k0 + c * 8 :
                (op == 2) ? Bhi_g + (size_t)(col0 + row) * K + k0 + c * 8 :
                            Blo_g + (size_t)(col0 + row) * K + k0 + c * 8;
            uint32_t dst = smem_b + (uint32_t)(((op << 12) + row * 32 + ((c ^ (row & 7)) << 2)) << 2);
            cp16_(dst, gsrc);
        }
        asm volatile("cp.async.commit_group;");
        asm volatile("cp.async.wait_group 0;");
        __syncthreads();

#pragma unroll
        for (int ks = 0; ks < 4; ks++) {
            uint32_t ah[2][4], al[2][4];
#pragma unroll
            for (int mt = 0; mt < 2; mt++) {
                int row = arow + mt * 16;
                int pc = (2 * ks + aqb) ^ (row & 7);
                uint32_t ad = smem_b + (uint32_t)((row * 32 + pc * 4) << 2);
                LDSM_X4_(ah[mt][0], ah[mt][1], ah[mt][2], ah[mt][3], ad);
                LDSM_X4_(al[mt][0], al[mt][1], al[mt][2], al[mt][3], ad + 16384);
            }
#pragma unroll
            for (int p = 0; p < 4; p++) {
                int n = brow + p * 16;
                int pc = (2 * ks + bqb) ^ (n & 7);
                uint32_t bd = smem_b + (uint32_t)(((8192 + n * 32 + pc * 4)) << 2);
                uint32_t bh0, bh1, bh2, bh3, bl0, bl1, bl2, bl3;
                LDSM_X4_(bh0, bh1, bh2, bh3, bd);
                LDSM_X4_(bl0, bl1, bl2, bl3, bd + 16384);
#pragma unroll
                for (int mt = 0; mt < 2; mt++) {
                    MMA_BF16_(acc[mt][2*p],   ah[mt][0], ah[mt][1], ah[mt][2], ah[mt][3], bh0, bh1);
                    MMA_BF16_(acc[mt][2*p],   ah[mt][0], ah[mt][1], ah[mt][2], ah[mt][3], bl0, bl1);
                    MMA_BF16_(acc[mt][2*p],   al[mt][0], al[mt][1], al[mt][2], al[mt][3], bh0, bh1);
                    MMA_BF16_(acc[mt][2*p+1], ah[mt][0], ah[mt][1], ah[mt][2], ah[mt][3], bh2, bh3);
                    MMA_BF16_(acc[mt][2*p+1], ah[mt][0], ah[mt][1], ah[mt][2], ah[mt][3], bl2, bl3);
                    MMA_BF16_(acc[mt][2*p+1], al[mt][0], al[mt][1], al[mt][2], al[mt][3], bh2, bh3);
                }
            }
        }
    }

    if (act == 2) {
        float* sw   = (float*)smem_u;            // [128][20]
        float* slog = (float*)smem_u + 2560;     // [2][128][16]
        __syncthreads();
        for (int i = tid; i < 2048; i += 256) {
            int cl = i >> 4, j = i & 15;
            sw[cl * 20 + j] = Wf2g[(size_t)(col0 + cl) * 16 + j];
        }
        __syncthreads();
        const float* biasp = bias + col0;
#pragma unroll
        for (int mt = 0; mt < 2; mt++)
#pragma unroll
        for (int rw = 0; rw < 2; rw++) {
            float pl[16];
#pragma unroll
            for (int j = 0; j < 16; j++) pl[j] = 0.f;
#pragma unroll
            for (int nt = 0; nt < 8; nt++) {
                int cl = warp_n + nt * 8 + 2 * t;
                float v0 = geluf_(acc[mt][nt][rw * 2 + 0] + biasp[cl]);
                float v1 = geluf_(acc[mt][nt][rw * 2 + 1] + biasp[cl + 1]);
                const float* w0 = sw + cl * 20;
                const float* w1 = w0 + 20;
#pragma unroll
                for (int j4 = 0; j4 < 16; j4 += 4) {
                    float4 a4 = *(const float4*)(w0 + j4);
                    float4 b4 = *(const float4*)(w1 + j4);
                    pl[j4 + 0] += v0 * a4.x + v1 * b4.x;
                    pl[j4 + 1] += v0 * a4.y + v1 * b4.y;
                    pl[j4 + 2] += v0 * a4.z + v1 * b4.z;
                    pl[j4 + 3] += v0 * a4.w + v1 * b4.w;
                }
            }
#pragma unroll
            for (int o = 1; o <= 2; o <<= 1)
#pragma unroll
                for (int j = 0; j < 16; j++)
                    pl[j] += __shfl_xor_sync(0xffffffffu, pl[j], o);
            if (t == 0) {
                int r = warp_m + mt * 16 + g + rw * 8;
                float* dst = slog + (((wid >> 2) << 7) + r) * 16;
                *(float4*)(dst + 0)  = make_float4(pl[0], pl[1], pl[2], pl[3]);
                *(float4*)(dst + 4)  = make_float4(pl[4], pl[5], pl[6], pl[7]);
                *(float4*)(dst + 8)  = make_float4(pl[8], pl[9], pl[10], pl[11]);
                *(float4*)(dst + 12) = make_float4(pl[12], pl[13], pl[14], pl[15]);
            }
        }
        __syncthreads();
        for (int i = tid; i < 2048; i += 256) {
            int r = i >> 4, j = i & 15;
            float v = slog[r * 16 + j] + slog[(128 + r) * 16 + j];
            Lgp[(size_t)blockIdx.x * (BL_ * 16) + (size_t)(row0 + r) * 16 + j] = v;
        }
        return;
    }

#pragma unroll
    for (int mt = 0; mt < 2; mt++) {
        int r0g = row0 + warp_m + mt * 16 + g;
#pragma unroll
        for (int nt = 0; nt < 8; nt++) {
            int c = col0 + warp_n + nt * 8 + 2 * t;
            float2 v0, v1;
            v0.x = acc[mt][nt][0]; v0.y = acc[mt][nt][1];
            v1.x = acc[mt][nt][2]; v1.y = acc[mt][nt][3];
            if (act == 1) {
                float b0 = bias[c], b1 = bias[c + 1];
                v0.x = geluf_(v0.x + b0); v0.y = geluf_(v0.y + b1);
                v1.x = geluf_(v1.x + b0); v1.y = geluf_(v1.y + b1);
            }
            *(float2*)(C + (size_t)r0g * N + c) = v0;
            *(float2*)(C + (size_t)(r0g + 8) * N + c) = v1;
        }
    }
}

// ------------------------- softmax over 4 gate branches ---------------------
__global__ __launch_bounds__(256) void softmax4_kernel(
    const float* __restrict__ Lgp, const float* __restrict__ bf2, float* __restrict__ fw)
{
    int idx = blockIdx.x * 256 + threadIdx.x;
    int bl = idx >> 2, h = idx & 3;
    float l0 = bf2[h * 4 + 0], l1 = bf2[h * 4 + 1];
    float l2 = bf2[h * 4 + 2], l3 = bf2[h * 4 + 3];
#pragma unroll
    for (int tl = 0; tl < 16; tl++) {
        float4 v = *(const float4*)(Lgp + (size_t)tl * (BL_ * 16) + bl * 16 + h * 4);
        l0 += v.x; l1 += v.y; l2 += v.z; l3 += v.w;
    }
    float m = fmaxf(fmaxf(l0, l1), fmaxf(l2, l3));
    float e0 = expf(l0 - m), e1 = expf(l1 - m), e2 = expf(l2 - m), e3 = expf(l3 - m);
    float inv = 1.f / (e0 + e1 + e2 + e3);
    *(float4*)(fw + bl * 16 + h * 4) = make_float4(e0 * inv, e1 * inv, e2 * inv, e3 * inv);
}

// ------------------------- fused q/k/v short conv (K=4) + silu --------------
__global__ __launch_bounds__(256) void conv4_all_kernel(
    const float* __restrict__ x,
    const float* __restrict__ fq, const float* __restrict__ fk, const float* __restrict__ fv,
    float* __restrict__ qs, float* __restrict__ ks, float* __restrict__ vs)
{
    int idx = blockIdx.x * 256 + threadIdx.x;
    int bl = idx / NQKV;
    int c3 = idx - bl * NQKV;
    int s  = c3 >> 10;
    int c  = c3 & (H_ - 1);
    int l  = bl & (L_ - 1);
    const float* f = (s == 0) ? fq : (s == 1) ? fk : fv;
    float* y = (s == 0) ? qs : (s == 1) ? ks : vs;
    const float* xp = x + (size_t)bl * NQKV + c3;
    float4 fv4 = *(const float4*)(f + c * 4);
    float acc = fv4.w * xp[0];
    if (l >= 1) acc += fv4.z * xp[-NQKV];
    if (l >= 2) acc += fv4.y * xp[-2 * NQKV];
    if (l >= 3) acc += fv4.x * xp[-3 * NQKV];
    y[(size_t)bl * H_ + c] = acc * sigmoidf_(acc);
}

// ------------------------- beta = sigmoid(hs @ Wb) --------------------------
__global__ __launch_bounds__(128) void beta_kernel(
    const float* __restrict__ hs, const float* __restrict__ Wb, float* __restrict__ beta)
{
    int bl = blockIdx.x;
    int wrp = threadIdx.x >> 5, lane = threadIdx.x & 31;
    const float* hp = hs + (size_t)bl * H_;
    float acc = 0.f;
    for (int d = lane; d < H_; d += 32) acc += hp[d] * Wb[d * NH_ + wrp];
#pragma unroll
    for (int o = 16; o; o >>= 1) acc += __shfl_xor_sync(0xffffffffu, acc, o);
    if (lane == 0) beta[bl * NH_ + wrp] = sigmoidf_(acc);
}

// ------------------------- l2norm + beta + transpose -> fp32 + bf16 hi/lo ---
__global__ __launch_bounds__(256) void normtr_kernel(
    const float* __restrict__ qs, const float* __restrict__ ks, const float* __restrict__ vs,
    const float* __restrict__ beta,
    float* __restrict__ kb, float* __restrict__ vb,
    __nv_bfloat16* __restrict__ qnh, __nv_bfloat16* __restrict__ qnl,
    __nv_bfloat16* __restrict__ knh, __nv_bfloat16* __restrict__ knl,
    __nv_bfloat16* __restrict__ kbh, __nv_bfloat16* __restrict__ kbl)
{
    int bl = blockIdx.x, h = blockIdx.y, d = threadIdx.x;
    int b = bl >> 12;
    int l = bl & (L_ - 1);
    size_t src = (size_t)bl * H_ + h * DK_ + d;
    float qv = qs[src], kv = ks[src], vv = vs[src];
    float s1 = qv * qv, s2 = kv * kv;
#pragma unroll
    for (int o = 16; o; o >>= 1) {
        s1 += __shfl_xor_sync(0xffffffffu, s1, o);
        s2 += __shfl_xor_sync(0xffffffffu, s2, o);
    }
    __shared__ float r1[8], r2[8];
    __shared__ float inv1, inv2;
    int lane = d & 31, wid = d >> 5;
    if (lane == 0) { r1[wid] = s1; r2[wid] = s2; }
    __syncthreads();
    if (d == 0) {
        float t1 = 0.f, t2 = 0.f;
        for (int i = 0; i < 8; i++) { t1 += r1[i]; t2 += r2[i]; }
        inv1 = rsqrtf(t1);
        inv2 = rsqrtf(t2);
    }
    __syncthreads();
    float bt = beta[bl * NH_ + h];
    size_t dst = (((size_t)b * NH_ + h) * L_ + l) * DK_ + d;
    float knv = kv * inv2;
    float qnv = qv * inv1;
    float kbv = knv * bt;
    kb[dst] = kbv;
    vb[dst] = vv * bt;
    __nv_bfloat16 t0;
    t0 = __float2bfloat16(qnv); qnh[dst] = t0;
    qnl[dst] = __float2bfloat16(qnv - __bfloat162float(t0));
    t0 = __float2bfloat16(knv); knh[dst] = t0;
    knl[dst] = __float2bfloat16(knv - __bfloat162float(t0));
    t0 = __float2bfloat16(kbv); kbh[dst] = t0;
    kbl[dst] = __float2bfloat16(kbv - __bfloat162float(t0));
}

// ------------------------- per-chunk: HMMA A/attn + UT transform, u, w ------
#define CK_STRIDE 257
#define CK_SMEM (33888 * 4)
__global__ __launch_bounds__(256) void chunk_kernel(
    const float* __restrict__ kb, const float* __restrict__ vb,
    const __nv_bfloat16* __restrict__ knh_g, const __nv_bfloat16* __restrict__ knl_g,
    const __nv_bfloat16* __restrict__ kbh_g, const __nv_bfloat16* __restrict__ kbl_g,
    const __nv_bfloat16* __restrict__ qnh_g, const __nv_bfloat16* __restrict__ qnl_g,
    float* __restrict__ U, __nv_bfloat16* __restrict__ Wmh, __nv_bfloat16* __restrict__ Wml,
    float* __restrict__ ATT)
{
    extern __shared__ float sm[];
    float* skb = sm;
    float* sx  = sm + 8224;
    float* T   = sm + 16448;
    const uint32_t smem_b = smem_u32_(sm);
    const int bh = blockIdx.x, n = blockIdx.y;
    const int tid = threadIdx.x;
    const int wid = tid >> 5, lane = tid & 31;
    size_t base = ((size_t)bh * L_ + n * C_) * DK_;

    for (int i = tid; i < 2048; i += 256) {
        int r = i >> 6, c4 = (i & 63) << 2;
        float4 b = ((const float4*)(kb + base))[i];
        float4 v = ((const float4*)(vb + base))[i];
        float* pb = skb + r * CK_STRIDE + c4;
        float* pv = sx + r * CK_STRIDE + c4;
        pb[0] = b.x; pb[1] = b.y; pb[2] = b.z; pb[3] = b.w;
        pv[0] = v.x; pv[1] = v.y; pv[2] = v.z; pv[3] = v.w;
    }
#pragma unroll
    for (int i = 0; i < 16; i++) {
        const int arr = i >> 2;
        int idx = (i & 3) * 256 + tid;
        int row = idx >> 5, ch = idx & 31;
        const __nv_bfloat16* gp =
            (arr == 0) ? knh_g + base + row * 256 + ch * 8 :
            (arr == 1) ? knl_g + base + row * 256 + ch * 8 :
            (arr == 2) ? kbh_g + base + row * 256 + ch * 8 :
                         kbl_g + base + row * 256 + ch * 8;
        const uint32_t ab = (arr == 0) ? 17504u : (arr == 1) ? 21600u
                          : (arr == 2) ? 25696u : 29792u;
        uint32_t w = ab + (uint32_t)(row * 128 + (((ch & 24) | ((ch & 7) ^ (row & 7))) << 2));
        cp16_(smem_b + w * 4, gp);
    }
    asm volatile("cp.async.commit_group;");
    asm volatile("cp.async.wait_group 0;");
    __syncthreads();

    const int m0 = (wid & 1) << 4, n0 = (wid >> 1) << 3;
    const int qq = lane >> 3, rr = lane & 7;
    const int gg = lane >> 2, tt = lane & 3;
    const int arow = m0 + ((qq & 1) << 3) + rr;
    const int aqb = qq >> 1;
    const int brw = n0 + rr;
    {
        float acc[4] = {0.f, 0.f, 0.f, 0.f};
#pragma unroll
        for (int p = 0; p < 8; p++) {
            int bch = 4 * p + qq;
            uint32_t bw = 17504u + (uint32_t)(brw * 128 + (((bch & 24) | ((bch & 7) ^ (brw & 7))) << 2));
            uint32_t b0, b1, b2, b3, c0, c1, c2, c3;
            LDSM_X4_(b0, b1, b2, b3, smem_b + bw * 4);
            LDSM_X4_(c0, c1, c2, c3, smem_b + (bw + 4096u) * 4);
#pragma unroll
            for (int s = 0; s < 2; s++) {
                int ach = 2 * (2 * p + s) + aqb;
                uint32_t aw = 25696u + (uint32_t)(arow * 128 + (((ach & 24) | ((ach & 7) ^ (arow & 7))) << 2));
                uint32_t ah0, ah1, ah2, ah3, al0, al1, al2, al3;
                LDSM_X4_(ah0, ah1, ah2, ah3, smem_b + aw * 4);
                LDSM_X4_(al0, al1, al2, al3, smem_b + (aw + 4096u) * 4);
                uint32_t Bh0 = s ? b2 : b0, Bh1 = s ? b3 : b1;
                uint32_t Bl0 = s ? c2 : c0, Bl1 = s ? c3 : c1;
                MMA_BF16_(acc, ah0, ah1, ah2, ah3, Bh0, Bh1);
                MMA_BF16_(acc, ah0, ah1, ah2, ah3, Bl0, Bl1);
                MMA_BF16_(acc, al0, al1, al2, al3, Bh0, Bh1);
            }
        }
        int i0 = m0 + gg, j0 = n0 + 2 * tt;
        T[i0 * 33 + j0]           = (j0 < i0)         ? -acc[0] : 0.f;
        T[i0 * 33 + j0 + 1]       = (j0 + 1 < i0)     ? -acc[1] : 0.f;
        T[(i0 + 8) * 33 + j0]     = (j0 < i0 + 8)     ? -acc[2] : 0.f;
        T[(i0 + 8) * 33 + j0 + 1] = (j0 + 1 < i0 + 8) ? -acc[3] : 0.f;
    }
    __syncthreads();

#pragma unroll
    for (int i = 0; i < 8; i++) {
        const int arr = i >> 2;
        int idx = (i & 3) * 256 + tid;
        int row = idx >> 5, ch = idx & 31;
        const __nv_bfloat16* gp = (arr ? qnl_g : qnh_g) + base + row * 256 + ch * 8;
        uint32_t w = (arr ? 29792u : 25696u)
                   + (uint32_t)(row * 128 + (((ch & 24) | ((ch & 7) ^ (row & 7))) << 2));
        cp16_(smem_b + w * 4, gp);
    }
    asm volatile("cp.async.commit_group;");

    if (tid < 32) {
        int j = tid;
        for (int i = 1; i < 32; i++) {
            float rv = T[i * 33 + j];
            float acc = rv;
            for (int m = 1; m < i; m++)
                acc += __shfl_sync(0xffffffffu, rv, m) * T[m * 33 + j];
            __syncwarp();
            T[i * 33 + j] = acc;
            __syncwarp();
        }
        T[j * 33 + j] = 1.f;
    }
    __syncthreads();

    for (int idx = tid; idx < 8192; idx += 256) {
        int c = idx >> 8, d = idx & 255;
        float au = 0.f, aw = 0.f;
#pragma unroll
        for (int j = 0; j < 32; j++) {
            float t = T[c * 33 + j];
            au += t * sx[j * CK_STRIDE + d];
            aw += t * skb[j * CK_STRIDE + d];
        }
        U[base + idx] = au;
        __nv_bfloat16 hh = __float2bfloat16(aw);
        Wmh[base + idx] = hh;
        Wml[base + idx] = __float2bfloat16(aw - __bfloat162float(hh));
    }

    asm volatile("cp.async.wait_group 0;");
    __syncthreads();

    {
        float acc[4] = {0.f, 0.f, 0.f, 0.f};
#pragma unroll
        for (int p = 0; p < 8; p++) {
            int bch = 4 * p + qq;
            uint32_t bw = 17504u + (uint32_t)(brw * 128 + (((bch & 24) | ((bch & 7) ^ (brw & 7))) << 2));
            uint32_t b0, b1, b2, b3, c0, c1, c2, c3;
            LDSM_X4_(b0, b1, b2, b3, smem_b + bw * 4);
            LDSM_X4_(c0, c1, c2, c3, smem_b + (bw + 4096u) * 4);
#pragma unroll
            for (int s = 0; s < 2; s++) {
                int ach = 2 * (2 * p + s) + aqb;
                uint32_t aw = 25696u + (uint32_t)(arow * 128 + (((ach & 24) | ((ach & 7) ^ (arow & 7))) << 2));
                uint32_t ah0, ah1, ah2, ah3, al0, al1, al2, al3;
                LDSM_X4_(ah0, ah1, ah2, ah3, smem_b + aw * 4);
                LDSM_X4_(al0, al1, al2, al3, smem_b + (aw + 4096u) * 4);
                uint32_t Bh0 = s ? b2 : b0, Bh1 = s ? b3 : b1;
                uint32_t Bl0 = s ? c2 : c0, Bl1 = s ? c3 : c1;
                MMA_BF16_(acc, ah0, ah1, ah2, ah3, Bh0, Bh1);
                MMA_BF16_(acc, ah0, ah1, ah2, ah3, Bl0, Bl1);
                MMA_BF16_(acc, al0, al1, al2, al3, Bh0, Bh1);
            }
        }
        float* att = ATT + ((size_t)bh * NC_ + n) * 1024;
        int i0 = m0 + gg, j0 = n0 + 2 * tt;
        att[i0 * 32 + j0]           = (j0 <= i0)         ? acc[0] : 0.f;
        att[i0 * 32 + j0 + 1]       = (j0 + 1 <= i0)     ? acc[1] : 0.f;
        att[(i0 + 8) * 32 + j0]     = (j0 <= i0 + 8)     ? acc[2] : 0.f;
        att[(i0 + 8) * 32 + j0 + 1] = (j0 + 1 <= i0 + 8) ? acc[3] : 0.f;
    }
}

// ------------------------- sequential chunk scan: full-HMMA -----------------
// smem (float words):
//  S 0..4096 | A tiles wh 4096 / wl 8192 / qh 12288 / ql 16384 |
//  knh 20480 / knl 24576 | Sbh 28672 (2112) / Sbl 30784 |
//  su 32896 | sut 33408 | sutbh 33920 (384) / sutbl 34304 |
//  sat 34688 (1152) | swS 35840 (576) | sqS 36416 (576)  -> 36992 words
#define SCAN_SMEM (36992 * 4)
__global__ __launch_bounds__(256) void scan_kernel(
    const __nv_bfloat16* __restrict__ qh_g, const __nv_bfloat16* __restrict__ ql_g,
    const __nv_bfloat16* __restrict__ wh_g, const __nv_bfloat16* __restrict__ wl_g,
    const __nv_bfloat16* __restrict__ knh_g, const __nv_bfloat16* __restrict__ knl_g,
    const float* __restrict__ U, const float* __restrict__ ATT, float* __restrict__ OUT)
{
    extern __shared__ float sm[];
    float* S   = sm;             // [256][16]
    uint32_t* sbh = (uint32_t*)(sm + 28672);
    uint32_t* sbl = (uint32_t*)(sm + 30784);
    float* su  = sm + 32896;
    float* sut = sm + 33408;
    uint32_t* sutbh = (uint32_t*)(sm + 33920);   // [32][12]
    uint32_t* sutbl = (uint32_t*)(sm + 34304);
    float* sat = sm + 34688;
    float* swS = sm + 35840;
    float* sqS = sm + 36416;
    const uint32_t smem_b = smem_u32_(sm);
    const int bh = blockIdx.x, tile = blockIdx.y;
    const int tid = threadIdx.x;
    const int wid = tid >> 5, lane = tid & 31;
    const int b = bh >> 2, h = bh & 3;
    const int g = tid >> 3, eg = tid & 7, eg2 = eg * 2;
    // wS/qS HMMA roles
    const int pr = wid & 1, mt = (wid >> 1) & 1, nt = wid >> 2;
    const int qq = lane >> 3, rr = lane & 7;
    const int arow = mt * 16 + ((qq & 1) << 3) + rr;
    const int aqb  = qq >> 1;
    const int brow = ((qq >> 1) << 3) + rr;
    const int bqb  = qq & 1;
    const int gg = lane >> 2, tt = lane & 3;
    const uint32_t abaseW = 4096u + (pr ? 8192u : 0u);
    // S conversion role
    const int ce = tid & 15, cd0 = (tid >> 4) * 16;

    for (int i = tid; i < 4096; i += 256) S[i] = 0.f;

    for (int n = 0; n < NC_; n++) {
        __syncthreads();
        size_t base = ((size_t)bh * L_ + n * C_) * 256;
        // A tiles: wh, wl, qh, ql
#pragma unroll
        for (int i = 0; i < 16; i++) {
            const int arr = i >> 2, r = i & 3;
            int row = r * 8 + wid;
            int ch  = lane;
            const __nv_bfloat16* gp =
                (arr == 0) ? wh_g + base + row * 256 + ch * 8 :
                (arr == 1) ? wl_g + base + row * 256 + ch * 8 :
                (arr == 2) ? qh_g + base + row * 256 + ch * 8 :
                             ql_g + base + row * 256 + ch * 8;
            uint32_t w = 4096u + (uint32_t)(arr * 4096 + row * 128
                         + (((ch & 24) | ((ch & 7) ^ (row & 7))) << 2));
            cp16_(smem_b + w * 4, gp);
        }
        // kn tiles (for S update)
#pragma unroll
        for (int i = 0; i < 8; i++) {
            const int arr = i >> 2;
            int idx = (i & 3) * 256 + tid;
            int row = idx >> 5, ch = idx & 31;
            const __nv_bfloat16* gp = (arr ? knl_g : knh_g) + base + row * 256 + ch * 8;
            uint32_t w = (arr ? 24576u : 20480u)
                       + (uint32_t)(row * 128 + (((ch & 24) | ((ch & 7) ^ (row & 7))) << 2));
            cp16_(smem_b + w * 4, gp);
        }
        asm volatile("cp.async.commit_group;");
        if (tid < 128) {
            int c = tid >> 2, e4 = tid & 3;
            ((float4*)su)[tid] = *(const float4*)(U + base + c * 256 + tile * 16 + e4 * 4);
        }
        {
            int c = tid >> 3, j4 = (tid & 7) * 4;
            *(float4*)(sat + c * 36 + j4) =
                ((const float4*)(ATT + ((size_t)bh * NC_ + n) * 1024))[tid];
        }
        // S[d][e] -> Sb16 hi/lo [e][d]
#pragma unroll
        for (int i2 = 0; i2 < 8; i2++) {
            int d = cd0 + i2 * 2;
            float x = S[d * 16 + ce], y = S[(d + 1) * 16 + ce];
            sbh[ce * 132 + (d >> 1)] = pack_bf16_hi_(x, y);
            sbl[ce * 132 + (d >> 1)] = pack_bf16_lo_(x, y);
        }
        asm volatile("cp.async.wait_group 0;");
        __syncthreads();

        // wS / qS HMMA
        float acc[4] = {0.f, 0.f, 0.f, 0.f};
#pragma unroll
        for (int ks = 0; ks < 16; ks++) {
            int ch = 2 * ks + aqb;
            uint32_t aw_ = abaseW + (uint32_t)(arow * 128
                          + (((ch & 24) | ((ch & 7) ^ (arow & 7))) << 2));
            uint32_t ah0, ah1, ah2, ah3, al0, al1, al2, al3;
            LDSM_X4_(ah0, ah1, ah2, ah3, smem_b + aw_ * 4);
            LDSM_X4_(al0, al1, al2, al3, smem_b + (aw_ + 4096u) * 4);
            uint32_t bw_ = 28672u + (uint32_t)(brow * 132 + (2 * ks + bqb) * 4);
            uint32_t bh0, bh1, bh2, bh3, bl0, bl1, bl2, bl3;
            LDSM_X4_(bh0, bh1, bh2, bh3, smem_b + bw_ * 4);
            LDSM_X4_(bl0, bl1, bl2, bl3, smem_b + (bw_ + 2112u) * 4);
            uint32_t B0h = nt ? bh2 : bh0, B1h = nt ? bh3 : bh1;
            uint32_t B0l = nt ? bl2 : bl0, B1l = nt ? bl3 : bl1;
            MMA_BF16_(acc, ah0, ah1, ah2, ah3, B0h, B1h);
            MMA_BF16_(acc, ah0, ah1, ah2, ah3, B0l, B1l);
            MMA_BF16_(acc, al0, al1, al2, al3, B0h, B1h);
        }
        {
            float* dst = pr ? sqS : swS;
            int c0 = mt * 16 + gg, e0 = nt * 8 + 2 * tt;
            *(float2*)(dst + c0 * 18 + e0) = make_float2(acc[0], acc[1]);
            *(float2*)(dst + (c0 + 8) * 18 + e0) = make_float2(acc[2], acc[3]);
        }
        __syncthreads();

        // ut = u - wS ; store fp32 + bf16 hi/lo ([c][e] stride 12 words)
        float2 uv = *(float2*)(su + g * 16 + eg2);
        float2 wv = *(float2*)(swS + g * 18 + eg2);
        float2 ut = make_float2(uv.x - wv.x, uv.y - wv.y);
        *(float2*)(sut + g * 16 + eg2) = ut;
        sutbh[g * 12 + eg] = pack_bf16_hi_(ut.x, ut.y);
        sutbl[g * 12 + eg] = pack_bf16_lo_(ut.x, ut.y);
        float2 aq = *(float2*)(sqS + g * 18 + eg2);
        __syncthreads();

        // o = qS + attn @ ut
        const float* ar = sat + g * 36;
#pragma unroll
        for (int j = 0; j < 32; j += 4) {
            float4 a4 = *(const float4*)(ar + j);
            float2 u0 = *(float2*)(sut + (j + 0) * 16 + eg2);
            float2 u1 = *(float2*)(sut + (j + 1) * 16 + eg2);
            float2 u2 = *(float2*)(sut + (j + 2) * 16 + eg2);
            float2 u3 = *(float2*)(sut + (j + 3) * 16 + eg2);
            aq.x += a4.x * u0.x + a4.y * u1.x + a4.z * u2.x + a4.w * u3.x;
            aq.y += a4.x * u0.y + a4.y * u1.y + a4.z * u2.y + a4.w * u3.y;
        }
        *(float2*)(OUT + (size_t)(b * L_ + n * C_ + g) * H_ + h * 256 + tile * 16 + eg2) = aq;

        // S += k^T @ ut (HMMA via ldmatrix.trans; warp wid owns d rows 32w..+31)
        {
            float accS[2][2][4];
#pragma unroll
            for (int m2 = 0; m2 < 2; m2++)
#pragma unroll
                for (int n2 = 0; n2 < 2; n2++)
#pragma unroll
                    for (int e = 0; e < 4; e++) accS[m2][n2][e] = 0.f;
#pragma unroll
            for (int ks2 = 0; ks2 < 2; ks2++) {
                const int cbase = ks2 * 16;
                // B fragments from ut b16 [c][e]: x4 covers both nt tiles
                int br2 = cbase + ((qq & 1) << 3) + rr;
                uint32_t ba = smem_b + (33920u + (uint32_t)(br2 * 12 + ((qq >> 1) << 2))) * 4;
                uint32_t ub0, ub1, ub2, ub3, uc0, uc1, uc2, uc3;
                LDSM_X4T_(ub0, ub1, ub2, ub3, ba);
                LDSM_X4T_(uc0, uc1, uc2, uc3, ba + 1536);
#pragma unroll
                for (int m2 = 0; m2 < 2; m2++) {
                    int ar2 = cbase + ((qq >> 1) << 3) + rr;
                    int ch = wid * 4 + m2 * 2 + (qq & 1);
                    uint32_t aa = smem_b + (20480u + (uint32_t)(ar2 * 128
                                  + (((ch & 24) | ((ch & 7) ^ (ar2 & 7))) << 2))) * 4;
                    uint32_t ka0, ka1, ka2, ka3, kl0, kl1, kl2, kl3;
                    LDSM_X4T_(ka0, ka1, ka2, ka3, aa);
                    LDSM_X4T_(kl0, kl1, kl2, kl3, aa + 16384);
                    MMA_BF16_(accS[m2][0], ka0, ka1, ka2, ka3, ub0, ub1);
                    MMA_BF16_(accS[m2][0], ka0, ka1, ka2, ka3, uc0, uc1);
                    MMA_BF16_(accS[m2][0], kl0, kl1, kl2, kl3, ub0, ub1);
                    MMA_BF16_(accS[m2][1], ka0, ka1, ka2, ka3, ub2, ub3);
                    MMA_BF16_(accS[m2][1], ka0, ka1, ka2, ka3, uc2, uc3);
                    MMA_BF16_(accS[m2][1], kl0, kl1, kl2, kl3, ub2, ub3);
                }
            }
#pragma unroll
            for (int m2 = 0; m2 < 2; m2++)
#pragma unroll
            for (int n2 = 0; n2 < 2; n2++) {
                int d0 = wid * 32 + m2 * 16 + gg;
                int e0 = n2 * 8 + 2 * tt;
                float2 s0 = *(float2*)(S + d0 * 16 + e0);
                s0.x += accS[m2][n2][0]; s0.y += accS[m2][n2][1];
                *(float2*)(S + d0 * 16 + e0) = s0;
                float2 s1 = *(float2*)(S + (d0 + 8) * 16 + e0);
                s1.x += accS[m2][n2][2]; s1.y += accS[m2][n2][3];
                *(float2*)(S + (d0 + 8) * 16 + e0) = s1;
            }
        }
    }
}

// ------------------------- FIR K=64: smem tile + register sliding window ----
#define FIR64_SMEM ((127 * 128 + 64 * 129) * 4)
__global__ __launch_bounds__(256) void fir64_smem_kernel(
    const float* __restrict__ x, const float* __restrict__ f, float* __restrict__ y)
{
    extern __shared__ float fsm[];
    float* sx = fsm;
    float* sf = fsm + 127 * 128;
    const int ctile = blockIdx.x & 7;
    const int ltile = blockIdx.x >> 3;
    const int l0 = ltile * 64;
    const int lb = l0 & (L_ - 1);
    const int c0 = ctile * 128;
    const int tid = threadIdx.x;

    for (int i = tid; i < 64 * 128; i += 256) {
        int c = i >> 6, t = i & 63;
        sf[t * 129 + c] = f[(size_t)(c0 + c) * 64 + t];
    }
    for (int i = tid; i < 127 * 128; i += 256) {
        int j = i >> 7, c = i & 127;
        int lrel = lb + j - 63;
        float v = 0.f;
        if (lrel >= 0)
            v = x[(size_t)(l0 + j - 63) * H_ + c0 + c];
        sx[j * 128 + c] = v;
    }
    __syncthreads();

    const int c = tid & 127;
    const int lg = (tid >> 7) * 32;
    float acc[32], win[32];
#pragma unroll
    for (int i = 0; i < 32; i++) acc[i] = 0.f;
#pragma unroll
    for (int i = 0; i < 32; i++) win[i] = sx[(lg + i) * 128 + c];
#pragma unroll
    for (int t = 0; t < 64; t++) {
        float ft = sf[t * 129 + c];
#pragma unroll
        for (int i = 0; i < 32; i++) acc[i] += ft * win[i];
        if (t < 63) {
#pragma unroll
            for (int i = 0; i < 31; i++) win[i] = win[i + 1];
            win[31] = sx[(lg + t + 32) * 128 + c];
        }
    }
#pragma unroll
    for (int i = 0; i < 32; i++)
        y[(size_t)(l0 + lg + i) * H_ + c0 + c] = acc[i];
}

// ------------------------- mix (incl. inline fir7) + rmsnorm -> bf16 --------
__global__ __launch_bounds__(256) void mix_rms_kernel(
    const float* __restrict__ vs, const float* __restrict__ br_l,
    const float* __restrict__ br_d, const float* __restrict__ fsw,
    const float* __restrict__ fw, const float* __restrict__ rmsw,
    __nv_bfloat16* __restrict__ Mhi, __nv_bfloat16* __restrict__ Mlo)
{
    int bl = blockIdx.x, h = blockIdx.y, d = threadIdx.x;
    size_t i = (size_t)bl * H_ + h * 256 + d;
    int l = bl & (L_ - 1);
    const float* f = fw + (size_t)bl * 16 + h * 4;
    // inline K=7 causal FIR on vs
    const float* fp = fsw + (size_t)(h * 256 + d) * 7;
    float vsv = vs[i];
    float sacc = fp[6] * vsv;
    if (l >= 1) sacc += fp[5] * vs[i - H_];
    if (l >= 2) sacc += fp[4] * vs[i - 2 * H_];
    if (l >= 3) sacc += fp[3] * vs[i - 3 * H_];
    if (l >= 4) sacc += fp[2] * vs[i - 4 * H_];
    if (l >= 5) sacc += fp[1] * vs[i - 5 * H_];
    if (l >= 6) sacc += fp[0] * vs[i - 6 * H_];
    float val = f[0] * sacc + f[1] * br_l[i] + f[2] * br_d[i] + f[3] * vsv;
    float ss = val * val;
#pragma unroll
    for (int o = 16; o; o >>= 1) ss += __shfl_xor_sync(0xffffffffu, ss, o);
    __shared__ float red[8];
    __shared__ float scale;
    if ((d & 31) == 0) red[d >> 5] = ss;
    __syncthreads();
    if (d == 0) {
        float t = 0.f;
        for (int k = 0; k < 8; k++) t += red[k];
        scale = rsqrtf(t * (1.f / 256.f) + 1e-5f);
    }
    __syncthreads();
    float o = val * scale * rmsw[d];
    __nv_bfloat16 hb = __float2bfloat16(o);
    Mhi[i] = hb;
    Mlo[i] = __float2bfloat16(o - __bfloat162float(hb));
}

// ------------------------- launcher ----------------------------------------
extern "C" void kernel_launch(void* const* d_in, const int* in_sizes, int n_in,
                              void* d_out, int out_size)
{
    const float* hs   = (const float*)d_in[0];
    const float* Wq   = (const float*)d_in[1];
    const float* Wk   = (const float*)d_in[2];
    const float* Wv   = (const float*)d_in[3];
    const float* Wb   = (const float*)d_in[4];
    const float* cq   = (const float*)d_in[5];
    const float* ck   = (const float*)d_in[6];
    const float* cv   = (const float*)d_in[7];
    const float* fsw  = (const float*)d_in[8];
    const float* flw  = (const float*)d_in[9];
    const float* Wf1  = (const float*)d_in[10];
    const float* bf1  = (const float*)d_in[11];
    const float* Wf2  = (const float*)d_in[12];
    const float* bf2  = (const float*)d_in[13];
    const float* rmsw = (const float*)d_in[14];
    const float* Wo   = (const float*)d_in[15];
    float* out = (float*)d_out;

    float *qkvp, *qs, *ks, *vs, *kb, *vb;
    float *u, *delta, *lng, *lgp, *att, *beta, *fw;
    __nv_bfloat16 *ahi, *alo, *mhi, *mlo, *wqh, *wql, *wf1h, *wf1l, *woh, *wol;
    __nv_bfloat16 *qnh, *qnl, *knh, *knl, *kbh, *kbl, *wmh, *wml;
    cudaGetSymbolAddress((void**)&qkvp, g_qkvp);
    cudaGetSymbolAddress((void**)&qs, g_qs);
    cudaGetSymbolAddress((void**)&ks, g_ks);
    cudaGetSymbolAddress((void**)&vs, g_vs);
    cudaGetSymbolAddress((void**)&kb, g_kb);
    cudaGetSymbolAddress((void**)&vb, g_vb);
    cudaGetSymbolAddress((void**)&u, g_u);
    cudaGetSymbolAddress((void**)&delta, g_delta);
    cudaGetSymbolAddress((void**)&lng, g_long);
    cudaGetSymbolAddress((void**)&lgp, g_lgp);
    cudaGetSymbolAddress((void**)&att, g_att);
    cudaGetSymbolAddress((void**)&beta, g_beta);
    cudaGetSymbolAddress((void**)&fw, g_fw);
    cudaGetSymbolAddress((void**)&ahi, g_ahi);
    cudaGetSymbolAddress((void**)&alo, g_alo);
    cudaGetSymbolAddress((void**)&mhi, g_mhi);
    cudaGetSymbolAddress((void**)&mlo, g_mlo);
    cudaGetSymbolAddress((void**)&qnh, g_qnh);
    cudaGetSymbolAddress((void**)&qnl, g_qnl);
    cudaGetSymbolAddress((void**)&knh, g_knh);
    cudaGetSymbolAddress((void**)&knl, g_knl);
    cudaGetSymbolAddress((void**)&kbh, g_kbh);
    cudaGetSymbolAddress((void**)&kbl, g_kbl);
    cudaGetSymbolAddress((void**)&wmh, g_wh);
    cudaGetSymbolAddress((void**)&wml, g_wl);
    cudaGetSymbolAddress((void**)&wqh, g_wqkv_hi);
    cudaGetSymbolAddress((void**)&wql, g_wqkv_lo);
    cudaGetSymbolAddress((void**)&wf1h, g_wf1_hi);
    cudaGetSymbolAddress((void**)&wf1l, g_wf1_lo);
    cudaGetSymbolAddress((void**)&woh, g_wo_hi);
    cudaGetSymbolAddress((void**)&wol, g_wo_lo);

    cudaFuncSetAttribute(mma_gemm2_kernel, cudaFuncAttributeMaxDynamicSharedMemorySize, MG_SMEM);
    cudaFuncSetAttribute(chunk_kernel, cudaFuncAttributeMaxDynamicSharedMemorySize, CK_SMEM);
    cudaFuncSetAttribute(scan_kernel,  cudaFuncAttributeMaxDynamicSharedMemorySize, SCAN_SMEM);
    cudaFuncSetAttribute(fir64_smem_kernel, cudaFuncAttributeMaxDynamicSharedMemorySize, FIR64_SMEM);

    // ---- prep: bf16 hi/lo conversions ----
    cvt_a_kernel<<<BL_ * H_ / 1024, 256>>>(hs, ahi, alo);
    cvt_wt_kernel<<<dim3(32, 32), 256>>>(Wq, wqh,             wql,             H_, H_);
    cvt_wt_kernel<<<dim3(32, 32), 256>>>(Wk, wqh + 1024 * H_, wql + 1024 * H_, H_, H_);
    cvt_wt_kernel<<<dim3(32, 32), 256>>>(Wv, wqh + 2048 * H_, wql + 2048 * H_, H_, H_);
    cvt_wt_kernel<<<dim3(64, 32), 256>>>(Wf1, wf1h, wf1l, H_, F1_);
    cvt_wt_kernel<<<dim3(32, 32), 256>>>(Wo, woh, wol, H_, H_);

    // ---- fused qkv projection; f1 GEMM + fused gate logits -----------------
    mma_gemm2_kernel<<<dim3(NQKV / 128, BL_ / 128), 256, MG_SMEM>>>(
        ahi, alo, wqh, wql, nullptr, qkvp, nullptr, nullptr, NQKV, H_, 0);
    mma_gemm2_kernel<<<dim3(F1_ / 128, BL_ / 128), 256, MG_SMEM>>>(
        ahi, alo, wf1h, wf1l, bf1, nullptr, Wf2, lgp, F1_, H_, 2);
    softmax4_kernel<<<BL_ * 4 / 256, 256>>>(lgp, bf2, fw);

    // fused short conv + silu
    conv4_all_kernel<<<BL_ * NQKV / 256, 256>>>(qkvp, cq, ck, cv, qs, ks, vs);

    // beta, l2norm + transpose
    beta_kernel<<<BL_, 128>>>(hs, Wb, beta);
    normtr_kernel<<<dim3(BL_, NH_), 256>>>(qs, ks, vs, beta, kb, vb,
                                           qnh, qnl, knh, knl, kbh, kbl);

    // delta rule
    chunk_kernel<<<dim3(BH_, NC_), 256, CK_SMEM>>>(
        kb, vb, knh, knl, kbh, kbl, qnh, qnl, u, wmh, wml, att);
    scan_kernel<<<dim3(BH_, 16), 256, SCAN_SMEM>>>(
        qnh, qnl, wmh, wml, knh, knl, u, att, delta);

    // FIR long branch
    fir64_smem_kernel<<<1024, 256, FIR64_SMEM>>>(vs, flw, lng);

    // mix (inline fir7) + rmsnorm, output projection
    mix_rms_kernel<<<dim3(BL_, NH_), 256>>>(vs, lng, delta, fsw, fw, rmsw, mhi, mlo);
    mma_gemm2_kernel<<<dim3(H_ / 128, BL_ / 128), 256, MG_SMEM>>>(
        mhi, mlo, woh, wol, nullptr, out, nullptr, nullptr, H_, H_, 0);
}